// round 4
// baseline (speedup 1.0000x reference)
#include <cuda_runtime.h>
#include <math.h>

#define NMAX 100000
#define EMAX 1600000
#define DI   128
#define H4   4
#define C32  32

// ---------------- static device scratch ----------------
__device__ float g_q[NMAX * DI];
__device__ float g_k[NMAX * DI];
__device__ float g_v[NMAX * DI];
__device__ int   g_src[EMAX];
__device__ int   g_dst[EMAX];
__device__ int   g_csr_src[EMAX];
__device__ int   g_deg[NMAX];
__device__ int   g_off[NMAX + 1];
__device__ int   g_cur[NMAX];
__device__ int   g_is64;

// ---------------- packed f32x2 helpers ----------------
__device__ __forceinline__ unsigned long long pack2(float a, float b) {
    unsigned long long r;
    asm("mov.b64 %0, {%1, %2};" : "=l"(r)
        : "r"(__float_as_uint(a)), "r"(__float_as_uint(b)));
    return r;
}
__device__ __forceinline__ void fma2(unsigned long long& d,
                                     unsigned long long a, unsigned long long b) {
    asm("fma.rn.f32x2 %0, %1, %2, %3;" : "=l"(d) : "l"(a), "l"(b), "l"(d));
}

// ---------------- fused 4-way GEMM: {q,k,v,skip} = x @ W* + b* ----------------
// Block: 64 rows x 128 cols, 256 threads. X tile resident in smem across all 4 W.
// Register tile per thread: 8 rows x 4 cols as 4x4 f32x2 accumulators (row pairs).
__global__ __launch_bounds__(256) void gemm128x4(
    const float* __restrict__ X,
    const float* __restrict__ W0, const float* __restrict__ b0,
    const float* __restrict__ W1, const float* __restrict__ b1,
    const float* __restrict__ W2, const float* __restrict__ b2,
    const float* __restrict__ W3, const float* __restrict__ b3,
    float* __restrict__ out3, int n)
{
    __shared__ float xs[128][64];   // [k][row], 32 KB
    __shared__ float ws[16][128];   // 8 KB

    int tid  = threadIdx.x;
    int tcol = tid & 31;            // cols 4*tcol..+3
    int trow = tid >> 5;            // rows 8*trow..+7
    int row0 = blockIdx.x * 64;

    // load X tile: 64 rows x 128 k, transposed into xs[k][row]
    {
        int r   = tid >> 2;          // 0..63
        int kq0 = (tid & 3) * 32;    // each of 4 threads/row covers 32 k
        int gr  = row0 + r;
#pragma unroll
        for (int c = 0; c < 8; c++) {
            int kk = kq0 + c * 4;
            float4 xv = make_float4(0.f, 0.f, 0.f, 0.f);
            if (gr < n) xv = *(const float4*)(X + (size_t)gr * DI + kk);
            xs[kk + 0][r] = xv.x; xs[kk + 1][r] = xv.y;
            xs[kk + 2][r] = xv.z; xs[kk + 3][r] = xv.w;
        }
    }

    const float* Ws[4] = {W0, W1, W2, W3};
    const float* Bs[4] = {b0, b1, b2, b3};

#pragma unroll 1
    for (int w = 0; w < 4; w++) {
        const float* __restrict__ W = Ws[w];

        unsigned long long acc2[4][4];
#pragma unroll
        for (int i = 0; i < 4; i++)
#pragma unroll
            for (int j = 0; j < 4; j++) acc2[i][j] = 0ull;

        for (int k0 = 0; k0 < DI; k0 += 16) {
            __syncthreads();   // also covers initial xs fill / prev-iter ws readers
            {
                int k    = tid >> 5;
                int colq = (tid & 31) * 4;
                *(float4*)&ws[k][colq]     = *(const float4*)(W + (size_t)(k0 + k) * DI + colq);
                *(float4*)&ws[k + 8][colq] = *(const float4*)(W + (size_t)(k0 + k + 8) * DI + colq);
            }
            __syncthreads();
#pragma unroll
            for (int kk = 0; kk < 16; kk++) {
                float4 wv = *(const float4*)&ws[kk][tcol * 4];
                unsigned long long wd[4];
                wd[0] = pack2(wv.x, wv.x);
                wd[1] = pack2(wv.y, wv.y);
                wd[2] = pack2(wv.z, wv.z);
                wd[3] = pack2(wv.w, wv.w);
                float4 xa = *(const float4*)&xs[k0 + kk][trow * 8];
                float4 xb = *(const float4*)&xs[k0 + kk][trow * 8 + 4];
                unsigned long long xp[4];
                xp[0] = pack2(xa.x, xa.y);
                xp[1] = pack2(xa.z, xa.w);
                xp[2] = pack2(xb.x, xb.y);
                xp[3] = pack2(xb.z, xb.w);
#pragma unroll
                for (int ip = 0; ip < 4; ip++)
#pragma unroll
                    for (int j = 0; j < 4; j++)
                        fma2(acc2[ip][j], xp[ip], wd[j]);
            }
        }

        float* out;
        if (w == 0)      out = g_q;
        else if (w == 1) out = g_k;
        else if (w == 2) out = g_v;
        else             out = out3;

        float4 bv = *(const float4*)(Bs[w] + tcol * 4);
#pragma unroll
        for (int ip = 0; ip < 4; ip++) {
            float2 c0 = *reinterpret_cast<float2*>(&acc2[ip][0]);
            float2 c1 = *reinterpret_cast<float2*>(&acc2[ip][1]);
            float2 c2 = *reinterpret_cast<float2*>(&acc2[ip][2]);
            float2 c3 = *reinterpret_cast<float2*>(&acc2[ip][3]);
            int r_lo = row0 + trow * 8 + 2 * ip;
            if (r_lo < n) {
                float4 o = make_float4(c0.x + bv.x, c1.x + bv.y, c2.x + bv.z, c3.x + bv.w);
                *(float4*)(out + (size_t)r_lo * DI + tcol * 4) = o;
            }
            if (r_lo + 1 < n) {
                float4 o = make_float4(c0.y + bv.x, c1.y + bv.y, c2.y + bv.z, c3.y + bv.w);
                *(float4*)(out + (size_t)(r_lo + 1) * DI + tcol * 4) = o;
            }
        }
    }
}

// ---------------- edge dtype sniff + CSR build ----------------
__global__ void sniff_dtype(const int* __restrict__ ei32, int e) {
    if (threadIdx.x == 0 && blockIdx.x == 0) {
        int allzero = 1;
        int stride = (2 * e) / 256;
        if (stride < 2) stride = 2;
        for (int s = 0; s < 256; s++) {
            long long idx = (long long)s * stride | 1;
            if (idx < 4LL * e) {
                if (ei32[idx] != 0) { allzero = 0; break; }
            }
        }
        g_is64 = allzero;
    }
}

__global__ void zero_deg(int n) {
    for (int i = blockIdx.x * blockDim.x + threadIdx.x; i < n; i += gridDim.x * blockDim.x)
        g_deg[i] = 0;
}

__global__ void hist_edges(const int* __restrict__ ei32, int e, int n) {
    int is64 = g_is64;
    for (int i = blockIdx.x * blockDim.x + threadIdx.x; i < e; i += gridDim.x * blockDim.x) {
        int s, d;
        if (is64) {
            s = ei32[(size_t)2 * i];
            d = ei32[(size_t)2 * (e + i)];
        } else {
            s = ei32[i];
            d = ei32[(size_t)e + i];
        }
        s = min(max(s, 0), n - 1);
        d = min(max(d, 0), n - 1);
        g_src[i] = s;
        g_dst[i] = d;
        atomicAdd(&g_deg[d], 1);
    }
}

__global__ __launch_bounds__(1024) void scan_deg(int n) {
    __shared__ int wsum[32];
    __shared__ int s_carry;
    __shared__ int s_total;
    int tid = threadIdx.x, lane = tid & 31, wid = tid >> 5;
    if (tid == 0) s_carry = 0;
    __syncthreads();
    for (int base = 0; base < n; base += 1024) {
        int i = base + tid;
        int v = (i < n) ? g_deg[i] : 0;
        int inc = v;
#pragma unroll
        for (int o = 1; o < 32; o <<= 1) {
            int t = __shfl_up_sync(0xffffffffu, inc, o);
            if (lane >= o) inc += t;
        }
        if (lane == 31) wsum[wid] = inc;
        __syncthreads();
        if (wid == 0) {
            int w  = wsum[lane];
            int wi = w;
#pragma unroll
            for (int o = 1; o < 32; o <<= 1) {
                int t = __shfl_up_sync(0xffffffffu, wi, o);
                if (lane >= o) wi += t;
            }
            wsum[lane] = wi - w;
            if (lane == 31) s_total = wi;
        }
        __syncthreads();
        int excl = s_carry + wsum[wid] + (inc - v);
        if (i < n) { g_off[i] = excl; g_cur[i] = excl; }
        __syncthreads();
        if (tid == 0) s_carry += s_total;
        __syncthreads();
    }
    if (threadIdx.x == 0) g_off[n] = s_carry;
}

__global__ void fill_csr(int e) {
    for (int i = blockIdx.x * blockDim.x + threadIdx.x; i < e; i += gridDim.x * blockDim.x) {
        int d   = g_dst[i];
        int pos = atomicAdd(&g_cur[d], 1);
        g_csr_src[pos] = g_src[i];
    }
}

// ---------------- attention: one warp per node, all 4 heads ----------------
__device__ __forceinline__ float red8(float d) {
    d += __shfl_xor_sync(0xffffffffu, d, 4);
    d += __shfl_xor_sync(0xffffffffu, d, 2);
    d += __shfl_xor_sync(0xffffffffu, d, 1);
    return d;
}

__global__ __launch_bounds__(256) void attn_node(float* __restrict__ out, int n) {
    int warp = (blockIdx.x * blockDim.x + threadIdx.x) >> 5;
    int lane = threadIdx.x & 31;
    if (warp >= n) return;
    int node = warp;

    int base = g_off[node];
    int end  = g_off[node + 1];

    const float* __restrict__ k = g_k;
    const float* __restrict__ v = g_v;

    float4 q4 = *(const float4*)(g_q + (size_t)node * DI + 4 * lane);
    const float scale = 0.17677669529663688f;  // 1/sqrt(32)

    float  z    = 0.f;
    float4 acc4 = make_float4(0.f, 0.f, 0.f, 0.f);

    for (int i0 = base; i0 < end; i0 += 32) {
        int nchunk = min(32, end - i0);
        int sidx = (i0 + lane < end) ? g_csr_src[i0 + lane] : 0;

        int j = 0;
        for (; j + 1 < nchunk; j += 2) {
            int s0 = __shfl_sync(0xffffffffu, sidx, j);
            int s1 = __shfl_sync(0xffffffffu, sidx, j + 1);
            const float4 k0 = *(const float4*)(k + (size_t)s0 * DI + 4 * lane);
            const float4 k1 = *(const float4*)(k + (size_t)s1 * DI + 4 * lane);
            const float4 v0 = *(const float4*)(v + (size_t)s0 * DI + 4 * lane);
            const float4 v1 = *(const float4*)(v + (size_t)s1 * DI + 4 * lane);
            float d0 = q4.x * k0.x + q4.y * k0.y + q4.z * k0.z + q4.w * k0.w;
            float d1 = q4.x * k1.x + q4.y * k1.y + q4.z * k1.z + q4.w * k1.w;
            d0 = red8(d0);
            d1 = red8(d1);
            float p0 = __expf(d0 * scale);
            float p1 = __expf(d1 * scale);
            z += p0 + p1;
            acc4.x += p0 * v0.x + p1 * v1.x;
            acc4.y += p0 * v0.y + p1 * v1.y;
            acc4.z += p0 * v0.z + p1 * v1.z;
            acc4.w += p0 * v0.w + p1 * v1.w;
        }
        if (j < nchunk) {
            int s0 = __shfl_sync(0xffffffffu, sidx, j);
            const float4 k0 = *(const float4*)(k + (size_t)s0 * DI + 4 * lane);
            const float4 v0 = *(const float4*)(v + (size_t)s0 * DI + 4 * lane);
            float d0 = q4.x * k0.x + q4.y * k0.y + q4.z * k0.z + q4.w * k0.w;
            d0 = red8(d0);
            float p0 = __expf(d0 * scale);
            z += p0;
            acc4.x += p0 * v0.x;
            acc4.y += p0 * v0.y;
            acc4.z += p0 * v0.z;
            acc4.w += p0 * v0.w;
        }
    }

    float inv = 1.f / (z + 1e-16f);
    float4* op = (float4*)(out + (size_t)node * DI + 4 * lane);
    float4 o = *op;
    o.x += acc4.x * inv;
    o.y += acc4.y * inv;
    o.z += acc4.z * inv;
    o.w += acc4.w * inv;
    *op = o;
}

// ---------------- launch ----------------
extern "C" void kernel_launch(void* const* d_in, const int* in_sizes, int n_in,
                              void* d_out, int out_size) {
    const float* x   = (const float*)d_in[0];
    const int*   ei  = (const int*)d_in[1];
    const float* Wq  = (const float*)d_in[2];
    const float* bq  = (const float*)d_in[3];
    const float* Wk  = (const float*)d_in[4];
    const float* bk  = (const float*)d_in[5];
    const float* Wv  = (const float*)d_in[6];
    const float* bv  = (const float*)d_in[7];
    const float* Wsk = (const float*)d_in[8];
    const float* bsk = (const float*)d_in[9];
    float*       out = (float*)d_out;

    int n = in_sizes[0] / DI;
    int e = in_sizes[1] / 2;

    dim3 gb((n + 63) / 64), tb(256);
    gemm128x4<<<gb, tb>>>(x, Wq, bq, Wk, bk, Wv, bv, Wsk, bsk, out, n);

    sniff_dtype<<<1, 32>>>(ei, e);
    zero_deg<<<256, 256>>>(n);
    hist_edges<<<2048, 256>>>(ei, e, n);
    scan_deg<<<1, 1024>>>(n);
    fill_csr<<<2048, 256>>>(e);

    int blocks = (n * 32 + 255) / 256;
    attn_node<<<blocks, 256>>>(out, n);
}

// round 5
// speedup vs baseline: 1.2519x; 1.2519x over previous
#include <cuda_runtime.h>
#include <mma.h>
#include <math.h>

using namespace nvcuda;

#define NMAX 100000
#define EMAX 1600000
#define DI   128
#define H4   4
#define C32  32

// ---------------- static device scratch ----------------
__device__ float g_q[NMAX * DI];
__device__ float g_k[NMAX * DI];
__device__ float g_v[NMAX * DI];
__device__ int   g_src[EMAX];
__device__ int   g_dst[EMAX];
__device__ int   g_csr_src[EMAX];
__device__ int   g_deg[NMAX];
__device__ int   g_off[NMAX + 1];
__device__ int   g_cur[NMAX];
__device__ int   g_is64;

// ---------------- fused tf32 tensor-core GEMM ----------------
// Block: 128 rows x 128 cols, 256 threads (8 warps). X tile staged once in
// smem, reused across the 4 weight matrices. Warp w computes rows [16w,16w+16)
// as eight 16x16 tiles via m16n16k8 tf32 wmma. B frags read from global W
// (64 KB, L1-resident). Epilogue: per-warp smem staging + guarded store.
#define XLD 132   // padded lda for xs (16B-aligned rows)

__global__ __launch_bounds__(256) void gemm_tc(
    const float* __restrict__ X,
    const float* __restrict__ W0, const float* __restrict__ b0,
    const float* __restrict__ W1, const float* __restrict__ b1,
    const float* __restrict__ W2, const float* __restrict__ b2,
    const float* __restrict__ W3, const float* __restrict__ b3,
    float* __restrict__ out3, int n)
{
    __shared__ float xs[128 * XLD];        // ~67.5 KB
    __shared__ float stage[8][16 * 20];    // per-warp 16x16 staging, ldm 20

    int tid   = threadIdx.x;
    int warp  = tid >> 5;
    int lane  = tid & 31;
    int row0  = blockIdx.x * 128;

    // load X tile (128 rows x 128 k) into smem, zero-pad OOB rows
    {
        for (int t = 0; t < 16; t++) {
            int idx = tid + t * 256;        // 4096 float4 slots
            int r   = idx >> 5;             // 32 float4 per row
            int c4  = idx & 31;
            float4 xv = make_float4(0.f, 0.f, 0.f, 0.f);
            int gr = row0 + r;
            if (gr < n) xv = *(const float4*)(X + (size_t)gr * DI + c4 * 4);
            *(float4*)&xs[r * XLD + c4 * 4] = xv;
        }
    }
    __syncthreads();

    const float* Ws[4] = {W0, W1, W2, W3};
    const float* Bs[4] = {b0, b1, b2, b3};

    const float* xrow = &xs[warp * 16 * XLD];

#pragma unroll 1
    for (int w = 0; w < 4; w++) {
        const float* __restrict__ W = Ws[w];
        const float* __restrict__ B = Bs[w];

        wmma::fragment<wmma::accumulator, 16, 16, 8, float> acc[8];
#pragma unroll
        for (int nt = 0; nt < 8; nt++) wmma::fill_fragment(acc[nt], 0.f);

#pragma unroll 1
        for (int k0 = 0; k0 < DI; k0 += 8) {
            wmma::fragment<wmma::matrix_a, 16, 16, 8, wmma::precision::tf32, wmma::row_major> a;
            wmma::load_matrix_sync(a, xrow + k0, XLD);
#pragma unroll
            for (int t = 0; t < a.num_elements; t++) a.x[t] = wmma::__float_to_tf32(a.x[t]);
#pragma unroll
            for (int nt = 0; nt < 8; nt++) {
                wmma::fragment<wmma::matrix_b, 16, 16, 8, wmma::precision::tf32, wmma::row_major> b;
                wmma::load_matrix_sync(b, W + (size_t)k0 * DI + nt * 16, DI);
#pragma unroll
                for (int t = 0; t < b.num_elements; t++) b.x[t] = wmma::__float_to_tf32(b.x[t]);
                wmma::mma_sync(acc[nt], a, b, acc[nt]);
            }
        }

        float* out;
        if (w == 0)      out = g_q;
        else if (w == 1) out = g_k;
        else if (w == 2) out = g_v;
        else             out = out3;

        int rbase = row0 + warp * 16;
#pragma unroll 1
        for (int nt = 0; nt < 8; nt++) {
            wmma::store_matrix_sync(stage[warp], acc[nt], 20, wmma::mem_row_major);
            __syncwarp();
            // lanes: pairs per row; lane&1 selects 8-col half
            int r    = lane >> 1;
            int half = (lane & 1) * 8;
            int gr   = rbase + r;
            if (gr < n) {
                int col = nt * 16 + half;
                float4 s0 = *(float4*)&stage[warp][r * 20 + half];
                float4 s1 = *(float4*)&stage[warp][r * 20 + half + 4];
                float4 bv0 = *(const float4*)(B + col);
                float4 bv1 = *(const float4*)(B + col + 4);
                s0.x += bv0.x; s0.y += bv0.y; s0.z += bv0.z; s0.w += bv0.w;
                s1.x += bv1.x; s1.y += bv1.y; s1.z += bv1.z; s1.w += bv1.w;
                *(float4*)(out + (size_t)gr * DI + col)     = s0;
                *(float4*)(out + (size_t)gr * DI + col + 4) = s1;
            }
            __syncwarp();
        }
    }
}

// ---------------- edge dtype sniff + CSR build ----------------
__global__ void sniff_dtype(const int* __restrict__ ei32, int e) {
    if (threadIdx.x == 0 && blockIdx.x == 0) {
        int allzero = 1;
        int stride = (2 * e) / 256;
        if (stride < 2) stride = 2;
        for (int s = 0; s < 256; s++) {
            long long idx = (long long)s * stride | 1;
            if (idx < 4LL * e) {
                if (ei32[idx] != 0) { allzero = 0; break; }
            }
        }
        g_is64 = allzero;
    }
}

__global__ void zero_deg(int n) {
    for (int i = blockIdx.x * blockDim.x + threadIdx.x; i < n; i += gridDim.x * blockDim.x)
        g_deg[i] = 0;
}

__global__ void hist_edges(const int* __restrict__ ei32, int e, int n) {
    int is64 = g_is64;
    for (int i = blockIdx.x * blockDim.x + threadIdx.x; i < e; i += gridDim.x * blockDim.x) {
        int s, d;
        if (is64) {
            s = ei32[(size_t)2 * i];
            d = ei32[(size_t)2 * (e + i)];
        } else {
            s = ei32[i];
            d = ei32[(size_t)e + i];
        }
        s = min(max(s, 0), n - 1);
        d = min(max(d, 0), n - 1);
        g_src[i] = s;
        g_dst[i] = d;
        atomicAdd(&g_deg[d], 1);
    }
}

__global__ __launch_bounds__(1024) void scan_deg(int n) {
    __shared__ int wsum[32];
    __shared__ int s_carry;
    __shared__ int s_total;
    int tid = threadIdx.x, lane = tid & 31, wid = tid >> 5;
    if (tid == 0) s_carry = 0;
    __syncthreads();
    for (int base = 0; base < n; base += 1024) {
        int i = base + tid;
        int v = (i < n) ? g_deg[i] : 0;
        int inc = v;
#pragma unroll
        for (int o = 1; o < 32; o <<= 1) {
            int t = __shfl_up_sync(0xffffffffu, inc, o);
            if (lane >= o) inc += t;
        }
        if (lane == 31) wsum[wid] = inc;
        __syncthreads();
        if (wid == 0) {
            int w  = wsum[lane];
            int wi = w;
#pragma unroll
            for (int o = 1; o < 32; o <<= 1) {
                int t = __shfl_up_sync(0xffffffffu, wi, o);
                if (lane >= o) wi += t;
            }
            wsum[lane] = wi - w;
            if (lane == 31) s_total = wi;
        }
        __syncthreads();
        int excl = s_carry + wsum[wid] + (inc - v);
        if (i < n) { g_off[i] = excl; g_cur[i] = excl; }
        __syncthreads();
        if (tid == 0) s_carry += s_total;
        __syncthreads();
    }
    if (threadIdx.x == 0) g_off[n] = s_carry;
}

__global__ void fill_csr(int e) {
    for (int i = blockIdx.x * blockDim.x + threadIdx.x; i < e; i += gridDim.x * blockDim.x) {
        int d   = g_dst[i];
        int pos = atomicAdd(&g_cur[d], 1);
        g_csr_src[pos] = g_src[i];
    }
}

// ---------------- attention: one warp per node, all 4 heads ----------------
__device__ __forceinline__ float red8(float d) {
    d += __shfl_xor_sync(0xffffffffu, d, 4);
    d += __shfl_xor_sync(0xffffffffu, d, 2);
    d += __shfl_xor_sync(0xffffffffu, d, 1);
    return d;
}

__global__ __launch_bounds__(256) void attn_node(float* __restrict__ out, int n) {
    int warp = (blockIdx.x * blockDim.x + threadIdx.x) >> 5;
    int lane = threadIdx.x & 31;
    if (warp >= n) return;
    int node = warp;

    int base = g_off[node];
    int end  = g_off[node + 1];

    const float* __restrict__ k = g_k;
    const float* __restrict__ v = g_v;

    float4 q4 = *(const float4*)(g_q + (size_t)node * DI + 4 * lane);
    const float scale = 0.17677669529663688f;  // 1/sqrt(32)

    float  z    = 0.f;
    float4 acc4 = make_float4(0.f, 0.f, 0.f, 0.f);

    for (int i0 = base; i0 < end; i0 += 32) {
        int nchunk = min(32, end - i0);
        int sidx = (i0 + lane < end) ? g_csr_src[i0 + lane] : 0;

        int j = 0;
        for (; j + 1 < nchunk; j += 2) {
            int s0 = __shfl_sync(0xffffffffu, sidx, j);
            int s1 = __shfl_sync(0xffffffffu, sidx, j + 1);
            const float4 k0 = *(const float4*)(k + (size_t)s0 * DI + 4 * lane);
            const float4 k1 = *(const float4*)(k + (size_t)s1 * DI + 4 * lane);
            const float4 v0 = *(const float4*)(v + (size_t)s0 * DI + 4 * lane);
            const float4 v1 = *(const float4*)(v + (size_t)s1 * DI + 4 * lane);
            float d0 = q4.x * k0.x + q4.y * k0.y + q4.z * k0.z + q4.w * k0.w;
            float d1 = q4.x * k1.x + q4.y * k1.y + q4.z * k1.z + q4.w * k1.w;
            d0 = red8(d0);
            d1 = red8(d1);
            float p0 = __expf(d0 * scale);
            float p1 = __expf(d1 * scale);
            z += p0 + p1;
            acc4.x += p0 * v0.x + p1 * v1.x;
            acc4.y += p0 * v0.y + p1 * v1.y;
            acc4.z += p0 * v0.z + p1 * v1.z;
            acc4.w += p0 * v0.w + p1 * v1.w;
        }
        if (j < nchunk) {
            int s0 = __shfl_sync(0xffffffffu, sidx, j);
            const float4 k0 = *(const float4*)(k + (size_t)s0 * DI + 4 * lane);
            const float4 v0 = *(const float4*)(v + (size_t)s0 * DI + 4 * lane);
            float d0 = q4.x * k0.x + q4.y * k0.y + q4.z * k0.z + q4.w * k0.w;
            d0 = red8(d0);
            float p0 = __expf(d0 * scale);
            z += p0;
            acc4.x += p0 * v0.x;
            acc4.y += p0 * v0.y;
            acc4.z += p0 * v0.z;
            acc4.w += p0 * v0.w;
        }
    }

    float inv = 1.f / (z + 1e-16f);
    float4* op = (float4*)(out + (size_t)node * DI + 4 * lane);
    float4 o = *op;
    o.x += acc4.x * inv;
    o.y += acc4.y * inv;
    o.z += acc4.z * inv;
    o.w += acc4.w * inv;
    *op = o;
}

// ---------------- launch ----------------
extern "C" void kernel_launch(void* const* d_in, const int* in_sizes, int n_in,
                              void* d_out, int out_size) {
    const float* x   = (const float*)d_in[0];
    const int*   ei  = (const int*)d_in[1];
    const float* Wq  = (const float*)d_in[2];
    const float* bq  = (const float*)d_in[3];
    const float* Wk  = (const float*)d_in[4];
    const float* bk  = (const float*)d_in[5];
    const float* Wv  = (const float*)d_in[6];
    const float* bv  = (const float*)d_in[7];
    const float* Wsk = (const float*)d_in[8];
    const float* bsk = (const float*)d_in[9];
    float*       out = (float*)d_out;

    int n = in_sizes[0] / DI;
    int e = in_sizes[1] / 2;

    int gblocks = (n + 127) / 128;
    gemm_tc<<<gblocks, 256>>>(x, Wq, bq, Wk, bk, Wv, bv, Wsk, bsk, out, n);

    sniff_dtype<<<1, 32>>>(ei, e);
    zero_deg<<<256, 256>>>(n);
    hist_edges<<<2048, 256>>>(ei, e, n);
    scan_deg<<<1, 1024>>>(n);
    fill_csr<<<2048, 256>>>(e);

    int blocks = (n * 32 + 255) / 256;
    attn_node<<<blocks, 256>>>(out, n);
}

// round 6
// speedup vs baseline: 1.3555x; 1.0827x over previous
#include <cuda_runtime.h>
#include <mma.h>
#include <math.h>

using namespace nvcuda;

#define NMAX 100000
#define EMAX 1600000
#define DI   128
#define H4   4
#define C32  32
#define XLD  132   // padded leading dim for smem tiles (mult of 4)

// ---------------- static device scratch ----------------
__device__ float g_q[NMAX * DI];
__device__ float g_k[NMAX * DI];
__device__ float g_v[NMAX * DI];
__device__ int   g_src[EMAX];
__device__ int   g_dst[EMAX];
__device__ int   g_csr_src[EMAX];
__device__ int   g_deg[NMAX];
__device__ int   g_off[NMAX + 1];
__device__ int   g_cur[NMAX];
__device__ int   g_is64;

// ---------------- fused tf32 tensor-core GEMM, operands in smem ----------------
// Block: 64 rows x 128 cols, 256 threads (8 warps). X tile converted to tf32
// once in smem, reused across 4 weight matrices. W streamed in 16-k slices.
// Warp (wr,wc): rows [16wr,16wr+16), cols [64wc,64wc+64) -> 4 m16n16k8 accs.
__global__ __launch_bounds__(256) void gemm_tc2(
    const float* __restrict__ X,
    const float* __restrict__ W0, const float* __restrict__ b0,
    const float* __restrict__ W1, const float* __restrict__ b1,
    const float* __restrict__ W2, const float* __restrict__ b2,
    const float* __restrict__ W3, const float* __restrict__ b3,
    float* __restrict__ out3, int n)
{
    __shared__ float xs[64 * XLD];   // 33 KB, tf32-converted X tile
    __shared__ float ws[16 * XLD];   // 8.25 KB, tf32 W slice; reused as epi stage

    int tid  = threadIdx.x;
    int warp = tid >> 5;
    int lane = tid & 31;
    int row0 = blockIdx.x * 64;
    int wr   = warp >> 1;           // 0..3: 16-row group
    int wc   = warp & 1;            // 0..1: 64-col group

    // fill X tile (64 rows x 128 k), convert to tf32 at fill
    for (int t = 0; t < 8; t++) {
        int idx = tid + t * 256;          // 0..2047 float4 slots
        int r   = idx >> 5;
        int c4  = (idx & 31) * 4;
        float4 xv = make_float4(0.f, 0.f, 0.f, 0.f);
        int gr = row0 + r;
        if (gr < n) xv = *(const float4*)(X + (size_t)gr * DI + c4);
        xv.x = wmma::__float_to_tf32(xv.x);
        xv.y = wmma::__float_to_tf32(xv.y);
        xv.z = wmma::__float_to_tf32(xv.z);
        xv.w = wmma::__float_to_tf32(xv.w);
        *(float4*)&xs[r * XLD + c4] = xv;
    }

    const float* Ws[4] = {W0, W1, W2, W3};
    const float* Bs[4] = {b0, b1, b2, b3};

#pragma unroll 1
    for (int w = 0; w < 4; w++) {
        const float* __restrict__ W = Ws[w];

        wmma::fragment<wmma::accumulator, 16, 16, 8, float> acc[4];
#pragma unroll
        for (int nt = 0; nt < 4; nt++) wmma::fill_fragment(acc[nt], 0.f);

#pragma unroll 1
        for (int ks = 0; ks < 8; ks++) {
            __syncthreads();   // xs fill / prior ws readers / prior epi stage
            // stage W slice: 16 k-rows x 128 cols, coalesced float4, tf32
#pragma unroll
            for (int t = 0; t < 2; t++) {
                int idx = tid + t * 256;       // 0..511 float4 slots
                int kr  = idx >> 5;
                int c4  = (idx & 31) * 4;
                float4 wv = *(const float4*)(W + (size_t)(ks * 16 + kr) * DI + c4);
                wv.x = wmma::__float_to_tf32(wv.x);
                wv.y = wmma::__float_to_tf32(wv.y);
                wv.z = wmma::__float_to_tf32(wv.z);
                wv.w = wmma::__float_to_tf32(wv.w);
                *(float4*)&ws[kr * XLD + c4] = wv;
            }
            __syncthreads();
#pragma unroll
            for (int k8 = 0; k8 < 16; k8 += 8) {
                wmma::fragment<wmma::matrix_a, 16, 16, 8, wmma::precision::tf32, wmma::row_major> a;
                wmma::load_matrix_sync(a, xs + wr * 16 * XLD + ks * 16 + k8, XLD);
#pragma unroll
                for (int nt = 0; nt < 4; nt++) {
                    wmma::fragment<wmma::matrix_b, 16, 16, 8, wmma::precision::tf32, wmma::row_major> b;
                    wmma::load_matrix_sync(b, ws + k8 * XLD + wc * 64 + nt * 16, XLD);
                    wmma::mma_sync(acc[nt], a, b, acc[nt]);
                }
            }
        }

        float* out;
        if (w == 0)      out = g_q;
        else if (w == 1) out = g_k;
        else if (w == 2) out = g_v;
        else             out = out3;
        const float* B = Bs[w];

        __syncthreads();   // all warps done reading ws before staging into it
        float* stg = ws + warp * 264;   // 256 floats per warp + pad
        int rbase = row0 + wr * 16;
#pragma unroll 1
        for (int nt = 0; nt < 4; nt++) {
            wmma::store_matrix_sync(stg, acc[nt], 16, wmma::mem_row_major);
            __syncwarp();
            int r    = lane >> 1;
            int half = (lane & 1) * 8;
            int gr   = rbase + r;
            int col  = wc * 64 + nt * 16 + half;
            if (gr < n) {
                float4 s0 = *(float4*)&stg[r * 16 + half];
                float4 s1 = *(float4*)&stg[r * 16 + half + 4];
                float4 bv0 = *(const float4*)(B + col);
                float4 bv1 = *(const float4*)(B + col + 4);
                s0.x += bv0.x; s0.y += bv0.y; s0.z += bv0.z; s0.w += bv0.w;
                s1.x += bv1.x; s1.y += bv1.y; s1.z += bv1.z; s1.w += bv1.w;
                *(float4*)(out + (size_t)gr * DI + col)     = s0;
                *(float4*)(out + (size_t)gr * DI + col + 4) = s1;
            }
            __syncwarp();
        }
    }
}

// ---------------- edge dtype sniff + CSR build ----------------
__global__ void sniff_dtype(const int* __restrict__ ei32, int e) {
    if (threadIdx.x == 0 && blockIdx.x == 0) {
        int allzero = 1;
        int stride = (2 * e) / 256;
        if (stride < 2) stride = 2;
        for (int s = 0; s < 256; s++) {
            long long idx = (long long)s * stride | 1;
            if (idx < 4LL * e) {
                if (ei32[idx] != 0) { allzero = 0; break; }
            }
        }
        g_is64 = allzero;
    }
}

__global__ void zero_deg(int n) {
    for (int i = blockIdx.x * blockDim.x + threadIdx.x; i < n; i += gridDim.x * blockDim.x)
        g_deg[i] = 0;
}

__global__ void hist_edges(const int* __restrict__ ei32, int e, int n) {
    int is64 = g_is64;
    for (int i = blockIdx.x * blockDim.x + threadIdx.x; i < e; i += gridDim.x * blockDim.x) {
        int s, d;
        if (is64) {
            s = ei32[(size_t)2 * i];
            d = ei32[(size_t)2 * (e + i)];
        } else {
            s = ei32[i];
            d = ei32[(size_t)e + i];
        }
        s = min(max(s, 0), n - 1);
        d = min(max(d, 0), n - 1);
        g_src[i] = s;
        g_dst[i] = d;
        atomicAdd(&g_deg[d], 1);
    }
}

__global__ __launch_bounds__(1024) void scan_deg(int n) {
    __shared__ int wsum[32];
    __shared__ int s_carry;
    __shared__ int s_total;
    int tid = threadIdx.x, lane = tid & 31, wid = tid >> 5;
    if (tid == 0) s_carry = 0;
    __syncthreads();
    for (int base = 0; base < n; base += 1024) {
        int i = base + tid;
        int v = (i < n) ? g_deg[i] : 0;
        int inc = v;
#pragma unroll
        for (int o = 1; o < 32; o <<= 1) {
            int t = __shfl_up_sync(0xffffffffu, inc, o);
            if (lane >= o) inc += t;
        }
        if (lane == 31) wsum[wid] = inc;
        __syncthreads();
        if (wid == 0) {
            int w  = wsum[lane];
            int wi = w;
#pragma unroll
            for (int o = 1; o < 32; o <<= 1) {
                int t = __shfl_up_sync(0xffffffffu, wi, o);
                if (lane >= o) wi += t;
            }
            wsum[lane] = wi - w;
            if (lane == 31) s_total = wi;
        }
        __syncthreads();
        int excl = s_carry + wsum[wid] + (inc - v);
        if (i < n) { g_off[i] = excl; g_cur[i] = excl; }
        __syncthreads();
        if (tid == 0) s_carry += s_total;
        __syncthreads();
    }
    if (threadIdx.x == 0) g_off[n] = s_carry;
}

__global__ void fill_csr(int e) {
    for (int i = blockIdx.x * blockDim.x + threadIdx.x; i < e; i += gridDim.x * blockDim.x) {
        int d   = g_dst[i];
        int pos = atomicAdd(&g_cur[d], 1);
        g_csr_src[pos] = g_src[i];
    }
}

// ---------------- attention: one warp per node, all 4 heads ----------------
__device__ __forceinline__ float red8(float d) {
    d += __shfl_xor_sync(0xffffffffu, d, 4);
    d += __shfl_xor_sync(0xffffffffu, d, 2);
    d += __shfl_xor_sync(0xffffffffu, d, 1);
    return d;
}

__global__ __launch_bounds__(256) void attn_node(float* __restrict__ out, int n) {
    int warp = (blockIdx.x * blockDim.x + threadIdx.x) >> 5;
    int lane = threadIdx.x & 31;
    if (warp >= n) return;
    int node = warp;

    int base = g_off[node];
    int end  = g_off[node + 1];

    const float* __restrict__ k = g_k;
    const float* __restrict__ v = g_v;

    float4 q4 = *(const float4*)(g_q + (size_t)node * DI + 4 * lane);
    const float scale = 0.17677669529663688f;  // 1/sqrt(32)

    float  z    = 0.f;
    float4 acc4 = make_float4(0.f, 0.f, 0.f, 0.f);

    for (int i0 = base; i0 < end; i0 += 32) {
        int nchunk = min(32, end - i0);
        int sidx = (i0 + lane < end) ? g_csr_src[i0 + lane] : 0;

        int j = 0;
        for (; j + 1 < nchunk; j += 2) {
            int s0 = __shfl_sync(0xffffffffu, sidx, j);
            int s1 = __shfl_sync(0xffffffffu, sidx, j + 1);
            const float4 k0 = *(const float4*)(k + (size_t)s0 * DI + 4 * lane);
            const float4 k1 = *(const float4*)(k + (size_t)s1 * DI + 4 * lane);
            const float4 v0 = *(const float4*)(v + (size_t)s0 * DI + 4 * lane);
            const float4 v1 = *(const float4*)(v + (size_t)s1 * DI + 4 * lane);
            float d0 = q4.x * k0.x + q4.y * k0.y + q4.z * k0.z + q4.w * k0.w;
            float d1 = q4.x * k1.x + q4.y * k1.y + q4.z * k1.z + q4.w * k1.w;
            d0 = red8(d0);
            d1 = red8(d1);
            float p0 = __expf(d0 * scale);
            float p1 = __expf(d1 * scale);
            z += p0 + p1;
            acc4.x += p0 * v0.x + p1 * v1.x;
            acc4.y += p0 * v0.y + p1 * v1.y;
            acc4.z += p0 * v0.z + p1 * v1.z;
            acc4.w += p0 * v0.w + p1 * v1.w;
        }
        if (j < nchunk) {
            int s0 = __shfl_sync(0xffffffffu, sidx, j);
            const float4 k0 = *(const float4*)(k + (size_t)s0 * DI + 4 * lane);
            const float4 v0 = *(const float4*)(v + (size_t)s0 * DI + 4 * lane);
            float d0 = q4.x * k0.x + q4.y * k0.y + q4.z * k0.z + q4.w * k0.w;
            d0 = red8(d0);
            float p0 = __expf(d0 * scale);
            z += p0;
            acc4.x += p0 * v0.x;
            acc4.y += p0 * v0.y;
            acc4.z += p0 * v0.z;
            acc4.w += p0 * v0.w;
        }
    }

    float inv = 1.f / (z + 1e-16f);
    float4* op = (float4*)(out + (size_t)node * DI + 4 * lane);
    float4 o = *op;
    o.x += acc4.x * inv;
    o.y += acc4.y * inv;
    o.z += acc4.z * inv;
    o.w += acc4.w * inv;
    *op = o;
}

// ---------------- launch ----------------
extern "C" void kernel_launch(void* const* d_in, const int* in_sizes, int n_in,
                              void* d_out, int out_size) {
    const float* x   = (const float*)d_in[0];
    const int*   ei  = (const int*)d_in[1];
    const float* Wq  = (const float*)d_in[2];
    const float* bq  = (const float*)d_in[3];
    const float* Wk  = (const float*)d_in[4];
    const float* bk  = (const float*)d_in[5];
    const float* Wv  = (const float*)d_in[6];
    const float* bv  = (const float*)d_in[7];
    const float* Wsk = (const float*)d_in[8];
    const float* bsk = (const float*)d_in[9];
    float*       out = (float*)d_out;

    int n = in_sizes[0] / DI;
    int e = in_sizes[1] / 2;

    int gblocks = (n + 63) / 64;
    gemm_tc2<<<gblocks, 256>>>(x, Wq, bq, Wk, bk, Wv, bv, Wsk, bsk, out, n);

    sniff_dtype<<<1, 32>>>(ei, e);
    zero_deg<<<256, 256>>>(n);
    hist_edges<<<2048, 256>>>(ei, e, n);
    scan_deg<<<1, 1024>>>(n);
    fill_csr<<<2048, 256>>>(e);

    int blocks = (n * 32 + 255) / 256;
    attn_node<<<blocks, 256>>>(out, n);
}

// round 7
// speedup vs baseline: 1.4031x; 1.0351x over previous
#include <cuda_runtime.h>
#include <math.h>

#define NMAX 100000
#define EMAX 1600000
#define DI   128
#define H4   4
#define C32  32

// ---------------- static device scratch ----------------
__device__ float g_q[NMAX * DI];
__device__ float g_k[NMAX * DI];
__device__ float g_v[NMAX * DI];
__device__ int   g_src[EMAX];
__device__ int   g_dst[EMAX];
__device__ int   g_csr_src[EMAX];
__device__ int   g_deg[NMAX];
__device__ int   g_off[NMAX + 1];
__device__ int   g_cur[NMAX];
__device__ int   g_is64;

// ---------------- SGEMM: 128x128 block tile, 8x8 micro-tile ----------------
// grid = (ceil(n/128), 4); blockIdx.y selects which W/bias/output.
// 256 threads as 16x16; thread (tx,ty) owns rows ty*8..+8, cols tx*8..+8.
// Per kk: 2 LDS.128 (x) + 2 LDS.128 (w) + 64 FFMA.
#define XSL 132   // padded rows (528B = 33*16, float4-aligned)

__global__ __launch_bounds__(256) void sgemm(
    const float* __restrict__ X,
    const float* __restrict__ W0, const float* __restrict__ b0,
    const float* __restrict__ W1, const float* __restrict__ b1,
    const float* __restrict__ W2, const float* __restrict__ b2,
    const float* __restrict__ W3, const float* __restrict__ b3,
    float* __restrict__ out3, int n)
{
    __shared__ float xs[16 * XSL];   // [k][row] transposed X slice
    __shared__ float ws[16 * XSL];   // [k][col] W slice

    int tid = threadIdx.x;
    int tx  = tid & 15;
    int ty  = tid >> 4;
    int row0 = blockIdx.x * 128;
    int w    = blockIdx.y;

    const float* W;
    const float* B;
    float* out;
    if (w == 0)      { W = W0; B = b0; out = g_q; }
    else if (w == 1) { W = W1; B = b1; out = g_k; }
    else if (w == 2) { W = W2; B = b2; out = g_v; }
    else             { W = W3; B = b3; out = out3; }

    float acc[8][8];
#pragma unroll
    for (int i = 0; i < 8; i++)
#pragma unroll
        for (int j = 0; j < 8; j++) acc[i][j] = 0.f;

#pragma unroll 1
    for (int ks = 0; ks < 8; ks++) {
        int k0 = ks * 16;
        // stage X slice: 128 rows x 16 k -> xs[k][row] (transposed)
#pragma unroll
        for (int t = 0; t < 2; t++) {
            int slot = tid + t * 256;       // 0..511
            int r    = slot >> 2;           // 0..127
            int c4   = (slot & 3) * 4;      // 0,4,8,12
            float4 xv = make_float4(0.f, 0.f, 0.f, 0.f);
            int gr = row0 + r;
            if (gr < n) xv = *(const float4*)(X + (size_t)gr * DI + k0 + c4);
            xs[(c4 + 0) * XSL + r] = xv.x;
            xs[(c4 + 1) * XSL + r] = xv.y;
            xs[(c4 + 2) * XSL + r] = xv.z;
            xs[(c4 + 3) * XSL + r] = xv.w;
        }
        // stage W slice: 16 k x 128 cols (coalesced)
#pragma unroll
        for (int t = 0; t < 2; t++) {
            int slot = tid + t * 256;
            int kr   = slot >> 5;           // 0..15
            int c4   = (slot & 31) * 4;     // 0..124
            *(float4*)&ws[kr * XSL + c4] =
                *(const float4*)(W + (size_t)(k0 + kr) * DI + c4);
        }
        __syncthreads();
#pragma unroll
        for (int kk = 0; kk < 16; kk++) {
            float4 xa = *(const float4*)&xs[kk * XSL + ty * 8];
            float4 xb = *(const float4*)&xs[kk * XSL + ty * 8 + 4];
            float4 wa = *(const float4*)&ws[kk * XSL + tx * 8];
            float4 wb = *(const float4*)&ws[kk * XSL + tx * 8 + 4];
            float xr[8] = {xa.x, xa.y, xa.z, xa.w, xb.x, xb.y, xb.z, xb.w};
            float wr[8] = {wa.x, wa.y, wa.z, wa.w, wb.x, wb.y, wb.z, wb.w};
#pragma unroll
            for (int i = 0; i < 8; i++)
#pragma unroll
                for (int j = 0; j < 8; j++)
                    acc[i][j] += xr[i] * wr[j];
        }
        __syncthreads();
    }

    // epilogue: bias + store
    float4 bv0 = *(const float4*)(B + tx * 8);
    float4 bv1 = *(const float4*)(B + tx * 8 + 4);
#pragma unroll
    for (int i = 0; i < 8; i++) {
        int gr = row0 + ty * 8 + i;
        if (gr < n) {
            float4 o0 = make_float4(acc[i][0] + bv0.x, acc[i][1] + bv0.y,
                                    acc[i][2] + bv0.z, acc[i][3] + bv0.w);
            float4 o1 = make_float4(acc[i][4] + bv1.x, acc[i][5] + bv1.y,
                                    acc[i][6] + bv1.z, acc[i][7] + bv1.w);
            *(float4*)(out + (size_t)gr * DI + tx * 8)     = o0;
            *(float4*)(out + (size_t)gr * DI + tx * 8 + 4) = o1;
        }
    }
}

// ---------------- edge dtype sniff + CSR build ----------------
__global__ void sniff_dtype(const int* __restrict__ ei32, int e) {
    if (threadIdx.x == 0 && blockIdx.x == 0) {
        int allzero = 1;
        int stride = (2 * e) / 256;
        if (stride < 2) stride = 2;
        for (int s = 0; s < 256; s++) {
            long long idx = (long long)s * stride | 1;
            if (idx < 4LL * e) {
                if (ei32[idx] != 0) { allzero = 0; break; }
            }
        }
        g_is64 = allzero;
    }
}

__global__ void zero_deg(int n) {
    for (int i = blockIdx.x * blockDim.x + threadIdx.x; i < n; i += gridDim.x * blockDim.x)
        g_deg[i] = 0;
}

__global__ void hist_edges(const int* __restrict__ ei32, int e, int n) {
    int is64 = g_is64;
    for (int i = blockIdx.x * blockDim.x + threadIdx.x; i < e; i += gridDim.x * blockDim.x) {
        int s, d;
        if (is64) {
            s = ei32[(size_t)2 * i];
            d = ei32[(size_t)2 * (e + i)];
        } else {
            s = ei32[i];
            d = ei32[(size_t)e + i];
        }
        s = min(max(s, 0), n - 1);
        d = min(max(d, 0), n - 1);
        g_src[i] = s;
        g_dst[i] = d;
        atomicAdd(&g_deg[d], 1);
    }
}

__global__ __launch_bounds__(1024) void scan_deg(int n) {
    __shared__ int wsum[32];
    __shared__ int s_carry;
    __shared__ int s_total;
    int tid = threadIdx.x, lane = tid & 31, wid = tid >> 5;
    if (tid == 0) s_carry = 0;
    __syncthreads();
    for (int base = 0; base < n; base += 1024) {
        int i = base + tid;
        int v = (i < n) ? g_deg[i] : 0;
        int inc = v;
#pragma unroll
        for (int o = 1; o < 32; o <<= 1) {
            int t = __shfl_up_sync(0xffffffffu, inc, o);
            if (lane >= o) inc += t;
        }
        if (lane == 31) wsum[wid] = inc;
        __syncthreads();
        if (wid == 0) {
            int w  = wsum[lane];
            int wi = w;
#pragma unroll
            for (int o = 1; o < 32; o <<= 1) {
                int t = __shfl_up_sync(0xffffffffu, wi, o);
                if (lane >= o) wi += t;
            }
            wsum[lane] = wi - w;
            if (lane == 31) s_total = wi;
        }
        __syncthreads();
        int excl = s_carry + wsum[wid] + (inc - v);
        if (i < n) { g_off[i] = excl; g_cur[i] = excl; }
        __syncthreads();
        if (tid == 0) s_carry += s_total;
        __syncthreads();
    }
    if (threadIdx.x == 0) g_off[n] = s_carry;
}

__global__ void fill_csr(int e) {
    for (int i = blockIdx.x * blockDim.x + threadIdx.x; i < e; i += gridDim.x * blockDim.x) {
        int d   = g_dst[i];
        int pos = atomicAdd(&g_cur[d], 1);
        g_csr_src[pos] = g_src[i];
    }
}

// ---------------- attention: one warp per node, all 4 heads ----------------
__device__ __forceinline__ float red8(float d) {
    d += __shfl_xor_sync(0xffffffffu, d, 4);
    d += __shfl_xor_sync(0xffffffffu, d, 2);
    d += __shfl_xor_sync(0xffffffffu, d, 1);
    return d;
}

__global__ __launch_bounds__(256) void attn_node(float* __restrict__ out, int n) {
    int warp = (blockIdx.x * blockDim.x + threadIdx.x) >> 5;
    int lane = threadIdx.x & 31;
    if (warp >= n) return;
    int node = warp;

    int base = g_off[node];
    int end  = g_off[node + 1];

    const float* __restrict__ k = g_k;
    const float* __restrict__ v = g_v;

    float4 q4 = *(const float4*)(g_q + (size_t)node * DI + 4 * lane);
    const float scale = 0.17677669529663688f;  // 1/sqrt(32)

    float  z    = 0.f;
    float4 acc4 = make_float4(0.f, 0.f, 0.f, 0.f);

    for (int i0 = base; i0 < end; i0 += 32) {
        int nchunk = min(32, end - i0);
        int sidx = (i0 + lane < end) ? g_csr_src[i0 + lane] : 0;

        int j = 0;
        for (; j + 1 < nchunk; j += 2) {
            int s0 = __shfl_sync(0xffffffffu, sidx, j);
            int s1 = __shfl_sync(0xffffffffu, sidx, j + 1);
            const float4 k0 = *(const float4*)(k + (size_t)s0 * DI + 4 * lane);
            const float4 k1 = *(const float4*)(k + (size_t)s1 * DI + 4 * lane);
            const float4 v0 = *(const float4*)(v + (size_t)s0 * DI + 4 * lane);
            const float4 v1 = *(const float4*)(v + (size_t)s1 * DI + 4 * lane);
            float d0 = q4.x * k0.x + q4.y * k0.y + q4.z * k0.z + q4.w * k0.w;
            float d1 = q4.x * k1.x + q4.y * k1.y + q4.z * k1.z + q4.w * k1.w;
            d0 = red8(d0);
            d1 = red8(d1);
            float p0 = __expf(d0 * scale);
            float p1 = __expf(d1 * scale);
            z += p0 + p1;
            acc4.x += p0 * v0.x + p1 * v1.x;
            acc4.y += p0 * v0.y + p1 * v1.y;
            acc4.z += p0 * v0.z + p1 * v1.z;
            acc4.w += p0 * v0.w + p1 * v1.w;
        }
        if (j < nchunk) {
            int s0 = __shfl_sync(0xffffffffu, sidx, j);
            const float4 k0 = *(const float4*)(k + (size_t)s0 * DI + 4 * lane);
            const float4 v0 = *(const float4*)(v + (size_t)s0 * DI + 4 * lane);
            float d0 = q4.x * k0.x + q4.y * k0.y + q4.z * k0.z + q4.w * k0.w;
            d0 = red8(d0);
            float p0 = __expf(d0 * scale);
            z += p0;
            acc4.x += p0 * v0.x;
            acc4.y += p0 * v0.y;
            acc4.z += p0 * v0.z;
            acc4.w += p0 * v0.w;
        }
    }

    float inv = 1.f / (z + 1e-16f);
    float4* op = (float4*)(out + (size_t)node * DI + 4 * lane);
    float4 o = *op;
    o.x += acc4.x * inv;
    o.y += acc4.y * inv;
    o.z += acc4.z * inv;
    o.w += acc4.w * inv;
    *op = o;
}

// ---------------- launch ----------------
extern "C" void kernel_launch(void* const* d_in, const int* in_sizes, int n_in,
                              void* d_out, int out_size) {
    const float* x   = (const float*)d_in[0];
    const int*   ei  = (const int*)d_in[1];
    const float* Wq  = (const float*)d_in[2];
    const float* bq  = (const float*)d_in[3];
    const float* Wk  = (const float*)d_in[4];
    const float* bk  = (const float*)d_in[5];
    const float* Wv  = (const float*)d_in[6];
    const float* bv  = (const float*)d_in[7];
    const float* Wsk = (const float*)d_in[8];
    const float* bsk = (const float*)d_in[9];
    float*       out = (float*)d_out;

    int n = in_sizes[0] / DI;
    int e = in_sizes[1] / 2;

    dim3 gg((n + 127) / 128, 4);
    sgemm<<<gg, 256>>>(x, Wq, bq, Wk, bk, Wv, bv, Wsk, bsk, out, n);

    sniff_dtype<<<1, 32>>>(ei, e);
    zero_deg<<<256, 256>>>(n);
    hist_edges<<<2048, 256>>>(ei, e, n);
    scan_deg<<<1, 1024>>>(n);
    fill_csr<<<2048, 256>>>(e);

    int blocks = (n * 32 + 255) / 256;
    attn_node<<<blocks, 256>>>(out, n);
}

// round 8
// speedup vs baseline: 1.9862x; 1.4156x over previous
#include <cuda_runtime.h>
#include <math.h>

#define NMAX 100000
#define EMAX 1600000
#define DI   128
#define H4   4
#define C32  32
#define XLD  132   // pad: 132 mod 32 = 4 -> conflict-free A-frag loads

// ---------------- static device scratch ----------------
__device__ float g_q[NMAX * DI];
__device__ float g_k[NMAX * DI];
__device__ float g_v[NMAX * DI];
__device__ int   g_src[EMAX];
__device__ int   g_dst[EMAX];
__device__ int   g_csr_src[EMAX];
__device__ int   g_deg[NMAX];
__device__ int   g_off[NMAX + 1];
__device__ int   g_cur[NMAX];
__device__ int   g_is64;

// ---------------- tf32 mma helpers ----------------
__device__ __forceinline__ unsigned f2tf32(float f) {
    unsigned r;
    asm("cvt.rna.tf32.f32 %0, %1;" : "=r"(r) : "f"(f));
    return r;
}
__device__ __forceinline__ void mma_tf32(float* c, const unsigned* a, const unsigned* b) {
    asm volatile(
        "mma.sync.aligned.m16n8k8.row.col.f32.tf32.tf32.f32 "
        "{%0,%1,%2,%3}, {%4,%5,%6,%7}, {%8,%9}, {%0,%1,%2,%3};\n"
        : "+f"(c[0]), "+f"(c[1]), "+f"(c[2]), "+f"(c[3])
        : "r"(a[0]), "r"(a[1]), "r"(a[2]), "r"(a[3]), "r"(b[0]), "r"(b[1]));
}

// ---------------- tf32 tensor-core GEMM via raw mma.sync ----------------
// Block: 64 rows x 128 cols, 256 thr (8 warps); grid.y = which W.
// Warp owns 16 cols (2 n-tiles). B frags (16 ktiles x 2 ntiles x 2 regs = 64
// regs) preloaded once from L1-resident W. X tile staged to smem once
// (tf32-converted). Mainloop: LDS.32 A-frags + mma only, no syncs.
__global__ __launch_bounds__(256) void gemm_mma(
    const float* __restrict__ X,
    const float* __restrict__ W0, const float* __restrict__ b0,
    const float* __restrict__ W1, const float* __restrict__ b1,
    const float* __restrict__ W2, const float* __restrict__ b2,
    const float* __restrict__ W3, const float* __restrict__ b3,
    float* __restrict__ out3, int n)
{
    __shared__ float xs[64 * XLD];   // ~33.8 KB

    int tid  = threadIdx.x;
    int warp = tid >> 5;
    int lane = tid & 31;
    int row0 = blockIdx.x * 64;
    int w    = blockIdx.y;

    const float* W;
    const float* B;
    float* out;
    if (w == 0)      { W = W0; B = b0; out = g_q; }
    else if (w == 1) { W = W1; B = b1; out = g_k; }
    else if (w == 2) { W = W2; B = b2; out = g_v; }
    else             { W = W3; B = b3; out = out3; }

    // stage X tile (64 rows x 128 k), tf32-converted
#pragma unroll
    for (int t = 0; t < 8; t++) {
        int idx = tid + t * 256;          // 2048 float4 slots
        int r   = idx >> 5;
        int c4  = (idx & 31) * 4;
        float4 xv = make_float4(0.f, 0.f, 0.f, 0.f);
        int gr = row0 + r;
        if (gr < n) xv = *(const float4*)(X + (size_t)gr * DI + c4);
        xv.x = __uint_as_float(f2tf32(xv.x));
        xv.y = __uint_as_float(f2tf32(xv.y));
        xv.z = __uint_as_float(f2tf32(xv.z));
        xv.w = __uint_as_float(f2tf32(xv.w));
        *(float4*)&xs[r * XLD + c4] = xv;
    }
    __syncthreads();

    int n0 = warp * 16;
    int bk = lane & 3;        // k within tile
    int bn = lane >> 2;       // n within tile

    // preload B fragments: 16 ktiles x 2 ntiles x 2 regs
    unsigned bf[16][2][2];
#pragma unroll
    for (int kt = 0; kt < 16; kt++) {
#pragma unroll
        for (int nt = 0; nt < 2; nt++) {
            int col = n0 + nt * 8 + bn;
            bf[kt][nt][0] = f2tf32(W[(size_t)(kt * 8 + bk) * DI + col]);
            bf[kt][nt][1] = f2tf32(W[(size_t)(kt * 8 + bk + 4) * DI + col]);
        }
    }

    // bias for this thread's output cols
    float bias[2][2];
#pragma unroll
    for (int nt = 0; nt < 2; nt++) {
        int c = n0 + nt * 8 + 2 * (lane & 3);
        bias[nt][0] = B[c];
        bias[nt][1] = B[c + 1];
    }

    int arow = lane >> 2;     // 0..7
    int acol = lane & 3;

#pragma unroll
    for (int chunk = 0; chunk < 4; chunk++) {
        float acc[2][4];
#pragma unroll
        for (int nt = 0; nt < 2; nt++)
#pragma unroll
            for (int i = 0; i < 4; i++) acc[nt][i] = 0.f;

        const float* xr0 = &xs[(chunk * 16 + arow) * XLD];
        const float* xr1 = xr0 + 8 * XLD;
#pragma unroll
        for (int kt = 0; kt < 16; kt++) {
            unsigned af[4];
            af[0] = __float_as_uint(xr0[kt * 8 + acol]);
            af[1] = __float_as_uint(xr1[kt * 8 + acol]);
            af[2] = __float_as_uint(xr0[kt * 8 + acol + 4]);
            af[3] = __float_as_uint(xr1[kt * 8 + acol + 4]);
            mma_tf32(acc[0], af, bf[kt][0]);
            mma_tf32(acc[1], af, bf[kt][1]);
        }

        int r0 = row0 + chunk * 16 + arow;
#pragma unroll
        for (int nt = 0; nt < 2; nt++) {
            int c = n0 + nt * 8 + 2 * (lane & 3);
            if (r0 < n) {
                float2 o = make_float2(acc[nt][0] + bias[nt][0],
                                       acc[nt][1] + bias[nt][1]);
                *(float2*)(out + (size_t)r0 * DI + c) = o;
            }
            if (r0 + 8 < n) {
                float2 o = make_float2(acc[nt][2] + bias[nt][0],
                                       acc[nt][3] + bias[nt][1]);
                *(float2*)(out + (size_t)(r0 + 8) * DI + c) = o;
            }
        }
    }
}

// ---------------- edge dtype sniff + CSR build ----------------
__global__ void sniff_dtype(const int* __restrict__ ei32, int e) {
    if (threadIdx.x == 0 && blockIdx.x == 0) {
        int allzero = 1;
        int stride = (2 * e) / 256;
        if (stride < 2) stride = 2;
        for (int s = 0; s < 256; s++) {
            long long idx = (long long)s * stride | 1;
            if (idx < 4LL * e) {
                if (ei32[idx] != 0) { allzero = 0; break; }
            }
        }
        g_is64 = allzero;
    }
}

__global__ void zero_deg(int n) {
    for (int i = blockIdx.x * blockDim.x + threadIdx.x; i < n; i += gridDim.x * blockDim.x)
        g_deg[i] = 0;
}

__global__ void hist_edges(const int* __restrict__ ei32, int e, int n) {
    int is64 = g_is64;
    for (int i = blockIdx.x * blockDim.x + threadIdx.x; i < e; i += gridDim.x * blockDim.x) {
        int s, d;
        if (is64) {
            s = ei32[(size_t)2 * i];
            d = ei32[(size_t)2 * (e + i)];
        } else {
            s = ei32[i];
            d = ei32[(size_t)e + i];
        }
        s = min(max(s, 0), n - 1);
        d = min(max(d, 0), n - 1);
        g_src[i] = s;
        g_dst[i] = d;
        atomicAdd(&g_deg[d], 1);
    }
}

__global__ __launch_bounds__(1024) void scan_deg(int n) {
    __shared__ int wsum[32];
    __shared__ int s_carry;
    __shared__ int s_total;
    int tid = threadIdx.x, lane = tid & 31, wid = tid >> 5;
    if (tid == 0) s_carry = 0;
    __syncthreads();
    for (int base = 0; base < n; base += 1024) {
        int i = base + tid;
        int v = (i < n) ? g_deg[i] : 0;
        int inc = v;
#pragma unroll
        for (int o = 1; o < 32; o <<= 1) {
            int t = __shfl_up_sync(0xffffffffu, inc, o);
            if (lane >= o) inc += t;
        }
        if (lane == 31) wsum[wid] = inc;
        __syncthreads();
        if (wid == 0) {
            int w  = wsum[lane];
            int wi = w;
#pragma unroll
            for (int o = 1; o < 32; o <<= 1) {
                int t = __shfl_up_sync(0xffffffffu, wi, o);
                if (lane >= o) wi += t;
            }
            wsum[lane] = wi - w;
            if (lane == 31) s_total = wi;
        }
        __syncthreads();
        int excl = s_carry + wsum[wid] + (inc - v);
        if (i < n) { g_off[i] = excl; g_cur[i] = excl; }
        __syncthreads();
        if (tid == 0) s_carry += s_total;
        __syncthreads();
    }
    if (threadIdx.x == 0) g_off[n] = s_carry;
}

__global__ void fill_csr(int e) {
    for (int i = blockIdx.x * blockDim.x + threadIdx.x; i < e; i += gridDim.x * blockDim.x) {
        int d   = g_dst[i];
        int pos = atomicAdd(&g_cur[d], 1);
        g_csr_src[pos] = g_src[i];
    }
}

// ---------------- attention: one warp per node, all 4 heads ----------------
__device__ __forceinline__ float red8(float d) {
    d += __shfl_xor_sync(0xffffffffu, d, 4);
    d += __shfl_xor_sync(0xffffffffu, d, 2);
    d += __shfl_xor_sync(0xffffffffu, d, 1);
    return d;
}

__global__ __launch_bounds__(256) void attn_node(float* __restrict__ out, int n) {
    int warp = (blockIdx.x * blockDim.x + threadIdx.x) >> 5;
    int lane = threadIdx.x & 31;
    if (warp >= n) return;
    int node = warp;

    int base = g_off[node];
    int end  = g_off[node + 1];

    const float* __restrict__ k = g_k;
    const float* __restrict__ v = g_v;

    float4 q4 = *(const float4*)(g_q + (size_t)node * DI + 4 * lane);
    const float scale = 0.17677669529663688f;  // 1/sqrt(32)

    float  z    = 0.f;
    float4 acc4 = make_float4(0.f, 0.f, 0.f, 0.f);

    for (int i0 = base; i0 < end; i0 += 32) {
        int nchunk = min(32, end - i0);
        int sidx = (i0 + lane < end) ? g_csr_src[i0 + lane] : 0;

        int j = 0;
        for (; j + 1 < nchunk; j += 2) {
            int s0 = __shfl_sync(0xffffffffu, sidx, j);
            int s1 = __shfl_sync(0xffffffffu, sidx, j + 1);
            const float4 k0 = *(const float4*)(k + (size_t)s0 * DI + 4 * lane);
            const float4 k1 = *(const float4*)(k + (size_t)s1 * DI + 4 * lane);
            const float4 v0 = *(const float4*)(v + (size_t)s0 * DI + 4 * lane);
            const float4 v1 = *(const float4*)(v + (size_t)s1 * DI + 4 * lane);
            float d0 = q4.x * k0.x + q4.y * k0.y + q4.z * k0.z + q4.w * k0.w;
            float d1 = q4.x * k1.x + q4.y * k1.y + q4.z * k1.z + q4.w * k1.w;
            d0 = red8(d0);
            d1 = red8(d1);
            float p0 = __expf(d0 * scale);
            float p1 = __expf(d1 * scale);
            z += p0 + p1;
            acc4.x += p0 * v0.x + p1 * v1.x;
            acc4.y += p0 * v0.y + p1 * v1.y;
            acc4.z += p0 * v0.z + p1 * v1.z;
            acc4.w += p0 * v0.w + p1 * v1.w;
        }
        if (j < nchunk) {
            int s0 = __shfl_sync(0xffffffffu, sidx, j);
            const float4 k0 = *(const float4*)(k + (size_t)s0 * DI + 4 * lane);
            const float4 v0 = *(const float4*)(v + (size_t)s0 * DI + 4 * lane);
            float d0 = q4.x * k0.x + q4.y * k0.y + q4.z * k0.z + q4.w * k0.w;
            d0 = red8(d0);
            float p0 = __expf(d0 * scale);
            z += p0;
            acc4.x += p0 * v0.x;
            acc4.y += p0 * v0.y;
            acc4.z += p0 * v0.z;
            acc4.w += p0 * v0.w;
        }
    }

    float inv = 1.f / (z + 1e-16f);
    float4* op = (float4*)(out + (size_t)node * DI + 4 * lane);
    float4 o = *op;
    o.x += acc4.x * inv;
    o.y += acc4.y * inv;
    o.z += acc4.z * inv;
    o.w += acc4.w * inv;
    *op = o;
}

// ---------------- launch ----------------
extern "C" void kernel_launch(void* const* d_in, const int* in_sizes, int n_in,
                              void* d_out, int out_size) {
    const float* x   = (const float*)d_in[0];
    const int*   ei  = (const int*)d_in[1];
    const float* Wq  = (const float*)d_in[2];
    const float* bq  = (const float*)d_in[3];
    const float* Wk  = (const float*)d_in[4];
    const float* bk  = (const float*)d_in[5];
    const float* Wv  = (const float*)d_in[6];
    const float* bv  = (const float*)d_in[7];
    const float* Wsk = (const float*)d_in[8];
    const float* bsk = (const float*)d_in[9];
    float*       out = (float*)d_out;

    int n = in_sizes[0] / DI;
    int e = in_sizes[1] / 2;

    dim3 gg((n + 63) / 64, 4);
    gemm_mma<<<gg, 256>>>(x, Wq, bq, Wk, bk, Wv, bv, Wsk, bsk, out, n);

    sniff_dtype<<<1, 32>>>(ei, e);
    zero_deg<<<256, 256>>>(n);
    hist_edges<<<2048, 256>>>(ei, e, n);
    scan_deg<<<1, 1024>>>(n);
    fill_csr<<<2048, 256>>>(e);

    int blocks = (n * 32 + 255) / 256;
    attn_node<<<blocks, 256>>>(out, n);
}

// round 9
// speedup vs baseline: 2.1080x; 1.0613x over previous
#include <cuda_runtime.h>
#include <cuda_fp16.h>
#include <math.h>

#define NMAX 100000
#define EMAX 1600000
#define DI   128
#define H4   4
#define C32  32
#define XLD  132   // pad: 132 mod 32 = 4 -> conflict-free A-frag loads

// ---------------- static device scratch ----------------
__device__ float  g_q[NMAX * DI];
__device__ __half g_k[NMAX * DI];
__device__ __half g_v[NMAX * DI];
__device__ int    g_csr_src[EMAX];
__device__ int    g_deg[NMAX];
__device__ int    g_off[NMAX + 1];
__device__ int    g_cur[NMAX];
__device__ int    g_is64;

// ---------------- tf32 mma helpers ----------------
__device__ __forceinline__ unsigned f2tf32(float f) {
    unsigned r;
    asm("cvt.rna.tf32.f32 %0, %1;" : "=r"(r) : "f"(f));
    return r;
}
__device__ __forceinline__ void mma_tf32(float* c, const unsigned* a, const unsigned* b) {
    asm volatile(
        "mma.sync.aligned.m16n8k8.row.col.f32.tf32.tf32.f32 "
        "{%0,%1,%2,%3}, {%4,%5,%6,%7}, {%8,%9}, {%0,%1,%2,%3};\n"
        : "+f"(c[0]), "+f"(c[1]), "+f"(c[2]), "+f"(c[3])
        : "r"(a[0]), "r"(a[1]), "r"(a[2]), "r"(a[3]), "r"(b[0]), "r"(b[1]));
}

// ---------------- tf32 tensor-core GEMM via raw mma.sync ----------------
// Block: 64 rows x 128 cols, 256 thr (8 warps); grid.y = which W.
// k (w=1) and v (w=2) outputs stored as fp16 for the attention pass.
__global__ __launch_bounds__(256) void gemm_mma(
    const float* __restrict__ X,
    const float* __restrict__ W0, const float* __restrict__ b0,
    const float* __restrict__ W1, const float* __restrict__ b1,
    const float* __restrict__ W2, const float* __restrict__ b2,
    const float* __restrict__ W3, const float* __restrict__ b3,
    float* __restrict__ out3, int n)
{
    __shared__ float xs[64 * XLD];   // ~33.8 KB

    int tid  = threadIdx.x;
    int warp = tid >> 5;
    int lane = tid & 31;
    int row0 = blockIdx.x * 64;
    int w    = blockIdx.y;

    const float* W;
    const float* B;
    float*  outf = 0;
    __half* outh = 0;
    int ishalf = (w == 1 || w == 2);
    if (w == 0)      { W = W1 ? W0 : W0; W = W0; B = b0; outf = g_q; }
    else if (w == 1) { W = W1; B = b1; outh = g_k; }
    else if (w == 2) { W = W2; B = b2; outh = g_v; }
    else             { W = W3; B = b3; outf = out3; }

    // stage X tile (64 rows x 128 k), tf32-converted
#pragma unroll
    for (int t = 0; t < 8; t++) {
        int idx = tid + t * 256;
        int r   = idx >> 5;
        int c4  = (idx & 31) * 4;
        float4 xv = make_float4(0.f, 0.f, 0.f, 0.f);
        int gr = row0 + r;
        if (gr < n) xv = *(const float4*)(X + (size_t)gr * DI + c4);
        xv.x = __uint_as_float(f2tf32(xv.x));
        xv.y = __uint_as_float(f2tf32(xv.y));
        xv.z = __uint_as_float(f2tf32(xv.z));
        xv.w = __uint_as_float(f2tf32(xv.w));
        *(float4*)&xs[r * XLD + c4] = xv;
    }
    __syncthreads();

    int n0 = warp * 16;
    int bk = lane & 3;
    int bn = lane >> 2;

    // preload B fragments: 16 ktiles x 2 ntiles x 2 regs
    unsigned bf[16][2][2];
#pragma unroll
    for (int kt = 0; kt < 16; kt++) {
#pragma unroll
        for (int nt = 0; nt < 2; nt++) {
            int col = n0 + nt * 8 + bn;
            bf[kt][nt][0] = f2tf32(W[(size_t)(kt * 8 + bk) * DI + col]);
            bf[kt][nt][1] = f2tf32(W[(size_t)(kt * 8 + bk + 4) * DI + col]);
        }
    }

    float bias[2][2];
#pragma unroll
    for (int nt = 0; nt < 2; nt++) {
        int c = n0 + nt * 8 + 2 * (lane & 3);
        bias[nt][0] = B[c];
        bias[nt][1] = B[c + 1];
    }

    int arow = lane >> 2;
    int acol = lane & 3;

#pragma unroll
    for (int chunk = 0; chunk < 4; chunk++) {
        float acc[2][4];
#pragma unroll
        for (int nt = 0; nt < 2; nt++)
#pragma unroll
            for (int i = 0; i < 4; i++) acc[nt][i] = 0.f;

        const float* xr0 = &xs[(chunk * 16 + arow) * XLD];
        const float* xr1 = xr0 + 8 * XLD;
#pragma unroll
        for (int kt = 0; kt < 16; kt++) {
            unsigned af[4];
            af[0] = __float_as_uint(xr0[kt * 8 + acol]);
            af[1] = __float_as_uint(xr1[kt * 8 + acol]);
            af[2] = __float_as_uint(xr0[kt * 8 + acol + 4]);
            af[3] = __float_as_uint(xr1[kt * 8 + acol + 4]);
            mma_tf32(acc[0], af, bf[kt][0]);
            mma_tf32(acc[1], af, bf[kt][1]);
        }

        int r0 = row0 + chunk * 16 + arow;
#pragma unroll
        for (int nt = 0; nt < 2; nt++) {
            int c = n0 + nt * 8 + 2 * (lane & 3);
            float o00 = acc[nt][0] + bias[nt][0];
            float o01 = acc[nt][1] + bias[nt][1];
            float o10 = acc[nt][2] + bias[nt][0];
            float o11 = acc[nt][3] + bias[nt][1];
            if (ishalf) {
                if (r0 < n)
                    *(__half2*)(outh + (size_t)r0 * DI + c) = __floats2half2_rn(o00, o01);
                if (r0 + 8 < n)
                    *(__half2*)(outh + (size_t)(r0 + 8) * DI + c) = __floats2half2_rn(o10, o11);
            } else {
                if (r0 < n)
                    *(float2*)(outf + (size_t)r0 * DI + c) = make_float2(o00, o01);
                if (r0 + 8 < n)
                    *(float2*)(outf + (size_t)(r0 + 8) * DI + c) = make_float2(o10, o11);
            }
        }
    }
}

// ---------------- edge dtype sniff + CSR build ----------------
__global__ void sniff_dtype(const int* __restrict__ ei32, int e) {
    if (threadIdx.x == 0 && blockIdx.x == 0) {
        int allzero = 1;
        int stride = (2 * e) / 256;
        if (stride < 2) stride = 2;
        for (int s = 0; s < 256; s++) {
            long long idx = (long long)s * stride | 1;
            if (idx < 4LL * e) {
                if (ei32[idx] != 0) { allzero = 0; break; }
            }
        }
        g_is64 = allzero;
    }
}

__global__ void zero_deg(int n) {
    for (int i = blockIdx.x * blockDim.x + threadIdx.x; i < n; i += gridDim.x * blockDim.x)
        g_deg[i] = 0;
}

__device__ __forceinline__ int load_edge(const int* __restrict__ ei32,
                                         int is64, long long pos) {
    return is64 ? ei32[2 * pos] : ei32[pos];
}

__global__ void hist_edges(const int* __restrict__ ei32, int e, int n) {
    int is64 = g_is64;
    for (int i = blockIdx.x * blockDim.x + threadIdx.x; i < e; i += gridDim.x * blockDim.x) {
        int d = load_edge(ei32, is64, (long long)e + i);
        d = min(max(d, 0), n - 1);
        atomicAdd(&g_deg[d], 1);
    }
}

__global__ __launch_bounds__(1024) void scan_deg(int n) {
    __shared__ int wsum[32];
    __shared__ int s_carry;
    __shared__ int s_total;
    int tid = threadIdx.x, lane = tid & 31, wid = tid >> 5;
    if (tid == 0) s_carry = 0;
    __syncthreads();
    for (int base = 0; base < n; base += 1024) {
        int i = base + tid;
        int v = (i < n) ? g_deg[i] : 0;
        int inc = v;
#pragma unroll
        for (int o = 1; o < 32; o <<= 1) {
            int t = __shfl_up_sync(0xffffffffu, inc, o);
            if (lane >= o) inc += t;
        }
        if (lane == 31) wsum[wid] = inc;
        __syncthreads();
        if (wid == 0) {
            int w  = wsum[lane];
            int wi = w;
#pragma unroll
            for (int o = 1; o < 32; o <<= 1) {
                int t = __shfl_up_sync(0xffffffffu, wi, o);
                if (lane >= o) wi += t;
            }
            wsum[lane] = wi - w;
            if (lane == 31) s_total = wi;
        }
        __syncthreads();
        int excl = s_carry + wsum[wid] + (inc - v);
        if (i < n) { g_off[i] = excl; g_cur[i] = excl; }
        __syncthreads();
        if (tid == 0) s_carry += s_total;
        __syncthreads();
    }
    if (threadIdx.x == 0) g_off[n] = s_carry;
}

__global__ void fill_csr(const int* __restrict__ ei32, int e, int n) {
    int is64 = g_is64;
    for (int i = blockIdx.x * blockDim.x + threadIdx.x; i < e; i += gridDim.x * blockDim.x) {
        int s = load_edge(ei32, is64, i);
        int d = load_edge(ei32, is64, (long long)e + i);
        s = min(max(s, 0), n - 1);
        d = min(max(d, 0), n - 1);
        int pos = atomicAdd(&g_cur[d], 1);
        g_csr_src[pos] = s;
    }
}

// ---------------- attention: one warp per node, all 4 heads, fp16 k/v ----------------
__device__ __forceinline__ float red8(float d) {
    d += __shfl_xor_sync(0xffffffffu, d, 4);
    d += __shfl_xor_sync(0xffffffffu, d, 2);
    d += __shfl_xor_sync(0xffffffffu, d, 1);
    return d;
}

__global__ __launch_bounds__(256) void attn_node(float* __restrict__ out, int n) {
    int warp = (blockIdx.x * blockDim.x + threadIdx.x) >> 5;
    int lane = threadIdx.x & 31;
    if (warp >= n) return;
    int node = warp;

    int base = g_off[node];
    int end  = g_off[node + 1];

    const __half* __restrict__ kh = g_k;
    const __half* __restrict__ vh = g_v;

    float4 q4 = *(const float4*)(g_q + (size_t)node * DI + 4 * lane);
    const float scale = 0.17677669529663688f;  // 1/sqrt(32)

    float  z    = 0.f;
    float4 acc4 = make_float4(0.f, 0.f, 0.f, 0.f);

    for (int i0 = base; i0 < end; i0 += 32) {
        int nchunk = min(32, end - i0);
        int sidx = (i0 + lane < end) ? g_csr_src[i0 + lane] : 0;

        int j = 0;
        for (; j + 1 < nchunk; j += 2) {
            int s0 = __shfl_sync(0xffffffffu, sidx, j);
            int s1 = __shfl_sync(0xffffffffu, sidx, j + 1);
            uint2 kp0 = *(const uint2*)(kh + (size_t)s0 * DI + 4 * lane);
            uint2 kp1 = *(const uint2*)(kh + (size_t)s1 * DI + 4 * lane);
            uint2 vp0 = *(const uint2*)(vh + (size_t)s0 * DI + 4 * lane);
            uint2 vp1 = *(const uint2*)(vh + (size_t)s1 * DI + 4 * lane);
            float2 k0a = __half22float2(*(const __half2*)&kp0.x);
            float2 k0b = __half22float2(*(const __half2*)&kp0.y);
            float2 k1a = __half22float2(*(const __half2*)&kp1.x);
            float2 k1b = __half22float2(*(const __half2*)&kp1.y);
            float d0 = q4.x * k0a.x + q4.y * k0a.y + q4.z * k0b.x + q4.w * k0b.y;
            float d1 = q4.x * k1a.x + q4.y * k1a.y + q4.z * k1b.x + q4.w * k1b.y;
            d0 = red8(d0);
            d1 = red8(d1);
            float p0 = __expf(d0 * scale);
            float p1 = __expf(d1 * scale);
            z += p0 + p1;
            float2 v0a = __half22float2(*(const __half2*)&vp0.x);
            float2 v0b = __half22float2(*(const __half2*)&vp0.y);
            float2 v1a = __half22float2(*(const __half2*)&vp1.x);
            float2 v1b = __half22float2(*(const __half2*)&vp1.y);
            acc4.x += p0 * v0a.x + p1 * v1a.x;
            acc4.y += p0 * v0a.y + p1 * v1a.y;
            acc4.z += p0 * v0b.x + p1 * v1b.x;
            acc4.w += p0 * v0b.y + p1 * v1b.y;
        }
        if (j < nchunk) {
            int s0 = __shfl_sync(0xffffffffu, sidx, j);
            uint2 kp0 = *(const uint2*)(kh + (size_t)s0 * DI + 4 * lane);
            uint2 vp0 = *(const uint2*)(vh + (size_t)s0 * DI + 4 * lane);
            float2 k0a = __half22float2(*(const __half2*)&kp0.x);
            float2 k0b = __half22float2(*(const __half2*)&kp0.y);
            float d0 = q4.x * k0a.x + q4.y * k0a.y + q4.z * k0b.x + q4.w * k0b.y;
            d0 = red8(d0);
            float p0 = __expf(d0 * scale);
            z += p0;
            float2 v0a = __half22float2(*(const __half2*)&vp0.x);
            float2 v0b = __half22float2(*(const __half2*)&vp0.y);
            acc4.x += p0 * v0a.x;
            acc4.y += p0 * v0a.y;
            acc4.z += p0 * v0b.x;
            acc4.w += p0 * v0b.y;
        }
    }

    float inv = 1.f / (z + 1e-16f);
    float4* op = (float4*)(out + (size_t)node * DI + 4 * lane);
    float4 o = *op;
    o.x += acc4.x * inv;
    o.y += acc4.y * inv;
    o.z += acc4.z * inv;
    o.w += acc4.w * inv;
    *op = o;
}

// ---------------- launch ----------------
extern "C" void kernel_launch(void* const* d_in, const int* in_sizes, int n_in,
                              void* d_out, int out_size) {
    const float* x   = (const float*)d_in[0];
    const int*   ei  = (const int*)d_in[1];
    const float* Wq  = (const float*)d_in[2];
    const float* bq  = (const float*)d_in[3];
    const float* Wk  = (const float*)d_in[4];
    const float* bk  = (const float*)d_in[5];
    const float* Wv  = (const float*)d_in[6];
    const float* bv  = (const float*)d_in[7];
    const float* Wsk = (const float*)d_in[8];
    const float* bsk = (const float*)d_in[9];
    float*       out = (float*)d_out;

    int n = in_sizes[0] / DI;
    int e = in_sizes[1] / 2;

    dim3 gg((n + 63) / 64, 4);
    gemm_mma<<<gg, 256>>>(x, Wq, bq, Wk, bk, Wv, bv, Wsk, bsk, out, n);

    sniff_dtype<<<1, 32>>>(ei, e);
    zero_deg<<<256, 256>>>(n);
    hist_edges<<<2048, 256>>>(ei, e, n);
    scan_deg<<<1, 1024>>>(n);
    fill_csr<<<2048, 256>>>(ei, e, n);

    int blocks = (n * 32 + 255) / 256;
    attn_node<<<blocks, 256>>>(out, n);
}

// round 10
// speedup vs baseline: 2.4516x; 1.1630x over previous
#include <cuda_runtime.h>
#include <cuda_fp16.h>
#include <math.h>

#define NMAX 100000
#define EMAX 1600000
#define DI   128
#define H4   4
#define C32  32
#define XLD  132   // pad: 132 mod 32 = 4 -> conflict-free A-frag loads

// ---------------- static device scratch ----------------
__device__ float  g_q[NMAX * DI];
__device__ __half g_k[NMAX * DI];
__device__ __half g_v[NMAX * DI];
__device__ int    g_csr_src[EMAX];
__device__ int    g_deg[NMAX];
__device__ int    g_off[NMAX + 1];
__device__ int    g_cur[NMAX];
__device__ int    g_bsum[256];
__device__ int    g_is64;

// ---------------- tf32 mma helpers ----------------
__device__ __forceinline__ unsigned f2tf32(float f) {
    unsigned r;
    asm("cvt.rna.tf32.f32 %0, %1;" : "=r"(r) : "f"(f));
    return r;
}
__device__ __forceinline__ void mma_tf32(float* c, const unsigned* a, const unsigned* b) {
    asm volatile(
        "mma.sync.aligned.m16n8k8.row.col.f32.tf32.tf32.f32 "
        "{%0,%1,%2,%3}, {%4,%5,%6,%7}, {%8,%9}, {%0,%1,%2,%3};\n"
        : "+f"(c[0]), "+f"(c[1]), "+f"(c[2]), "+f"(c[3])
        : "r"(a[0]), "r"(a[1]), "r"(a[2]), "r"(a[3]), "r"(b[0]), "r"(b[1]));
}

// ---------------- tf32 tensor-core GEMM via raw mma.sync ----------------
__global__ __launch_bounds__(256) void gemm_mma(
    const float* __restrict__ X,
    const float* __restrict__ W0, const float* __restrict__ b0,
    const float* __restrict__ W1, const float* __restrict__ b1,
    const float* __restrict__ W2, const float* __restrict__ b2,
    const float* __restrict__ W3, const float* __restrict__ b3,
    float* __restrict__ out3, int n)
{
    __shared__ float xs[64 * XLD];

    int tid  = threadIdx.x;
    int warp = tid >> 5;
    int lane = tid & 31;
    int row0 = blockIdx.x * 64;
    int w    = blockIdx.y;

    const float* W;
    const float* B;
    float*  outf = 0;
    __half* outh = 0;
    int ishalf = (w == 1 || w == 2);
    if (w == 0)      { W = W0; B = b0; outf = g_q; }
    else if (w == 1) { W = W1; B = b1; outh = g_k; }
    else if (w == 2) { W = W2; B = b2; outh = g_v; }
    else             { W = W3; B = b3; outf = out3; }

    // stage X tile (64 rows x 128 k), tf32-converted
#pragma unroll
    for (int t = 0; t < 8; t++) {
        int idx = tid + t * 256;
        int r   = idx >> 5;
        int c4  = (idx & 31) * 4;
        float4 xv = make_float4(0.f, 0.f, 0.f, 0.f);
        int gr = row0 + r;
        if (gr < n) xv = *(const float4*)(X + (size_t)gr * DI + c4);
        xv.x = __uint_as_float(f2tf32(xv.x));
        xv.y = __uint_as_float(f2tf32(xv.y));
        xv.z = __uint_as_float(f2tf32(xv.z));
        xv.w = __uint_as_float(f2tf32(xv.w));
        *(float4*)&xs[r * XLD + c4] = xv;
    }
    __syncthreads();

    int n0 = warp * 16;
    int bk = lane & 3;
    int bn = lane >> 2;

    unsigned bf[16][2][2];
#pragma unroll
    for (int kt = 0; kt < 16; kt++) {
#pragma unroll
        for (int nt = 0; nt < 2; nt++) {
            int col = n0 + nt * 8 + bn;
            bf[kt][nt][0] = f2tf32(W[(size_t)(kt * 8 + bk) * DI + col]);
            bf[kt][nt][1] = f2tf32(W[(size_t)(kt * 8 + bk + 4) * DI + col]);
        }
    }

    float bias[2][2];
#pragma unroll
    for (int nt = 0; nt < 2; nt++) {
        int c = n0 + nt * 8 + 2 * (lane & 3);
        bias[nt][0] = B[c];
        bias[nt][1] = B[c + 1];
    }

    int arow = lane >> 2;
    int acol = lane & 3;

#pragma unroll
    for (int chunk = 0; chunk < 4; chunk++) {
        float acc[2][4];
#pragma unroll
        for (int nt = 0; nt < 2; nt++)
#pragma unroll
            for (int i = 0; i < 4; i++) acc[nt][i] = 0.f;

        const float* xr0 = &xs[(chunk * 16 + arow) * XLD];
        const float* xr1 = xr0 + 8 * XLD;
#pragma unroll
        for (int kt = 0; kt < 16; kt++) {
            unsigned af[4];
            af[0] = __float_as_uint(xr0[kt * 8 + acol]);
            af[1] = __float_as_uint(xr1[kt * 8 + acol]);
            af[2] = __float_as_uint(xr0[kt * 8 + acol + 4]);
            af[3] = __float_as_uint(xr1[kt * 8 + acol + 4]);
            mma_tf32(acc[0], af, bf[kt][0]);
            mma_tf32(acc[1], af, bf[kt][1]);
        }

        int r0 = row0 + chunk * 16 + arow;
#pragma unroll
        for (int nt = 0; nt < 2; nt++) {
            int c = n0 + nt * 8 + 2 * (lane & 3);
            float o00 = acc[nt][0] + bias[nt][0];
            float o01 = acc[nt][1] + bias[nt][1];
            float o10 = acc[nt][2] + bias[nt][0];
            float o11 = acc[nt][3] + bias[nt][1];
            if (ishalf) {
                if (r0 < n)
                    *(__half2*)(outh + (size_t)r0 * DI + c) = __floats2half2_rn(o00, o01);
                if (r0 + 8 < n)
                    *(__half2*)(outh + (size_t)(r0 + 8) * DI + c) = __floats2half2_rn(o10, o11);
            } else {
                if (r0 < n)
                    *(float2*)(outf + (size_t)r0 * DI + c) = make_float2(o00, o01);
                if (r0 + 8 < n)
                    *(float2*)(outf + (size_t)(r0 + 8) * DI + c) = make_float2(o10, o11);
            }
        }
    }
}

// ---------------- edge dtype sniff + CSR build ----------------
__global__ void sniff_dtype(const int* __restrict__ ei32, int e) {
    if (threadIdx.x == 0 && blockIdx.x == 0) {
        int allzero = 1;
        int stride = (2 * e) / 256;
        if (stride < 2) stride = 2;
        for (int s = 0; s < 256; s++) {
            long long idx = (long long)s * stride | 1;
            if (idx < 4LL * e) {
                if (ei32[idx] != 0) { allzero = 0; break; }
            }
        }
        g_is64 = allzero;
    }
}

__global__ void zero_deg(int n) {
    for (int i = blockIdx.x * blockDim.x + threadIdx.x; i < n; i += gridDim.x * blockDim.x)
        g_deg[i] = 0;
}

__device__ __forceinline__ int load_edge(const int* __restrict__ ei32,
                                         int is64, long long pos) {
    return is64 ? ei32[2 * pos] : ei32[pos];
}

__global__ void hist_edges(const int* __restrict__ ei32, int e, int n) {
    int is64 = g_is64;
    for (int i = blockIdx.x * blockDim.x + threadIdx.x; i < e; i += gridDim.x * blockDim.x) {
        int d = load_edge(ei32, is64, (long long)e + i);
        d = min(max(d, 0), n - 1);
        atomicAdd(&g_deg[d], 1);
    }
}

// ---------------- 3-phase parallel exclusive scan of g_deg -> g_off/g_cur ----------------
__global__ __launch_bounds__(1024) void scan_p1(int n) {
    __shared__ int wsum[32];
    int tid = threadIdx.x, lane = tid & 31, wid = tid >> 5;
    int i = blockIdx.x * 1024 + tid;
    int v = (i < n) ? g_deg[i] : 0;
    int inc = v;
#pragma unroll
    for (int o = 1; o < 32; o <<= 1) {
        int t = __shfl_up_sync(0xffffffffu, inc, o);
        if (lane >= o) inc += t;
    }
    if (lane == 31) wsum[wid] = inc;
    __syncthreads();
    if (wid == 0) {
        int wv = wsum[lane];
        int wi = wv;
#pragma unroll
        for (int o = 1; o < 32; o <<= 1) {
            int t = __shfl_up_sync(0xffffffffu, wi, o);
            if (lane >= o) wi += t;
        }
        wsum[lane] = wi - wv;
        if (lane == 31) g_bsum[blockIdx.x] = wi;
    }
    __syncthreads();
    if (i < n) g_off[i] = wsum[wid] + inc - v;   // block-local exclusive
}

__global__ void scan_p2(int nb) {
    // single warp scans block sums (nb <= 128)
    int lane = threadIdx.x;
    int acc = 0;
    for (int base = 0; base < nb; base += 32) {
        int v = (base + lane < nb) ? g_bsum[base + lane] : 0;
        int inc = v;
#pragma unroll
        for (int o = 1; o < 32; o <<= 1) {
            int t = __shfl_up_sync(0xffffffffu, inc, o);
            if (lane >= o) inc += t;
        }
        if (base + lane < nb) g_bsum[base + lane] = acc + inc - v;
        acc += __shfl_sync(0xffffffffu, inc, 31);
    }
    if (lane == 0) g_bsum[255] = acc;   // total
}

__global__ __launch_bounds__(1024) void scan_p3(int n) {
    int i = blockIdx.x * 1024 + threadIdx.x;
    if (i < n) {
        int off = g_off[i] + g_bsum[blockIdx.x];
        g_off[i] = off;
        g_cur[i] = off;
    }
    if (i == 0) g_off[n] = g_bsum[255];
}

__global__ void fill_csr(const int* __restrict__ ei32, int e, int n) {
    int is64 = g_is64;
    for (int i = blockIdx.x * blockDim.x + threadIdx.x; i < e; i += gridDim.x * blockDim.x) {
        int s = load_edge(ei32, is64, i);
        int d = load_edge(ei32, is64, (long long)e + i);
        s = min(max(s, 0), n - 1);
        d = min(max(d, 0), n - 1);
        int pos = atomicAdd(&g_cur[d], 1);
        g_csr_src[pos] = s;
    }
}

// ---------------- attention: one warp per node, all 4 heads, fp16 k/v, MLP=8 ----------------
__device__ __forceinline__ float red8(float d) {
    d += __shfl_xor_sync(0xffffffffu, d, 4);
    d += __shfl_xor_sync(0xffffffffu, d, 2);
    d += __shfl_xor_sync(0xffffffffu, d, 1);
    return d;
}

__device__ __forceinline__ float dot_h(const uint2 kp, float4 q4) {
    float2 a = __half22float2(*(const __half2*)&kp.x);
    float2 b = __half22float2(*(const __half2*)&kp.y);
    return q4.x * a.x + q4.y * a.y + q4.z * b.x + q4.w * b.y;
}

__global__ __launch_bounds__(256) void attn_node(float* __restrict__ out, int n) {
    int warp = (blockIdx.x * blockDim.x + threadIdx.x) >> 5;
    int lane = threadIdx.x & 31;
    if (warp >= n) return;
    int node = warp;

    int base = g_off[node];
    int end  = g_off[node + 1];

    const __half* __restrict__ kh = g_k;
    const __half* __restrict__ vh = g_v;

    float4 q4 = *(const float4*)(g_q + (size_t)node * DI + 4 * lane);
    const float scale = 0.17677669529663688f;  // 1/sqrt(32)

    float  z    = 0.f;
    float4 acc4 = make_float4(0.f, 0.f, 0.f, 0.f);

    for (int i0 = base; i0 < end; i0 += 32) {
        int nchunk = min(32, end - i0);
        int sidx = (i0 + lane < end) ? g_csr_src[i0 + lane] : 0;

        int j = 0;
        for (; j + 3 < nchunk; j += 4) {
            int s0 = __shfl_sync(0xffffffffu, sidx, j);
            int s1 = __shfl_sync(0xffffffffu, sidx, j + 1);
            int s2 = __shfl_sync(0xffffffffu, sidx, j + 2);
            int s3 = __shfl_sync(0xffffffffu, sidx, j + 3);
            // issue all 8 row loads before any consumption (MLP=8)
            uint2 kp0 = *(const uint2*)(kh + (size_t)s0 * DI + 4 * lane);
            uint2 kp1 = *(const uint2*)(kh + (size_t)s1 * DI + 4 * lane);
            uint2 kp2 = *(const uint2*)(kh + (size_t)s2 * DI + 4 * lane);
            uint2 kp3 = *(const uint2*)(kh + (size_t)s3 * DI + 4 * lane);
            uint2 vp0 = *(const uint2*)(vh + (size_t)s0 * DI + 4 * lane);
            uint2 vp1 = *(const uint2*)(vh + (size_t)s1 * DI + 4 * lane);
            uint2 vp2 = *(const uint2*)(vh + (size_t)s2 * DI + 4 * lane);
            uint2 vp3 = *(const uint2*)(vh + (size_t)s3 * DI + 4 * lane);

            float d0 = red8(dot_h(kp0, q4));
            float d1 = red8(dot_h(kp1, q4));
            float d2 = red8(dot_h(kp2, q4));
            float d3 = red8(dot_h(kp3, q4));
            float p0 = __expf(d0 * scale);
            float p1 = __expf(d1 * scale);
            float p2 = __expf(d2 * scale);
            float p3 = __expf(d3 * scale);
            z += (p0 + p1) + (p2 + p3);

            float2 v0a = __half22float2(*(const __half2*)&vp0.x);
            float2 v0b = __half22float2(*(const __half2*)&vp0.y);
            float2 v1a = __half22float2(*(const __half2*)&vp1.x);
            float2 v1b = __half22float2(*(const __half2*)&vp1.y);
            float2 v2a = __half22float2(*(const __half2*)&vp2.x);
            float2 v2b = __half22float2(*(const __half2*)&vp2.y);
            float2 v3a = __half22float2(*(const __half2*)&vp3.x);
            float2 v3b = __half22float2(*(const __half2*)&vp3.y);
            acc4.x += p0 * v0a.x + p1 * v1a.x + p2 * v2a.x + p3 * v3a.x;
            acc4.y += p0 * v0a.y + p1 * v1a.y + p2 * v2a.y + p3 * v3a.y;
            acc4.z += p0 * v0b.x + p1 * v1b.x + p2 * v2b.x + p3 * v3b.x;
            acc4.w += p0 * v0b.y + p1 * v1b.y + p2 * v2b.y + p3 * v3b.y;
        }
        for (; j < nchunk; j++) {
            int s0 = __shfl_sync(0xffffffffu, sidx, j);
            uint2 kp0 = *(const uint2*)(kh + (size_t)s0 * DI + 4 * lane);
            uint2 vp0 = *(const uint2*)(vh + (size_t)s0 * DI + 4 * lane);
            float d0 = red8(dot_h(kp0, q4));
            float p0 = __expf(d0 * scale);
            z += p0;
            float2 v0a = __half22float2(*(const __half2*)&vp0.x);
            float2 v0b = __half22float2(*(const __half2*)&vp0.y);
            acc4.x += p0 * v0a.x;
            acc4.y += p0 * v0a.y;
            acc4.z += p0 * v0b.x;
            acc4.w += p0 * v0b.y;
        }
    }

    float inv = 1.f / (z + 1e-16f);
    float4* op = (float4*)(out + (size_t)node * DI + 4 * lane);
    float4 o = *op;
    o.x += acc4.x * inv;
    o.y += acc4.y * inv;
    o.z += acc4.z * inv;
    o.w += acc4.w * inv;
    *op = o;
}

// ---------------- launch ----------------
extern "C" void kernel_launch(void* const* d_in, const int* in_sizes, int n_in,
                              void* d_out, int out_size) {
    const float* x   = (const float*)d_in[0];
    const int*   ei  = (const int*)d_in[1];
    const float* Wq  = (const float*)d_in[2];
    const float* bq  = (const float*)d_in[3];
    const float* Wk  = (const float*)d_in[4];
    const float* bk  = (const float*)d_in[5];
    const float* Wv  = (const float*)d_in[6];
    const float* bv  = (const float*)d_in[7];
    const float* Wsk = (const float*)d_in[8];
    const float* bsk = (const float*)d_in[9];
    float*       out = (float*)d_out;

    int n = in_sizes[0] / DI;
    int e = in_sizes[1] / 2;

    dim3 gg((n + 63) / 64, 4);
    gemm_mma<<<gg, 256>>>(x, Wq, bq, Wk, bk, Wv, bv, Wsk, bsk, out, n);

    sniff_dtype<<<1, 32>>>(ei, e);
    zero_deg<<<256, 256>>>(n);
    hist_edges<<<2048, 256>>>(ei, e, n);

    int nb = (n + 1023) / 1024;
    scan_p1<<<nb, 1024>>>(n);
    scan_p2<<<1, 32>>>(nb);
    scan_p3<<<nb, 1024>>>(n);

    fill_csr<<<2048, 256>>>(ei, e, n);

    int blocks = (n * 32 + 255) / 256;
    attn_node<<<blocks, 256>>>(out, n);
}

// round 11
// speedup vs baseline: 2.5180x; 1.0271x over previous
#include <cuda_runtime.h>
#include <cuda_fp16.h>
#include <math.h>

#define NMAX 100000
#define EMAX 1600000
#define DI   128
#define H4   4
#define C32  32
#define XLD  132   // pad: 132 mod 32 = 4 -> conflict-free A-frag loads

// ---------------- static device scratch ----------------
__device__ float  g_q[NMAX * DI];
__device__ __half g_k[NMAX * DI];
__device__ __half g_v[NMAX * DI];
__device__ int    g_csr_src[EMAX];
__device__ int    g_deg[NMAX];
__device__ int    g_off[NMAX + 1];
__device__ int    g_cur[NMAX];
__device__ int    g_bsum[256];
__device__ int    g_is64;

// ---------------- tf32 mma helpers ----------------
__device__ __forceinline__ unsigned f2tf32(float f) {
    unsigned r;
    asm("cvt.rna.tf32.f32 %0, %1;" : "=r"(r) : "f"(f));
    return r;
}
__device__ __forceinline__ void mma_tf32(float* c, const unsigned* a, const unsigned* b) {
    asm volatile(
        "mma.sync.aligned.m16n8k8.row.col.f32.tf32.tf32.f32 "
        "{%0,%1,%2,%3}, {%4,%5,%6,%7}, {%8,%9}, {%0,%1,%2,%3};\n"
        : "+f"(c[0]), "+f"(c[1]), "+f"(c[2]), "+f"(c[3])
        : "r"(a[0]), "r"(a[1]), "r"(a[2]), "r"(a[3]), "r"(b[0]), "r"(b[1]));
}

// ---------------- fused tf32 tensor-core GEMM: all 4 W in one launch ----------------
// Block: 64 rows x 128 cols, 256 thr (8 warps). X tile staged to smem ONCE
// (tf32-converted), then loop over the 4 weight matrices. B frags preloaded
// into 64 regs per w from the L1-resident W. Mainloop: LDS A-frags + mma only.
__global__ __launch_bounds__(256) void gemm_mma(
    const float* __restrict__ X,
    const float* __restrict__ W0, const float* __restrict__ b0,
    const float* __restrict__ W1, const float* __restrict__ b1,
    const float* __restrict__ W2, const float* __restrict__ b2,
    const float* __restrict__ W3, const float* __restrict__ b3,
    float* __restrict__ out3, int n)
{
    __shared__ float xs[64 * XLD];

    int tid  = threadIdx.x;
    int warp = tid >> 5;
    int lane = tid & 31;
    int row0 = blockIdx.x * 64;

    // stage X tile (64 rows x 128 k), tf32-converted -- ONCE per block
#pragma unroll
    for (int t = 0; t < 8; t++) {
        int idx = tid + t * 256;
        int r   = idx >> 5;
        int c4  = (idx & 31) * 4;
        float4 xv = make_float4(0.f, 0.f, 0.f, 0.f);
        int gr = row0 + r;
        if (gr < n) xv = *(const float4*)(X + (size_t)gr * DI + c4);
        xv.x = __uint_as_float(f2tf32(xv.x));
        xv.y = __uint_as_float(f2tf32(xv.y));
        xv.z = __uint_as_float(f2tf32(xv.z));
        xv.w = __uint_as_float(f2tf32(xv.w));
        *(float4*)&xs[r * XLD + c4] = xv;
    }
    __syncthreads();

    const float* Ws[4] = {W0, W1, W2, W3};
    const float* Bs[4] = {b0, b1, b2, b3};

    int n0 = warp * 16;
    int bk = lane & 3;
    int bn = lane >> 2;
    int arow = lane >> 2;
    int acol = lane & 3;

#pragma unroll 1
    for (int w = 0; w < 4; w++) {
        const float* __restrict__ W = Ws[w];
        const float* __restrict__ B = Bs[w];
        float*  outf = 0;
        __half* outh = 0;
        int ishalf = (w == 1 || w == 2);
        if (w == 0)      outf = g_q;
        else if (w == 1) outh = g_k;
        else if (w == 2) outh = g_v;
        else             outf = out3;

        // preload B fragments: 16 ktiles x 2 ntiles x 2 regs (independent LDGs)
        unsigned bf[16][2][2];
#pragma unroll
        for (int kt = 0; kt < 16; kt++) {
#pragma unroll
            for (int nt = 0; nt < 2; nt++) {
                int col = n0 + nt * 8 + bn;
                bf[kt][nt][0] = f2tf32(W[(size_t)(kt * 8 + bk) * DI + col]);
                bf[kt][nt][1] = f2tf32(W[(size_t)(kt * 8 + bk + 4) * DI + col]);
            }
        }

        float bias[2][2];
#pragma unroll
        for (int nt = 0; nt < 2; nt++) {
            int c = n0 + nt * 8 + 2 * (lane & 3);
            bias[nt][0] = B[c];
            bias[nt][1] = B[c + 1];
        }

#pragma unroll
        for (int chunk = 0; chunk < 4; chunk++) {
            float acc[2][4];
#pragma unroll
            for (int nt = 0; nt < 2; nt++)
#pragma unroll
                for (int i = 0; i < 4; i++) acc[nt][i] = 0.f;

            const float* xr0 = &xs[(chunk * 16 + arow) * XLD];
            const float* xr1 = xr0 + 8 * XLD;
#pragma unroll
            for (int kt = 0; kt < 16; kt++) {
                unsigned af[4];
                af[0] = __float_as_uint(xr0[kt * 8 + acol]);
                af[1] = __float_as_uint(xr1[kt * 8 + acol]);
                af[2] = __float_as_uint(xr0[kt * 8 + acol + 4]);
                af[3] = __float_as_uint(xr1[kt * 8 + acol + 4]);
                mma_tf32(acc[0], af, bf[kt][0]);
                mma_tf32(acc[1], af, bf[kt][1]);
            }

            int r0 = row0 + chunk * 16 + arow;
#pragma unroll
            for (int nt = 0; nt < 2; nt++) {
                int c = n0 + nt * 8 + 2 * (lane & 3);
                float o00 = acc[nt][0] + bias[nt][0];
                float o01 = acc[nt][1] + bias[nt][1];
                float o10 = acc[nt][2] + bias[nt][0];
                float o11 = acc[nt][3] + bias[nt][1];
                if (ishalf) {
                    if (r0 < n)
                        *(__half2*)(outh + (size_t)r0 * DI + c) = __floats2half2_rn(o00, o01);
                    if (r0 + 8 < n)
                        *(__half2*)(outh + (size_t)(r0 + 8) * DI + c) = __floats2half2_rn(o10, o11);
                } else {
                    if (r0 < n)
                        *(float2*)(outf + (size_t)r0 * DI + c) = make_float2(o00, o01);
                    if (r0 + 8 < n)
                        *(float2*)(outf + (size_t)(r0 + 8) * DI + c) = make_float2(o10, o11);
                }
            }
        }
    }
}

// ---------------- edge dtype sniff + CSR build ----------------
__global__ void sniff_dtype(const int* __restrict__ ei32, int e) {
    if (threadIdx.x == 0 && blockIdx.x == 0) {
        int allzero = 1;
        int stride = (2 * e) / 256;
        if (stride < 2) stride = 2;
        for (int s = 0; s < 256; s++) {
            long long idx = (long long)s * stride | 1;
            if (idx < 4LL * e) {
                if (ei32[idx] != 0) { allzero = 0; break; }
            }
        }
        g_is64 = allzero;
    }
}

__global__ void zero_deg(int n) {
    for (int i = blockIdx.x * blockDim.x + threadIdx.x; i < n; i += gridDim.x * blockDim.x)
        g_deg[i] = 0;
}

__device__ __forceinline__ int load_edge(const int* __restrict__ ei32,
                                         int is64, long long pos) {
    return is64 ? ei32[2 * pos] : ei32[pos];
}

__global__ void hist_edges(const int* __restrict__ ei32, int e, int n) {
    int is64 = g_is64;
    for (int i = blockIdx.x * blockDim.x + threadIdx.x; i < e; i += gridDim.x * blockDim.x) {
        int d = load_edge(ei32, is64, (long long)e + i);
        d = min(max(d, 0), n - 1);
        atomicAdd(&g_deg[d], 1);
    }
}

// ---------------- 3-phase parallel exclusive scan of g_deg -> g_off/g_cur ----------------
__global__ __launch_bounds__(1024) void scan_p1(int n) {
    __shared__ int wsum[32];
    int tid = threadIdx.x, lane = tid & 31, wid = tid >> 5;
    int i = blockIdx.x * 1024 + tid;
    int v = (i < n) ? g_deg[i] : 0;
    int inc = v;
#pragma unroll
    for (int o = 1; o < 32; o <<= 1) {
        int t = __shfl_up_sync(0xffffffffu, inc, o);
        if (lane >= o) inc += t;
    }
    if (lane == 31) wsum[wid] = inc;
    __syncthreads();
    if (wid == 0) {
        int wv = wsum[lane];
        int wi = wv;
#pragma unroll
        for (int o = 1; o < 32; o <<= 1) {
            int t = __shfl_up_sync(0xffffffffu, wi, o);
            if (lane >= o) wi += t;
        }
        wsum[lane] = wi - wv;
        if (lane == 31) g_bsum[blockIdx.x] = wi;
    }
    __syncthreads();
    if (i < n) g_off[i] = wsum[wid] + inc - v;
}

__global__ void scan_p2(int nb) {
    int lane = threadIdx.x;
    int acc = 0;
    for (int base = 0; base < nb; base += 32) {
        int v = (base + lane < nb) ? g_bsum[base + lane] : 0;
        int inc = v;
#pragma unroll
        for (int o = 1; o < 32; o <<= 1) {
            int t = __shfl_up_sync(0xffffffffu, inc, o);
            if (lane >= o) inc += t;
        }
        if (base + lane < nb) g_bsum[base + lane] = acc + inc - v;
        acc += __shfl_sync(0xffffffffu, inc, 31);
    }
    if (lane == 0) g_bsum[255] = acc;
}

__global__ __launch_bounds__(1024) void scan_p3(int n) {
    int i = blockIdx.x * 1024 + threadIdx.x;
    if (i < n) {
        int off = g_off[i] + g_bsum[blockIdx.x];
        g_off[i] = off;
        g_cur[i] = off;
    }
    if (i == 0) g_off[n] = g_bsum[255];
}

__global__ void fill_csr(const int* __restrict__ ei32, int e, int n) {
    int is64 = g_is64;
    for (int i = blockIdx.x * blockDim.x + threadIdx.x; i < e; i += gridDim.x * blockDim.x) {
        int s = load_edge(ei32, is64, i);
        int d = load_edge(ei32, is64, (long long)e + i);
        s = min(max(s, 0), n - 1);
        d = min(max(d, 0), n - 1);
        int pos = atomicAdd(&g_cur[d], 1);
        g_csr_src[pos] = s;
    }
}

// ---------------- attention: one warp per node, all 4 heads, fp16 k/v, MLP=8 ----------------
__device__ __forceinline__ float red8(float d) {
    d += __shfl_xor_sync(0xffffffffu, d, 4);
    d += __shfl_xor_sync(0xffffffffu, d, 2);
    d += __shfl_xor_sync(0xffffffffu, d, 1);
    return d;
}

__device__ __forceinline__ float dot_h(const uint2 kp, float4 q4) {
    float2 a = __half22float2(*(const __half2*)&kp.x);
    float2 b = __half22float2(*(const __half2*)&kp.y);
    return q4.x * a.x + q4.y * a.y + q4.z * b.x + q4.w * b.y;
}

__global__ __launch_bounds__(256) void attn_node(float* __restrict__ out, int n) {
    int warp = (blockIdx.x * blockDim.x + threadIdx.x) >> 5;
    int lane = threadIdx.x & 31;
    if (warp >= n) return;
    int node = warp;

    int base = g_off[node];
    int end  = g_off[node + 1];

    const __half* __restrict__ kh = g_k;
    const __half* __restrict__ vh = g_v;

    float4 q4 = *(const float4*)(g_q + (size_t)node * DI + 4 * lane);
    const float scale = 0.17677669529663688f;  // 1/sqrt(32)

    float  z    = 0.f;
    float4 acc4 = make_float4(0.f, 0.f, 0.f, 0.f);

    for (int i0 = base; i0 < end; i0 += 32) {
        int nchunk = min(32, end - i0);
        int sidx = (i0 + lane < end) ? g_csr_src[i0 + lane] : 0;

        int j = 0;
        for (; j + 3 < nchunk; j += 4) {
            int s0 = __shfl_sync(0xffffffffu, sidx, j);
            int s1 = __shfl_sync(0xffffffffu, sidx, j + 1);
            int s2 = __shfl_sync(0xffffffffu, sidx, j + 2);
            int s3 = __shfl_sync(0xffffffffu, sidx, j + 3);
            uint2 kp0 = *(const uint2*)(kh + (size_t)s0 * DI + 4 * lane);
            uint2 kp1 = *(const uint2*)(kh + (size_t)s1 * DI + 4 * lane);
            uint2 kp2 = *(const uint2*)(kh + (size_t)s2 * DI + 4 * lane);
            uint2 kp3 = *(const uint2*)(kh + (size_t)s3 * DI + 4 * lane);
            uint2 vp0 = *(const uint2*)(vh + (size_t)s0 * DI + 4 * lane);
            uint2 vp1 = *(const uint2*)(vh + (size_t)s1 * DI + 4 * lane);
            uint2 vp2 = *(const uint2*)(vh + (size_t)s2 * DI + 4 * lane);
            uint2 vp3 = *(const uint2*)(vh + (size_t)s3 * DI + 4 * lane);

            float d0 = red8(dot_h(kp0, q4));
            float d1 = red8(dot_h(kp1, q4));
            float d2 = red8(dot_h(kp2, q4));
            float d3 = red8(dot_h(kp3, q4));
            float p0 = __expf(d0 * scale);
            float p1 = __expf(d1 * scale);
            float p2 = __expf(d2 * scale);
            float p3 = __expf(d3 * scale);
            z += (p0 + p1) + (p2 + p3);

            float2 v0a = __half22float2(*(const __half2*)&vp0.x);
            float2 v0b = __half22float2(*(const __half2*)&vp0.y);
            float2 v1a = __half22float2(*(const __half2*)&vp1.x);
            float2 v1b = __half22float2(*(const __half2*)&vp1.y);
            float2 v2a = __half22float2(*(const __half2*)&vp2.x);
            float2 v2b = __half22float2(*(const __half2*)&vp2.y);
            float2 v3a = __half22float2(*(const __half2*)&vp3.x);
            float2 v3b = __half22float2(*(const __half2*)&vp3.y);
            acc4.x += p0 * v0a.x + p1 * v1a.x + p2 * v2a.x + p3 * v3a.x;
            acc4.y += p0 * v0a.y + p1 * v1a.y + p2 * v2a.y + p3 * v3a.y;
            acc4.z += p0 * v0b.x + p1 * v1b.x + p2 * v2b.x + p3 * v3b.x;
            acc4.w += p0 * v0b.y + p1 * v1b.y + p2 * v2b.y + p3 * v3b.y;
        }
        for (; j < nchunk; j++) {
            int s0 = __shfl_sync(0xffffffffu, sidx, j);
            uint2 kp0 = *(const uint2*)(kh + (size_t)s0 * DI + 4 * lane);
            uint2 vp0 = *(const uint2*)(vh + (size_t)s0 * DI + 4 * lane);
            float d0 = red8(dot_h(kp0, q4));
            float p0 = __expf(d0 * scale);
            z += p0;
            float2 v0a = __half22float2(*(const __half2*)&vp0.x);
            float2 v0b = __half22float2(*(const __half2*)&vp0.y);
            acc4.x += p0 * v0a.x;
            acc4.y += p0 * v0a.y;
            acc4.z += p0 * v0b.x;
            acc4.w += p0 * v0b.y;
        }
    }

    float inv = 1.f / (z + 1e-16f);
    float4* op = (float4*)(out + (size_t)node * DI + 4 * lane);
    float4 o = *op;
    o.x += acc4.x * inv;
    o.y += acc4.y * inv;
    o.z += acc4.z * inv;
    o.w += acc4.w * inv;
    *op = o;
}

// ---------------- launch ----------------
extern "C" void kernel_launch(void* const* d_in, const int* in_sizes, int n_in,
                              void* d_out, int out_size) {
    const float* x   = (const float*)d_in[0];
    const int*   ei  = (const int*)d_in[1];
    const float* Wq  = (const float*)d_in[2];
    const float* bq  = (const float*)d_in[3];
    const float* Wk  = (const float*)d_in[4];
    const float* bk  = (const float*)d_in[5];
    const float* Wv  = (const float*)d_in[6];
    const float* bv  = (const float*)d_in[7];
    const float* Wsk = (const float*)d_in[8];
    const float* bsk = (const float*)d_in[9];
    float*       out = (float*)d_out;

    int n = in_sizes[0] / DI;
    int e = in_sizes[1] / 2;

    int gblocks = (n + 63) / 64;
    gemm_mma<<<gblocks, 256>>>(x, Wq, bq, Wk, bk, Wv, bv, Wsk, bsk, out, n);

    sniff_dtype<<<1, 32>>>(ei, e);
    zero_deg<<<256, 256>>>(n);
    hist_edges<<<2048, 256>>>(ei, e, n);

    int nb = (n + 1023) / 1024;
    scan_p1<<<nb, 1024>>>(n);
    scan_p2<<<1, 32>>>(nb);
    scan_p3<<<nb, 1024>>>(n);

    fill_csr<<<2048, 256>>>(ei, e, n);

    int blocks = (n * 32 + 255) / 256;
    attn_node<<<blocks, 256>>>(out, n);
}

// round 12
// speedup vs baseline: 2.6355x; 1.0467x over previous
#include <cuda_runtime.h>
#include <cuda_fp16.h>
#include <math.h>

#define NMAX 100000
#define EMAX 1600000
#define DI   128
#define H4   4
#define C32  32
#define XLD  132   // pad: 132 mod 32 = 4 -> conflict-free A-frag loads

// ---------------- static device scratch ----------------
__device__ float  g_q[NMAX * DI];
__device__ __half g_k[NMAX * DI];
__device__ __half g_v[NMAX * DI];
__device__ int    g_csr_src[EMAX];
__device__ int    g_deg[NMAX];
__device__ int    g_off[NMAX + 1];
__device__ int    g_cur[NMAX];
__device__ int    g_bsum[256];
__device__ int    g_is64;

// ---------------- tf32 mma helpers ----------------
__device__ __forceinline__ unsigned f2tf32(float f) {
    unsigned r;
    asm("cvt.rna.tf32.f32 %0, %1;" : "=r"(r) : "f"(f));
    return r;
}
__device__ __forceinline__ void mma_tf32(float* c, const unsigned* a, const unsigned* b) {
    asm volatile(
        "mma.sync.aligned.m16n8k8.row.col.f32.tf32.tf32.f32 "
        "{%0,%1,%2,%3}, {%4,%5,%6,%7}, {%8,%9}, {%0,%1,%2,%3};\n"
        : "+f"(c[0]), "+f"(c[1]), "+f"(c[2]), "+f"(c[3])
        : "r"(a[0]), "r"(a[1]), "r"(a[2]), "r"(a[3]), "r"(b[0]), "r"(b[1]));
}

// ---------------- fused tf32 tensor-core GEMM: all 4 W in one launch ----------------
__global__ __launch_bounds__(256) void gemm_mma(
    const float* __restrict__ X,
    const float* __restrict__ W0, const float* __restrict__ b0,
    const float* __restrict__ W1, const float* __restrict__ b1,
    const float* __restrict__ W2, const float* __restrict__ b2,
    const float* __restrict__ W3, const float* __restrict__ b3,
    float* __restrict__ out3, int n)
{
    __shared__ float xs[64 * XLD];

    int tid  = threadIdx.x;
    int warp = tid >> 5;
    int lane = tid & 31;
    int row0 = blockIdx.x * 64;

#pragma unroll
    for (int t = 0; t < 8; t++) {
        int idx = tid + t * 256;
        int r   = idx >> 5;
        int c4  = (idx & 31) * 4;
        float4 xv = make_float4(0.f, 0.f, 0.f, 0.f);
        int gr = row0 + r;
        if (gr < n) xv = *(const float4*)(X + (size_t)gr * DI + c4);
        xv.x = __uint_as_float(f2tf32(xv.x));
        xv.y = __uint_as_float(f2tf32(xv.y));
        xv.z = __uint_as_float(f2tf32(xv.z));
        xv.w = __uint_as_float(f2tf32(xv.w));
        *(float4*)&xs[r * XLD + c4] = xv;
    }
    __syncthreads();

    const float* Ws[4] = {W0, W1, W2, W3};
    const float* Bs[4] = {b0, b1, b2, b3};

    int n0 = warp * 16;
    int bk = lane & 3;
    int bn = lane >> 2;
    int arow = lane >> 2;
    int acol = lane & 3;

#pragma unroll 1
    for (int w = 0; w < 4; w++) {
        const float* __restrict__ W = Ws[w];
        const float* __restrict__ B = Bs[w];
        float*  outf = 0;
        __half* outh = 0;
        int ishalf = (w == 1 || w == 2);
        if (w == 0)      outf = g_q;
        else if (w == 1) outh = g_k;
        else if (w == 2) outh = g_v;
        else             outf = out3;

        unsigned bf[16][2][2];
#pragma unroll
        for (int kt = 0; kt < 16; kt++) {
#pragma unroll
            for (int nt = 0; nt < 2; nt++) {
                int col = n0 + nt * 8 + bn;
                bf[kt][nt][0] = f2tf32(W[(size_t)(kt * 8 + bk) * DI + col]);
                bf[kt][nt][1] = f2tf32(W[(size_t)(kt * 8 + bk + 4) * DI + col]);
            }
        }

        float bias[2][2];
#pragma unroll
        for (int nt = 0; nt < 2; nt++) {
            int c = n0 + nt * 8 + 2 * (lane & 3);
            bias[nt][0] = B[c];
            bias[nt][1] = B[c + 1];
        }

#pragma unroll
        for (int chunk = 0; chunk < 4; chunk++) {
            float acc[2][4];
#pragma unroll
            for (int nt = 0; nt < 2; nt++)
#pragma unroll
                for (int i = 0; i < 4; i++) acc[nt][i] = 0.f;

            const float* xr0 = &xs[(chunk * 16 + arow) * XLD];
            const float* xr1 = xr0 + 8 * XLD;
#pragma unroll
            for (int kt = 0; kt < 16; kt++) {
                unsigned af[4];
                af[0] = __float_as_uint(xr0[kt * 8 + acol]);
                af[1] = __float_as_uint(xr1[kt * 8 + acol]);
                af[2] = __float_as_uint(xr0[kt * 8 + acol + 4]);
                af[3] = __float_as_uint(xr1[kt * 8 + acol + 4]);
                mma_tf32(acc[0], af, bf[kt][0]);
                mma_tf32(acc[1], af, bf[kt][1]);
            }

            int r0 = row0 + chunk * 16 + arow;
#pragma unroll
            for (int nt = 0; nt < 2; nt++) {
                int c = n0 + nt * 8 + 2 * (lane & 3);
                float o00 = acc[nt][0] + bias[nt][0];
                float o01 = acc[nt][1] + bias[nt][1];
                float o10 = acc[nt][2] + bias[nt][0];
                float o11 = acc[nt][3] + bias[nt][1];
                if (ishalf) {
                    if (r0 < n)
                        *(__half2*)(outh + (size_t)r0 * DI + c) = __floats2half2_rn(o00, o01);
                    if (r0 + 8 < n)
                        *(__half2*)(outh + (size_t)(r0 + 8) * DI + c) = __floats2half2_rn(o10, o11);
                } else {
                    if (r0 < n)
                        *(float2*)(outf + (size_t)r0 * DI + c) = make_float2(o00, o01);
                    if (r0 + 8 < n)
                        *(float2*)(outf + (size_t)(r0 + 8) * DI + c) = make_float2(o10, o11);
                }
            }
        }
    }
}

// ---------------- edge dtype sniff + CSR build ----------------
__global__ void sniff_dtype(const int* __restrict__ ei32, int e) {
    if (threadIdx.x == 0 && blockIdx.x == 0) {
        int allzero = 1;
        int stride = (2 * e) / 256;
        if (stride < 2) stride = 2;
        for (int s = 0; s < 256; s++) {
            long long idx = (long long)s * stride | 1;
            if (idx < 4LL * e) {
                if (ei32[idx] != 0) { allzero = 0; break; }
            }
        }
        g_is64 = allzero;
    }
}

__global__ void zero_deg(int n) {
    for (int i = blockIdx.x * blockDim.x + threadIdx.x; i < n; i += gridDim.x * blockDim.x)
        g_deg[i] = 0;
}

__device__ __forceinline__ int load_edge(const int* __restrict__ ei32,
                                         int is64, long long pos) {
    return is64 ? ei32[2 * pos] : ei32[pos];
}

__global__ void hist_edges(const int* __restrict__ ei32, int e, int n) {
    int is64 = g_is64;
    for (int i = blockIdx.x * blockDim.x + threadIdx.x; i < e; i += gridDim.x * blockDim.x) {
        int d = load_edge(ei32, is64, (long long)e + i);
        d = min(max(d, 0), n - 1);
        atomicAdd(&g_deg[d], 1);
    }
}

// ---------------- 3-phase parallel exclusive scan ----------------
__global__ __launch_bounds__(1024) void scan_p1(int n) {
    __shared__ int wsum[32];
    int tid = threadIdx.x, lane = tid & 31, wid = tid >> 5;
    int i = blockIdx.x * 1024 + tid;
    int v = (i < n) ? g_deg[i] : 0;
    int inc = v;
#pragma unroll
    for (int o = 1; o < 32; o <<= 1) {
        int t = __shfl_up_sync(0xffffffffu, inc, o);
        if (lane >= o) inc += t;
    }
    if (lane == 31) wsum[wid] = inc;
    __syncthreads();
    if (wid == 0) {
        int wv = wsum[lane];
        int wi = wv;
#pragma unroll
        for (int o = 1; o < 32; o <<= 1) {
            int t = __shfl_up_sync(0xffffffffu, wi, o);
            if (lane >= o) wi += t;
        }
        wsum[lane] = wi - wv;
        if (lane == 31) g_bsum[blockIdx.x] = wi;
    }
    __syncthreads();
    if (i < n) g_off[i] = wsum[wid] + inc - v;
}

__global__ void scan_p2(int nb) {
    int lane = threadIdx.x;
    int acc = 0;
    for (int base = 0; base < nb; base += 32) {
        int v = (base + lane < nb) ? g_bsum[base + lane] : 0;
        int inc = v;
#pragma unroll
        for (int o = 1; o < 32; o <<= 1) {
            int t = __shfl_up_sync(0xffffffffu, inc, o);
            if (lane >= o) inc += t;
        }
        if (base + lane < nb) g_bsum[base + lane] = acc + inc - v;
        acc += __shfl_sync(0xffffffffu, inc, 31);
    }
    if (lane == 0) g_bsum[255] = acc;
}

__global__ __launch_bounds__(1024) void scan_p3(int n) {
    int i = blockIdx.x * 1024 + threadIdx.x;
    if (i < n) {
        int off = g_off[i] + g_bsum[blockIdx.x];
        g_off[i] = off;
        g_cur[i] = off;
    }
    if (i == 0) g_off[n] = g_bsum[255];
}

__global__ void fill_csr(const int* __restrict__ ei32, int e, int n) {
    int is64 = g_is64;
    for (int i = blockIdx.x * blockDim.x + threadIdx.x; i < e; i += gridDim.x * blockDim.x) {
        int s = load_edge(ei32, is64, i);
        int d = load_edge(ei32, is64, (long long)e + i);
        s = min(max(s, 0), n - 1);
        d = min(max(d, 0), n - 1);
        int pos = atomicAdd(&g_cur[d], 1);
        g_csr_src[pos] = s;
    }
}

// ---------------- attention: one warp per node, all 4 heads, fp16 k/v, MLP=8 ----------------
__device__ __forceinline__ float red8(float d) {
    d += __shfl_xor_sync(0xffffffffu, d, 4);
    d += __shfl_xor_sync(0xffffffffu, d, 2);
    d += __shfl_xor_sync(0xffffffffu, d, 1);
    return d;
}

__device__ __forceinline__ float dot_h(const uint2 kp, float4 q4) {
    float2 a = __half22float2(*(const __half2*)&kp.x);
    float2 b = __half22float2(*(const __half2*)&kp.y);
    return q4.x * a.x + q4.y * a.y + q4.z * b.x + q4.w * b.y;
}

__global__ __launch_bounds__(256) void attn_node(float* __restrict__ out, int n) {
    int warp = (blockIdx.x * blockDim.x + threadIdx.x) >> 5;
    int lane = threadIdx.x & 31;
    if (warp >= n) return;
    int node = warp;

    int base = g_off[node];
    int end  = g_off[node + 1];

    const __half* __restrict__ kh = g_k;
    const __half* __restrict__ vh = g_v;

    float4 q4 = *(const float4*)(g_q + (size_t)node * DI + 4 * lane);
    const float scale = 0.17677669529663688f;  // 1/sqrt(32)

    float  z    = 0.f;
    float4 acc4 = make_float4(0.f, 0.f, 0.f, 0.f);

    for (int i0 = base; i0 < end; i0 += 32) {
        int nchunk = min(32, end - i0);
        int sidx = (i0 + lane < end) ? g_csr_src[i0 + lane] : 0;

        int j = 0;
        for (; j + 3 < nchunk; j += 4) {
            int s0 = __shfl_sync(0xffffffffu, sidx, j);
            int s1 = __shfl_sync(0xffffffffu, sidx, j + 1);
            int s2 = __shfl_sync(0xffffffffu, sidx, j + 2);
            int s3 = __shfl_sync(0xffffffffu, sidx, j + 3);
            uint2 kp0 = *(const uint2*)(kh + (size_t)s0 * DI + 4 * lane);
            uint2 kp1 = *(const uint2*)(kh + (size_t)s1 * DI + 4 * lane);
            uint2 kp2 = *(const uint2*)(kh + (size_t)s2 * DI + 4 * lane);
            uint2 kp3 = *(const uint2*)(kh + (size_t)s3 * DI + 4 * lane);
            uint2 vp0 = *(const uint2*)(vh + (size_t)s0 * DI + 4 * lane);
            uint2 vp1 = *(const uint2*)(vh + (size_t)s1 * DI + 4 * lane);
            uint2 vp2 = *(const uint2*)(vh + (size_t)s2 * DI + 4 * lane);
            uint2 vp3 = *(const uint2*)(vh + (size_t)s3 * DI + 4 * lane);

            float d0 = red8(dot_h(kp0, q4));
            float d1 = red8(dot_h(kp1, q4));
            float d2 = red8(dot_h(kp2, q4));
            float d3 = red8(dot_h(kp3, q4));
            float p0 = __expf(d0 * scale);
            float p1 = __expf(d1 * scale);
            float p2 = __expf(d2 * scale);
            float p3 = __expf(d3 * scale);
            z += (p0 + p1) + (p2 + p3);

            float2 v0a = __half22float2(*(const __half2*)&vp0.x);
            float2 v0b = __half22float2(*(const __half2*)&vp0.y);
            float2 v1a = __half22float2(*(const __half2*)&vp1.x);
            float2 v1b = __half22float2(*(const __half2*)&vp1.y);
            float2 v2a = __half22float2(*(const __half2*)&vp2.x);
            float2 v2b = __half22float2(*(const __half2*)&vp2.y);
            float2 v3a = __half22float2(*(const __half2*)&vp3.x);
            float2 v3b = __half22float2(*(const __half2*)&vp3.y);
            acc4.x += p0 * v0a.x + p1 * v1a.x + p2 * v2a.x + p3 * v3a.x;
            acc4.y += p0 * v0a.y + p1 * v1a.y + p2 * v2a.y + p3 * v3a.y;
            acc4.z += p0 * v0b.x + p1 * v1b.x + p2 * v2b.x + p3 * v3b.x;
            acc4.w += p0 * v0b.y + p1 * v1b.y + p2 * v2b.y + p3 * v3b.y;
        }
        for (; j < nchunk; j++) {
            int s0 = __shfl_sync(0xffffffffu, sidx, j);
            uint2 kp0 = *(const uint2*)(kh + (size_t)s0 * DI + 4 * lane);
            uint2 vp0 = *(const uint2*)(vh + (size_t)s0 * DI + 4 * lane);
            float d0 = red8(dot_h(kp0, q4));
            float p0 = __expf(d0 * scale);
            z += p0;
            float2 v0a = __half22float2(*(const __half2*)&vp0.x);
            float2 v0b = __half22float2(*(const __half2*)&vp0.y);
            acc4.x += p0 * v0a.x;
            acc4.y += p0 * v0a.y;
            acc4.z += p0 * v0b.x;
            acc4.w += p0 * v0b.y;
        }
    }

    float inv = 1.f / (z + 1e-16f);
    float4* op = (float4*)(out + (size_t)node * DI + 4 * lane);
    float4 o = *op;
    o.x += acc4.x * inv;
    o.y += acc4.y * inv;
    o.z += acc4.z * inv;
    o.w += acc4.w * inv;
    *op = o;
}

// ---------------- launch: GEMM overlapped with CSR build via side stream ----------------
extern "C" void kernel_launch(void* const* d_in, const int* in_sizes, int n_in,
                              void* d_out, int out_size) {
    const float* x   = (const float*)d_in[0];
    const int*   ei  = (const int*)d_in[1];
    const float* Wq  = (const float*)d_in[2];
    const float* bq  = (const float*)d_in[3];
    const float* Wk  = (const float*)d_in[4];
    const float* bk  = (const float*)d_in[5];
    const float* Wv  = (const float*)d_in[6];
    const float* bv  = (const float*)d_in[7];
    const float* Wsk = (const float*)d_in[8];
    const float* bsk = (const float*)d_in[9];
    float*       out = (float*)d_out;

    int n = in_sizes[0] / DI;
    int e = in_sizes[1] / 2;

    static cudaStream_t sB = 0;
    static cudaEvent_t  evFork = 0, evJoin = 0;
    if (!sB) {
        cudaStreamCreateWithFlags(&sB, cudaStreamNonBlocking);
        cudaEventCreateWithFlags(&evFork, cudaEventDisableTiming);
        cudaEventCreateWithFlags(&evJoin, cudaEventDisableTiming);
    }

    // fork: side stream joins the capture graph
    cudaEventRecord(evFork, 0);
    cudaStreamWaitEvent(sB, evFork, 0);

    // main stream: fused GEMM (~150us)
    int gblocks = (n + 63) / 64;
    gemm_mma<<<gblocks, 256>>>(x, Wq, bq, Wk, bk, Wv, bv, Wsk, bsk, out, n);

    // side stream: CSR build chain (~50us, independent of GEMM)
    sniff_dtype<<<1, 32, 0, sB>>>(ei, e);
    zero_deg<<<256, 256, 0, sB>>>(n);
    hist_edges<<<2048, 256, 0, sB>>>(ei, e, n);
    int nb = (n + 1023) / 1024;
    scan_p1<<<nb, 1024, 0, sB>>>(n);
    scan_p2<<<1, 32, 0, sB>>>(nb);
    scan_p3<<<nb, 1024, 0, sB>>>(n);
    fill_csr<<<2048, 256, 0, sB>>>(ei, e, n);

    // join: attention needs both GEMM outputs and CSR
    cudaEventRecord(evJoin, sB);
    cudaStreamWaitEvent(0, evJoin, 0);

    int blocks = (n * 32 + 255) / 256;
    attn_node<<<blocks, 256>>>(out, n);
}

// round 13
// speedup vs baseline: 2.7511x; 1.0439x over previous
#include <cuda_runtime.h>
#include <cuda_fp16.h>
#include <math.h>

#define NMAX 100000
#define EMAX 1600000
#define DI   128
#define H4   4
#define C32  32
#define XLDH 136   // fp16 leading dim: 136 halves = 272B = 17x16B -> ldmatrix conflict-free

// ---------------- static device scratch ----------------
__device__ float  g_q[NMAX * DI];
__device__ __half g_k[NMAX * DI];
__device__ __half g_v[NMAX * DI];
__device__ int    g_csr_src[EMAX];
__device__ int    g_deg[NMAX];
__device__ int    g_off[NMAX + 1];
__device__ int    g_cur[NMAX];
__device__ int    g_bsum[256];
__device__ int    g_is64;

// ---------------- fp16 mma helpers ----------------
__device__ __forceinline__ void mma_f16(float* c, const unsigned* a, const unsigned* b) {
    asm volatile(
        "mma.sync.aligned.m16n8k16.row.col.f32.f16.f16.f32 "
        "{%0,%1,%2,%3}, {%4,%5,%6,%7}, {%8,%9}, {%0,%1,%2,%3};\n"
        : "+f"(c[0]), "+f"(c[1]), "+f"(c[2]), "+f"(c[3])
        : "r"(a[0]), "r"(a[1]), "r"(a[2]), "r"(a[3]), "r"(b[0]), "r"(b[1]));
}
__device__ __forceinline__ unsigned h2u(__half2 h) {
    return *reinterpret_cast<unsigned*>(&h);
}

// ---------------- fused fp16 tensor-core GEMM: all 4 W in one launch ----------------
// Block: 64 rows x 128 cols, 256 thr (8 warps). X tile staged to smem ONCE as
// fp16, then loop over 4 weight matrices. A-frags via ldmatrix.x4; B frags in
// 32 regs/warp/w. Mainloop per warp per w: 32 ldmatrix + 64 mma, no syncs.
__global__ __launch_bounds__(256) void gemm_mma(
    const float* __restrict__ X,
    const float* __restrict__ W0, const float* __restrict__ b0,
    const float* __restrict__ W1, const float* __restrict__ b1,
    const float* __restrict__ W2, const float* __restrict__ b2,
    const float* __restrict__ W3, const float* __restrict__ b3,
    float* __restrict__ out3, int n)
{
    __shared__ __half xs[64 * XLDH];   // ~17 KB

    int tid  = threadIdx.x;
    int warp = tid >> 5;
    int lane = tid & 31;
    int row0 = blockIdx.x * 64;

    // stage X tile (64 rows x 128 k) as fp16 -- once per block
#pragma unroll
    for (int t = 0; t < 8; t++) {
        int idx = tid + t * 256;
        int r   = idx >> 5;
        int c4  = (idx & 31) * 4;
        float4 xv = make_float4(0.f, 0.f, 0.f, 0.f);
        int gr = row0 + r;
        if (gr < n) xv = *(const float4*)(X + (size_t)gr * DI + c4);
        __half2 h0 = __floats2half2_rn(xv.x, xv.y);
        __half2 h1 = __floats2half2_rn(xv.z, xv.w);
        *(uint2*)&xs[r * XLDH + c4] = make_uint2(h2u(h0), h2u(h1));
    }
    __syncthreads();

    unsigned xs_base = (unsigned)__cvta_generic_to_shared(xs);

    const float* Ws[4] = {W0, W1, W2, W3};
    const float* Bs[4] = {b0, b1, b2, b3};

    int n0 = warp * 16;

    // ldmatrix source row/col for this lane (constant across chunks via offset)
    int lrow = lane & 15;
    int lcol = (lane >> 4) * 8;

#pragma unroll 1
    for (int w = 0; w < 4; w++) {
        const float* __restrict__ W = Ws[w];
        const float* __restrict__ B = Bs[w];
        float*  outf = 0;
        __half* outh = 0;
        int ishalf = (w == 1 || w == 2);
        if (w == 0)      outf = g_q;
        else if (w == 1) outh = g_k;
        else if (w == 2) outh = g_v;
        else             outf = out3;

        // preload B fragments: 8 ksteps x 2 ntiles x 2 regs (fp16 pairs)
        // reg0 = {W[kb][col], W[kb+1][col]}, reg1 = {W[kb+8][col], W[kb+9][col]}
        unsigned bf[8][2][2];
        {
            int col  = n0 + (lane >> 2);        // +nt*8 below
            int koff = (lane & 3) * 2;
#pragma unroll
            for (int kt = 0; kt < 8; kt++) {
                int kb = kt * 16 + koff;
#pragma unroll
                for (int nt = 0; nt < 2; nt++) {
                    int c = col + nt * 8;
                    bf[kt][nt][0] = h2u(__floats2half2_rn(W[(size_t)kb * DI + c],
                                                          W[(size_t)(kb + 1) * DI + c]));
                    bf[kt][nt][1] = h2u(__floats2half2_rn(W[(size_t)(kb + 8) * DI + c],
                                                          W[(size_t)(kb + 9) * DI + c]));
                }
            }
        }

        float bias[2][2];
#pragma unroll
        for (int nt = 0; nt < 2; nt++) {
            int c = n0 + nt * 8 + 2 * (lane & 3);
            bias[nt][0] = B[c];
            bias[nt][1] = B[c + 1];
        }

#pragma unroll
        for (int chunk = 0; chunk < 4; chunk++) {
            float acc[2][4];
#pragma unroll
            for (int nt = 0; nt < 2; nt++)
#pragma unroll
                for (int i = 0; i < 4; i++) acc[nt][i] = 0.f;

            unsigned abase = xs_base +
                ((chunk * 16 + lrow) * XLDH + lcol) * 2;   // bytes
#pragma unroll
            for (int kt = 0; kt < 8; kt++) {
                unsigned a0, a1, a2, a3;
                asm volatile(
                    "ldmatrix.sync.aligned.m8n8.x4.shared.b16 {%0,%1,%2,%3}, [%4];"
                    : "=r"(a0), "=r"(a1), "=r"(a2), "=r"(a3)
                    : "r"(abase + kt * 32));
                unsigned af[4] = {a0, a1, a2, a3};
                mma_f16(acc[0], af, bf[kt][0]);
                mma_f16(acc[1], af, bf[kt][1]);
            }

            int r0 = row0 + chunk * 16 + (lane >> 2);
#pragma unroll
            for (int nt = 0; nt < 2; nt++) {
                int c = n0 + nt * 8 + 2 * (lane & 3);
                float o00 = acc[nt][0] + bias[nt][0];
                float o01 = acc[nt][1] + bias[nt][1];
                float o10 = acc[nt][2] + bias[nt][0];
                float o11 = acc[nt][3] + bias[nt][1];
                if (ishalf) {
                    if (r0 < n)
                        *(__half2*)(outh + (size_t)r0 * DI + c) = __floats2half2_rn(o00, o01);
                    if (r0 + 8 < n)
                        *(__half2*)(outh + (size_t)(r0 + 8) * DI + c) = __floats2half2_rn(o10, o11);
                } else {
                    if (r0 < n)
                        *(float2*)(outf + (size_t)r0 * DI + c) = make_float2(o00, o01);
                    if (r0 + 8 < n)
                        *(float2*)(outf + (size_t)(r0 + 8) * DI + c) = make_float2(o10, o11);
                }
            }
        }
    }
}

// ---------------- edge dtype sniff + CSR build ----------------
__global__ void sniff_dtype(const int* __restrict__ ei32, int e) {
    if (threadIdx.x == 0 && blockIdx.x == 0) {
        int allzero = 1;
        int stride = (2 * e) / 256;
        if (stride < 2) stride = 2;
        for (int s = 0; s < 256; s++) {
            long long idx = (long long)s * stride | 1;
            if (idx < 4LL * e) {
                if (ei32[idx] != 0) { allzero = 0; break; }
            }
        }
        g_is64 = allzero;
    }
}

__global__ void zero_deg(int n) {
    for (int i = blockIdx.x * blockDim.x + threadIdx.x; i < n; i += gridDim.x * blockDim.x)
        g_deg[i] = 0;
}

__device__ __forceinline__ int load_edge(const int* __restrict__ ei32,
                                         int is64, long long pos) {
    return is64 ? ei32[2 * pos] : ei32[pos];
}

__global__ void hist_edges(const int* __restrict__ ei32, int e, int n) {
    int is64 = g_is64;
    for (int i = blockIdx.x * blockDim.x + threadIdx.x; i < e; i += gridDim.x * blockDim.x) {
        int d = load_edge(ei32, is64, (long long)e + i);
        d = min(max(d, 0), n - 1);
        atomicAdd(&g_deg[d], 1);
    }
}

// ---------------- 3-phase parallel exclusive scan ----------------
__global__ __launch_bounds__(1024) void scan_p1(int n) {
    __shared__ int wsum[32];
    int tid = threadIdx.x, lane = tid & 31, wid = tid >> 5;
    int i = blockIdx.x * 1024 + tid;
    int v = (i < n) ? g_deg[i] : 0;
    int inc = v;
#pragma unroll
    for (int o = 1; o < 32; o <<= 1) {
        int t = __shfl_up_sync(0xffffffffu, inc, o);
        if (lane >= o) inc += t;
    }
    if (lane == 31) wsum[wid] = inc;
    __syncthreads();
    if (wid == 0) {
        int wv = wsum[lane];
        int wi = wv;
#pragma unroll
        for (int o = 1; o < 32; o <<= 1) {
            int t = __shfl_up_sync(0xffffffffu, wi, o);
            if (lane >= o) wi += t;
        }
        wsum[lane] = wi - wv;
        if (lane == 31) g_bsum[blockIdx.x] = wi;
    }
    __syncthreads();
    if (i < n) g_off[i] = wsum[wid] + inc - v;
}

__global__ void scan_p2(int nb) {
    int lane = threadIdx.x;
    int acc = 0;
    for (int base = 0; base < nb; base += 32) {
        int v = (base + lane < nb) ? g_bsum[base + lane] : 0;
        int inc = v;
#pragma unroll
        for (int o = 1; o < 32; o <<= 1) {
            int t = __shfl_up_sync(0xffffffffu, inc, o);
            if (lane >= o) inc += t;
        }
        if (base + lane < nb) g_bsum[base + lane] = acc + inc - v;
        acc += __shfl_sync(0xffffffffu, inc, 31);
    }
    if (lane == 0) g_bsum[255] = acc;
}

__global__ __launch_bounds__(1024) void scan_p3(int n) {
    int i = blockIdx.x * 1024 + threadIdx.x;
    if (i < n) {
        int off = g_off[i] + g_bsum[blockIdx.x];
        g_off[i] = off;
        g_cur[i] = off;
    }
    if (i == 0) g_off[n] = g_bsum[255];
}

__global__ void fill_csr(const int* __restrict__ ei32, int e, int n) {
    int is64 = g_is64;
    for (int i = blockIdx.x * blockDim.x + threadIdx.x; i < e; i += gridDim.x * blockDim.x) {
        int s = load_edge(ei32, is64, i);
        int d = load_edge(ei32, is64, (long long)e + i);
        s = min(max(s, 0), n - 1);
        d = min(max(d, 0), n - 1);
        int pos = atomicAdd(&g_cur[d], 1);
        g_csr_src[pos] = s;
    }
}

// ---------------- attention: one warp per node, all 4 heads, fp16 k/v, MLP=8 ----------------
__device__ __forceinline__ float red8(float d) {
    d += __shfl_xor_sync(0xffffffffu, d, 4);
    d += __shfl_xor_sync(0xffffffffu, d, 2);
    d += __shfl_xor_sync(0xffffffffu, d, 1);
    return d;
}

__device__ __forceinline__ float dot_h(const uint2 kp, float4 q4) {
    float2 a = __half22float2(*(const __half2*)&kp.x);
    float2 b = __half22float2(*(const __half2*)&kp.y);
    return q4.x * a.x + q4.y * a.y + q4.z * b.x + q4.w * b.y;
}

__global__ __launch_bounds__(256) void attn_node(float* __restrict__ out, int n) {
    int warp = (blockIdx.x * blockDim.x + threadIdx.x) >> 5;
    int lane = threadIdx.x & 31;
    if (warp >= n) return;
    int node = warp;

    int base = g_off[node];
    int end  = g_off[node + 1];

    const __half* __restrict__ kh = g_k;
    const __half* __restrict__ vh = g_v;

    float4 q4 = *(const float4*)(g_q + (size_t)node * DI + 4 * lane);
    const float scale = 0.17677669529663688f;  // 1/sqrt(32)

    float  z    = 0.f;
    float4 acc4 = make_float4(0.f, 0.f, 0.f, 0.f);

    for (int i0 = base; i0 < end; i0 += 32) {
        int nchunk = min(32, end - i0);
        int sidx = (i0 + lane < end) ? g_csr_src[i0 + lane] : 0;

        int j = 0;
        for (; j + 3 < nchunk; j += 4) {
            int s0 = __shfl_sync(0xffffffffu, sidx, j);
            int s1 = __shfl_sync(0xffffffffu, sidx, j + 1);
            int s2 = __shfl_sync(0xffffffffu, sidx, j + 2);
            int s3 = __shfl_sync(0xffffffffu, sidx, j + 3);
            uint2 kp0 = *(const uint2*)(kh + (size_t)s0 * DI + 4 * lane);
            uint2 kp1 = *(const uint2*)(kh + (size_t)s1 * DI + 4 * lane);
            uint2 kp2 = *(const uint2*)(kh + (size_t)s2 * DI + 4 * lane);
            uint2 kp3 = *(const uint2*)(kh + (size_t)s3 * DI + 4 * lane);
            uint2 vp0 = *(const uint2*)(vh + (size_t)s0 * DI + 4 * lane);
            uint2 vp1 = *(const uint2*)(vh + (size_t)s1 * DI + 4 * lane);
            uint2 vp2 = *(const uint2*)(vh + (size_t)s2 * DI + 4 * lane);
            uint2 vp3 = *(const uint2*)(vh + (size_t)s3 * DI + 4 * lane);

            float d0 = red8(dot_h(kp0, q4));
            float d1 = red8(dot_h(kp1, q4));
            float d2 = red8(dot_h(kp2, q4));
            float d3 = red8(dot_h(kp3, q4));
            float p0 = __expf(d0 * scale);
            float p1 = __expf(d1 * scale);
            float p2 = __expf(d2 * scale);
            float p3 = __expf(d3 * scale);
            z += (p0 + p1) + (p2 + p3);

            float2 v0a = __half22float2(*(const __half2*)&vp0.x);
            float2 v0b = __half22float2(*(const __half2*)&vp0.y);
            float2 v1a = __half22float2(*(const __half2*)&vp1.x);
            float2 v1b = __half22float2(*(const __half2*)&vp1.y);
            float2 v2a = __half22float2(*(const __half2*)&vp2.x);
            float2 v2b = __half22float2(*(const __half2*)&vp2.y);
            float2 v3a = __half22float2(*(const __half2*)&vp3.x);
            float2 v3b = __half22float2(*(const __half2*)&vp3.y);
            acc4.x += p0 * v0a.x + p1 * v1a.x + p2 * v2a.x + p3 * v3a.x;
            acc4.y += p0 * v0a.y + p1 * v1a.y + p2 * v2a.y + p3 * v3a.y;
            acc4.z += p0 * v0b.x + p1 * v1b.x + p2 * v2b.x + p3 * v3b.x;
            acc4.w += p0 * v0b.y + p1 * v1b.y + p2 * v2b.y + p3 * v3b.y;
        }
        for (; j < nchunk; j++) {
            int s0 = __shfl_sync(0xffffffffu, sidx, j);
            uint2 kp0 = *(const uint2*)(kh + (size_t)s0 * DI + 4 * lane);
            uint2 vp0 = *(const uint2*)(vh + (size_t)s0 * DI + 4 * lane);
            float d0 = red8(dot_h(kp0, q4));
            float p0 = __expf(d0 * scale);
            z += p0;
            float2 v0a = __half22float2(*(const __half2*)&vp0.x);
            float2 v0b = __half22float2(*(const __half2*)&vp0.y);
            acc4.x += p0 * v0a.x;
            acc4.y += p0 * v0a.y;
            acc4.z += p0 * v0b.x;
            acc4.w += p0 * v0b.y;
        }
    }

    float inv = 1.f / (z + 1e-16f);
    float4* op = (float4*)(out + (size_t)node * DI + 4 * lane);
    float4 o = *op;
    o.x += acc4.x * inv;
    o.y += acc4.y * inv;
    o.z += acc4.z * inv;
    o.w += acc4.w * inv;
    *op = o;
}

// ---------------- launch: GEMM overlapped with CSR build via side stream ----------------
extern "C" void kernel_launch(void* const* d_in, const int* in_sizes, int n_in,
                              void* d_out, int out_size) {
    const float* x   = (const float*)d_in[0];
    const int*   ei  = (const int*)d_in[1];
    const float* Wq  = (const float*)d_in[2];
    const float* bq  = (const float*)d_in[3];
    const float* Wk  = (const float*)d_in[4];
    const float* bk  = (const float*)d_in[5];
    const float* Wv  = (const float*)d_in[6];
    const float* bv  = (const float*)d_in[7];
    const float* Wsk = (const float*)d_in[8];
    const float* bsk = (const float*)d_in[9];
    float*       out = (float*)d_out;

    int n = in_sizes[0] / DI;
    int e = in_sizes[1] / 2;

    static cudaStream_t sB = 0;
    static cudaEvent_t  evFork = 0, evJoin = 0;
    if (!sB) {
        cudaStreamCreateWithFlags(&sB, cudaStreamNonBlocking);
        cudaEventCreateWithFlags(&evFork, cudaEventDisableTiming);
        cudaEventCreateWithFlags(&evJoin, cudaEventDisableTiming);
    }

    // fork: side stream joins the capture graph
    cudaEventRecord(evFork, 0);
    cudaStreamWaitEvent(sB, evFork, 0);

    // main stream: fused GEMM
    int gblocks = (n + 63) / 64;
    gemm_mma<<<gblocks, 256>>>(x, Wq, bq, Wk, bk, Wv, bv, Wsk, bsk, out, n);

    // side stream: CSR build chain (independent of GEMM)
    sniff_dtype<<<1, 32, 0, sB>>>(ei, e);
    zero_deg<<<256, 256, 0, sB>>>(n);
    hist_edges<<<2048, 256, 0, sB>>>(ei, e, n);
    int nb = (n + 1023) / 1024;
    scan_p1<<<nb, 1024, 0, sB>>>(n);
    scan_p2<<<1, 32, 0, sB>>>(nb);
    scan_p3<<<nb, 1024, 0, sB>>>(n);
    fill_csr<<<2048, 256, 0, sB>>>(ei, e, n);

    // join: attention needs both GEMM outputs and CSR
    cudaEventRecord(evJoin, sB);
    cudaStreamWaitEvent(0, evJoin, 0);

    int blocks = (n * 32 + 255) / 256;
    attn_node<<<blocks, 256>>>(out, n);
}

// round 14
// speedup vs baseline: 3.2004x; 1.1633x over previous
#include <cuda_runtime.h>
#include <cuda_fp16.h>
#include <math.h>

#define NMAX 100000
#define EMAX 1600000
#define DI   128
#define H4   4
#define C32  32
#define XLDH 136   // fp16 leading dim: 272B = 17x16B -> ldmatrix conflict-free

// ---------------- static device scratch ----------------
__device__ float  g_q[NMAX * DI];
__device__ __half g_k[NMAX * DI];
__device__ __half g_v[NMAX * DI];
__device__ __half g_wt[4 * DI * DI];   // transposed fp16 weights: [w][col][k]
__device__ int    g_csr_src[EMAX];
__device__ int    g_deg[NMAX];
__device__ int    g_off[NMAX + 1];
__device__ int    g_cur[NMAX];
__device__ int    g_bsum[256];
__device__ int    g_is64;

// ---------------- fp16 mma helpers ----------------
__device__ __forceinline__ void mma_f16(float* c, const unsigned* a, const unsigned* b) {
    asm volatile(
        "mma.sync.aligned.m16n8k16.row.col.f32.f16.f16.f32 "
        "{%0,%1,%2,%3}, {%4,%5,%6,%7}, {%8,%9}, {%0,%1,%2,%3};\n"
        : "+f"(c[0]), "+f"(c[1]), "+f"(c[2]), "+f"(c[3])
        : "r"(a[0]), "r"(a[1]), "r"(a[2]), "r"(a[3]), "r"(b[0]), "r"(b[1]));
}
__device__ __forceinline__ unsigned h2u(__half2 h) {
    return *reinterpret_cast<unsigned*>(&h);
}

// ---------------- weight pre-transpose: W[k][col] fp32 -> Wt[col][k] fp16 ----------------
__global__ void prep_w(const float* __restrict__ W0, const float* __restrict__ W1,
                       const float* __restrict__ W2, const float* __restrict__ W3) {
    const float* Ws[4] = {W0, W1, W2, W3};
    int w   = blockIdx.y;
    int idx = blockIdx.x * 256 + threadIdx.x;   // 0..16383
    int col = idx >> 7;
    int k   = idx & 127;
    g_wt[(size_t)w * DI * DI + col * DI + k] = __float2half_rn(Ws[w][(size_t)k * DI + col]);
}

// ---------------- fused fp16 tensor-core GEMM: 128-row tiles, all 4 W ----------------
// Block: 128 rows x 128 cols, 256 thr (8 warps). X tile staged once as fp16.
// B frags: one aligned LDG.32 each from pre-transposed fp16 Wt (L1-hot).
__global__ __launch_bounds__(256) void gemm_mma(
    const float* __restrict__ X,
    const float* __restrict__ b0, const float* __restrict__ b1,
    const float* __restrict__ b2, const float* __restrict__ b3,
    float* __restrict__ out3, int n)
{
    __shared__ __half xs[128 * XLDH];   // ~34.8 KB

    int tid  = threadIdx.x;
    int warp = tid >> 5;
    int lane = tid & 31;
    int row0 = blockIdx.x * 128;

    // stage X tile (128 rows x 128 k) as fp16 -- once per block
#pragma unroll
    for (int t = 0; t < 16; t++) {
        int idx = tid + t * 256;          // 4096 uint2 slots
        int r   = idx >> 5;
        int c4  = (idx & 31) * 4;
        float4 xv = make_float4(0.f, 0.f, 0.f, 0.f);
        int gr = row0 + r;
        if (gr < n) xv = *(const float4*)(X + (size_t)gr * DI + c4);
        __half2 h0 = __floats2half2_rn(xv.x, xv.y);
        __half2 h1 = __floats2half2_rn(xv.z, xv.w);
        *(uint2*)&xs[r * XLDH + c4] = make_uint2(h2u(h0), h2u(h1));
    }
    __syncthreads();

    unsigned xs_base = (unsigned)__cvta_generic_to_shared(xs);

    const float* Bs[4] = {b0, b1, b2, b3};

    int n0   = warp * 16;
    int lrow = lane & 15;
    int lcol = (lane >> 4) * 8;

#pragma unroll 1
    for (int w = 0; w < 4; w++) {
        const float* __restrict__ B = Bs[w];
        const __half* __restrict__ Wt = g_wt + (size_t)w * DI * DI;
        float*  outf = 0;
        __half* outh = 0;
        int ishalf = (w == 1 || w == 2);
        if (w == 0)      outf = g_q;
        else if (w == 1) outh = g_k;
        else if (w == 2) outh = g_v;
        else             outf = out3;

        // preload B fragments: 8 ksteps x 2 ntiles x 2 regs, one LDG.32 each
        unsigned bf[8][2][2];
        {
            int colb = n0 + (lane >> 2);
            int koff = (lane & 3) * 2;
#pragma unroll
            for (int kt = 0; kt < 8; kt++) {
#pragma unroll
                for (int nt = 0; nt < 2; nt++) {
                    const __half* wp = Wt + (size_t)(colb + nt * 8) * DI + kt * 16 + koff;
                    bf[kt][nt][0] = *(const unsigned*)(wp);
                    bf[kt][nt][1] = *(const unsigned*)(wp + 8);
                }
            }
        }

        float bias[2][2];
#pragma unroll
        for (int nt = 0; nt < 2; nt++) {
            int c = n0 + nt * 8 + 2 * (lane & 3);
            bias[nt][0] = B[c];
            bias[nt][1] = B[c + 1];
        }

#pragma unroll
        for (int chunk = 0; chunk < 8; chunk++) {
            float acc[2][4];
#pragma unroll
            for (int nt = 0; nt < 2; nt++)
#pragma unroll
                for (int i = 0; i < 4; i++) acc[nt][i] = 0.f;

            unsigned abase = xs_base +
                ((chunk * 16 + lrow) * XLDH + lcol) * 2;   // bytes
#pragma unroll
            for (int kt = 0; kt < 8; kt++) {
                unsigned a0, a1, a2, a3;
                asm volatile(
                    "ldmatrix.sync.aligned.m8n8.x4.shared.b16 {%0,%1,%2,%3}, [%4];"
                    : "=r"(a0), "=r"(a1), "=r"(a2), "=r"(a3)
                    : "r"(abase + kt * 32));
                unsigned af[4] = {a0, a1, a2, a3};
                mma_f16(acc[0], af, bf[kt][0]);
                mma_f16(acc[1], af, bf[kt][1]);
            }

            int r0 = row0 + chunk * 16 + (lane >> 2);
#pragma unroll
            for (int nt = 0; nt < 2; nt++) {
                int c = n0 + nt * 8 + 2 * (lane & 3);
                float o00 = acc[nt][0] + bias[nt][0];
                float o01 = acc[nt][1] + bias[nt][1];
                float o10 = acc[nt][2] + bias[nt][0];
                float o11 = acc[nt][3] + bias[nt][1];
                if (ishalf) {
                    if (r0 < n)
                        *(__half2*)(outh + (size_t)r0 * DI + c) = __floats2half2_rn(o00, o01);
                    if (r0 + 8 < n)
                        *(__half2*)(outh + (size_t)(r0 + 8) * DI + c) = __floats2half2_rn(o10, o11);
                } else {
                    if (r0 < n)
                        *(float2*)(outf + (size_t)r0 * DI + c) = make_float2(o00, o01);
                    if (r0 + 8 < n)
                        *(float2*)(outf + (size_t)(r0 + 8) * DI + c) = make_float2(o10, o11);
                }
            }
        }
    }
}

// ---------------- edge dtype sniff + CSR build ----------------
__global__ void sniff_dtype(const int* __restrict__ ei32, int e) {
    if (threadIdx.x == 0 && blockIdx.x == 0) {
        int allzero = 1;
        int stride = (2 * e) / 256;
        if (stride < 2) stride = 2;
        for (int s = 0; s < 256; s++) {
            long long idx = (long long)s * stride | 1;
            if (idx < 4LL * e) {
                if (ei32[idx] != 0) { allzero = 0; break; }
            }
        }
        g_is64 = allzero;
    }
}

__global__ void zero_deg(int n) {
    for (int i = blockIdx.x * blockDim.x + threadIdx.x; i < n; i += gridDim.x * blockDim.x)
        g_deg[i] = 0;
}

__device__ __forceinline__ int load_edge(const int* __restrict__ ei32,
                                         int is64, long long pos) {
    return is64 ? ei32[2 * pos] : ei32[pos];
}

__global__ void hist_edges(const int* __restrict__ ei32, int e, int n) {
    int is64 = g_is64;
    for (int i = blockIdx.x * blockDim.x + threadIdx.x; i < e; i += gridDim.x * blockDim.x) {
        int d = load_edge(ei32, is64, (long long)e + i);
        d = min(max(d, 0), n - 1);
        atomicAdd(&g_deg[d], 1);
    }
}

// ---------------- 3-phase parallel exclusive scan ----------------
__global__ __launch_bounds__(1024) void scan_p1(int n) {
    __shared__ int wsum[32];
    int tid = threadIdx.x, lane = tid & 31, wid = tid >> 5;
    int i = blockIdx.x * 1024 + tid;
    int v = (i < n) ? g_deg[i] : 0;
    int inc = v;
#pragma unroll
    for (int o = 1; o < 32; o <<= 1) {
        int t = __shfl_up_sync(0xffffffffu, inc, o);
        if (lane >= o) inc += t;
    }
    if (lane == 31) wsum[wid] = inc;
    __syncthreads();
    if (wid == 0) {
        int wv = wsum[lane];
        int wi = wv;
#pragma unroll
        for (int o = 1; o < 32; o <<= 1) {
            int t = __shfl_up_sync(0xffffffffu, wi, o);
            if (lane >= o) wi += t;
        }
        wsum[lane] = wi - wv;
        if (lane == 31) g_bsum[blockIdx.x] = wi;
    }
    __syncthreads();
    if (i < n) g_off[i] = wsum[wid] + inc - v;
}

__global__ void scan_p2(int nb) {
    int lane = threadIdx.x;
    int acc = 0;
    for (int base = 0; base < nb; base += 32) {
        int v = (base + lane < nb) ? g_bsum[base + lane] : 0;
        int inc = v;
#pragma unroll
        for (int o = 1; o < 32; o <<= 1) {
            int t = __shfl_up_sync(0xffffffffu, inc, o);
            if (lane >= o) inc += t;
        }
        if (base + lane < nb) g_bsum[base + lane] = acc + inc - v;
        acc += __shfl_sync(0xffffffffu, inc, 31);
    }
    if (lane == 0) g_bsum[255] = acc;
}

__global__ __launch_bounds__(1024) void scan_p3(int n) {
    int i = blockIdx.x * 1024 + threadIdx.x;
    if (i < n) {
        int off = g_off[i] + g_bsum[blockIdx.x];
        g_off[i] = off;
        g_cur[i] = off;
    }
    if (i == 0) g_off[n] = g_bsum[255];
}

__global__ void fill_csr(const int* __restrict__ ei32, int e, int n) {
    int is64 = g_is64;
    for (int i = blockIdx.x * blockDim.x + threadIdx.x; i < e; i += gridDim.x * blockDim.x) {
        int s = load_edge(ei32, is64, i);
        int d = load_edge(ei32, is64, (long long)e + i);
        s = min(max(s, 0), n - 1);
        d = min(max(d, 0), n - 1);
        int pos = atomicAdd(&g_cur[d], 1);
        g_csr_src[pos] = s;
    }
}

// ---------------- attention: one warp per node, all 4 heads, fp16 k/v, MLP=8 ----------------
__device__ __forceinline__ float red8(float d) {
    d += __shfl_xor_sync(0xffffffffu, d, 4);
    d += __shfl_xor_sync(0xffffffffu, d, 2);
    d += __shfl_xor_sync(0xffffffffu, d, 1);
    return d;
}

__device__ __forceinline__ float dot_h(const uint2 kp, float4 q4) {
    float2 a = __half22float2(*(const __half2*)&kp.x);
    float2 b = __half22float2(*(const __half2*)&kp.y);
    return q4.x * a.x + q4.y * a.y + q4.z * b.x + q4.w * b.y;
}

__global__ __launch_bounds__(256) void attn_node(float* __restrict__ out, int n) {
    int warp = (blockIdx.x * blockDim.x + threadIdx.x) >> 5;
    int lane = threadIdx.x & 31;
    if (warp >= n) return;
    int node = warp;

    int base = g_off[node];
    int end  = g_off[node + 1];

    const __half* __restrict__ kh = g_k;
    const __half* __restrict__ vh = g_v;

    float4 q4 = *(const float4*)(g_q + (size_t)node * DI + 4 * lane);
    const float scale = 0.17677669529663688f;  // 1/sqrt(32)

    float  z    = 0.f;
    float4 acc4 = make_float4(0.f, 0.f, 0.f, 0.f);

    for (int i0 = base; i0 < end; i0 += 32) {
        int nchunk = min(32, end - i0);
        int sidx = (i0 + lane < end) ? g_csr_src[i0 + lane] : 0;

        int j = 0;
        for (; j + 3 < nchunk; j += 4) {
            int s0 = __shfl_sync(0xffffffffu, sidx, j);
            int s1 = __shfl_sync(0xffffffffu, sidx, j + 1);
            int s2 = __shfl_sync(0xffffffffu, sidx, j + 2);
            int s3 = __shfl_sync(0xffffffffu, sidx, j + 3);
            uint2 kp0 = *(const uint2*)(kh + (size_t)s0 * DI + 4 * lane);
            uint2 kp1 = *(const uint2*)(kh + (size_t)s1 * DI + 4 * lane);
            uint2 kp2 = *(const uint2*)(kh + (size_t)s2 * DI + 4 * lane);
            uint2 kp3 = *(const uint2*)(kh + (size_t)s3 * DI + 4 * lane);
            uint2 vp0 = *(const uint2*)(vh + (size_t)s0 * DI + 4 * lane);
            uint2 vp1 = *(const uint2*)(vh + (size_t)s1 * DI + 4 * lane);
            uint2 vp2 = *(const uint2*)(vh + (size_t)s2 * DI + 4 * lane);
            uint2 vp3 = *(const uint2*)(vh + (size_t)s3 * DI + 4 * lane);

            float d0 = red8(dot_h(kp0, q4));
            float d1 = red8(dot_h(kp1, q4));
            float d2 = red8(dot_h(kp2, q4));
            float d3 = red8(dot_h(kp3, q4));
            float p0 = __expf(d0 * scale);
            float p1 = __expf(d1 * scale);
            float p2 = __expf(d2 * scale);
            float p3 = __expf(d3 * scale);
            z += (p0 + p1) + (p2 + p3);

            float2 v0a = __half22float2(*(const __half2*)&vp0.x);
            float2 v0b = __half22float2(*(const __half2*)&vp0.y);
            float2 v1a = __half22float2(*(const __half2*)&vp1.x);
            float2 v1b = __half22float2(*(const __half2*)&vp1.y);
            float2 v2a = __half22float2(*(const __half2*)&vp2.x);
            float2 v2b = __half22float2(*(const __half2*)&vp2.y);
            float2 v3a = __half22float2(*(const __half2*)&vp3.x);
            float2 v3b = __half22float2(*(const __half2*)&vp3.y);
            acc4.x += p0 * v0a.x + p1 * v1a.x + p2 * v2a.x + p3 * v3a.x;
            acc4.y += p0 * v0a.y + p1 * v1a.y + p2 * v2a.y + p3 * v3a.y;
            acc4.z += p0 * v0b.x + p1 * v1b.x + p2 * v2b.x + p3 * v3b.x;
            acc4.w += p0 * v0b.y + p1 * v1b.y + p2 * v2b.y + p3 * v3b.y;
        }
        for (; j < nchunk; j++) {
            int s0 = __shfl_sync(0xffffffffu, sidx, j);
            uint2 kp0 = *(const uint2*)(kh + (size_t)s0 * DI + 4 * lane);
            uint2 vp0 = *(const uint2*)(vh + (size_t)s0 * DI + 4 * lane);
            float d0 = red8(dot_h(kp0, q4));
            float p0 = __expf(d0 * scale);
            z += p0;
            float2 v0a = __half22float2(*(const __half2*)&vp0.x);
            float2 v0b = __half22float2(*(const __half2*)&vp0.y);
            acc4.x += p0 * v0a.x;
            acc4.y += p0 * v0a.y;
            acc4.z += p0 * v0b.x;
            acc4.w += p0 * v0b.y;
        }
    }

    float inv = 1.f / (z + 1e-16f);
    float4* op = (float4*)(out + (size_t)node * DI + 4 * lane);
    float4 o = *op;
    o.x += acc4.x * inv;
    o.y += acc4.y * inv;
    o.z += acc4.z * inv;
    o.w += acc4.w * inv;
    *op = o;
}

// ---------------- launch: GEMM overlapped with CSR build via side stream ----------------
extern "C" void kernel_launch(void* const* d_in, const int* in_sizes, int n_in,
                              void* d_out, int out_size) {
    const float* x   = (const float*)d_in[0];
    const int*   ei  = (const int*)d_in[1];
    const float* Wq  = (const float*)d_in[2];
    const float* bq  = (const float*)d_in[3];
    const float* Wk  = (const float*)d_in[4];
    const float* bk  = (const float*)d_in[5];
    const float* Wv  = (const float*)d_in[6];
    const float* bv  = (const float*)d_in[7];
    const float* Wsk = (const float*)d_in[8];
    const float* bsk = (const float*)d_in[9];
    float*       out = (float*)d_out;

    int n = in_sizes[0] / DI;
    int e = in_sizes[1] / 2;

    static cudaStream_t sB = 0;
    static cudaEvent_t  evFork = 0, evJoin = 0;
    if (!sB) {
        cudaStreamCreateWithFlags(&sB, cudaStreamNonBlocking);
        cudaEventCreateWithFlags(&evFork, cudaEventDisableTiming);
        cudaEventCreateWithFlags(&evJoin, cudaEventDisableTiming);
    }

    // fork: side stream joins the capture graph
    cudaEventRecord(evFork, 0);
    cudaStreamWaitEvent(sB, evFork, 0);

    // main stream: weight transpose + fused GEMM
    prep_w<<<dim3(64, 4), 256>>>(Wq, Wk, Wv, Wsk);
    int gblocks = (n + 127) / 128;
    gemm_mma<<<gblocks, 256>>>(x, bq, bk, bv, bsk, out, n);

    // side stream: CSR build chain (independent of GEMM)
    sniff_dtype<<<1, 32, 0, sB>>>(ei, e);
    zero_deg<<<256, 256, 0, sB>>>(n);
    hist_edges<<<2048, 256, 0, sB>>>(ei, e, n);
    int nb = (n + 1023) / 1024;
    scan_p1<<<nb, 1024, 0, sB>>>(n);
    scan_p2<<<1, 32, 0, sB>>>(nb);
    scan_p3<<<nb, 1024, 0, sB>>>(n);
    fill_csr<<<2048, 256, 0, sB>>>(ei, e, n);

    // join: attention needs both GEMM outputs and CSR
    cudaEventRecord(evJoin, sB);
    cudaStreamWaitEvent(0, evJoin, 0);

    int blocks = (n * 32 + 255) / 256;
    attn_node<<<blocks, 256>>>(out, n);
}

// round 16
// speedup vs baseline: 3.4751x; 1.0858x over previous
#include <cuda_runtime.h>
#include <cuda_fp16.h>
#include <math.h>

#define NMAX 100000
#define EMAX 1600000
#define DI   128
#define H4   4
#define C32  32
#define XLDH 136   // fp16 leading dim: 272B = 17x16B -> ldmatrix conflict-free

// ---------------- static device scratch ----------------
__device__ float  g_q[NMAX * DI];
__device__ __half g_k[NMAX * DI];
__device__ __half g_v[NMAX * DI];
// B fragments in register order: [w][warp][kt(8)][lane(32)][4 words]
// word q = nt*2+reg: bf[kt][nt][reg] packed as __half2
__device__ uint4  g_wf[4 * 8 * 8 * 32];
__device__ int    g_csr_src[EMAX];
__device__ int    g_deg[NMAX];
__device__ int    g_off[NMAX + 1];
__device__ int    g_cur[NMAX];
__device__ int    g_bsum[256];
__device__ int    g_is64;

// ---------------- fp16 mma helpers ----------------
__device__ __forceinline__ void mma_f16(float* c, const unsigned* a, const unsigned* b) {
    asm volatile(
        "mma.sync.aligned.m16n8k16.row.col.f32.f16.f16.f32 "
        "{%0,%1,%2,%3}, {%4,%5,%6,%7}, {%8,%9}, {%0,%1,%2,%3};\n"
        : "+f"(c[0]), "+f"(c[1]), "+f"(c[2]), "+f"(c[3])
        : "r"(a[0]), "r"(a[1]), "r"(a[2]), "r"(a[3]), "r"(b[0]), "r"(b[1]));
}
__device__ __forceinline__ unsigned h2u(__half2 h) {
    return *reinterpret_cast<unsigned*>(&h);
}

// ---------------- weight prep: W fp32 -> fragment-ordered fp16 words ----------------
// Word (w, warp, kt, lane, q): nt = q>>1, reg = q&1,
//   col = warp*16 + nt*8 + (lane>>2), k = kt*16 + (lane&3)*2 + reg*8
//   value = half2{ W[k][col], W[k+1][col] }
__global__ void prep_w(const float* __restrict__ W0, const float* __restrict__ W1,
                       const float* __restrict__ W2, const float* __restrict__ W3) {
    const float* Ws[4] = {W0, W1, W2, W3};
    int idx = blockIdx.x * 256 + threadIdx.x;   // 0..32767 words
    int w    = idx >> 13;
    int rem  = idx & 8191;
    int warp = rem >> 10;
    int kt   = (rem >> 7) & 7;
    int lane = (rem >> 2) & 31;
    int q    = rem & 3;
    int nt   = q >> 1;
    int reg  = q & 1;
    int col  = warp * 16 + nt * 8 + (lane >> 2);
    int k    = kt * 16 + (lane & 3) * 2 + reg * 8;
    const float* W = Ws[w];
    __half2 val = __floats2half2_rn(W[(size_t)k * DI + col], W[(size_t)(k + 1) * DI + col]);
    ((unsigned*)g_wf)[idx] = h2u(val);
}

// ---------------- fused fp16 tensor-core GEMM: 128-row tiles, all 4 W ----------------
// Block: 128 rows x 128 cols, 256 thr (8 warps). X tile staged once as fp16.
// B frags: 8 coalesced LDG.128 per thread per w from fragment-ordered g_wf.
__global__ __launch_bounds__(256) void gemm_mma(
    const float* __restrict__ X,
    const float* __restrict__ b0, const float* __restrict__ b1,
    const float* __restrict__ b2, const float* __restrict__ b3,
    float* __restrict__ out3, int n)
{
    __shared__ __half xs[128 * XLDH];   // ~34.8 KB

    int tid  = threadIdx.x;
    int warp = tid >> 5;
    int lane = tid & 31;
    int row0 = blockIdx.x * 128;

    // stage X tile (128 rows x 128 k) as fp16 -- once per block
#pragma unroll
    for (int t = 0; t < 16; t++) {
        int idx = tid + t * 256;
        int r   = idx >> 5;
        int c4  = (idx & 31) * 4;
        float4 xv = make_float4(0.f, 0.f, 0.f, 0.f);
        int gr = row0 + r;
        if (gr < n) xv = *(const float4*)(X + (size_t)gr * DI + c4);
        __half2 h0 = __floats2half2_rn(xv.x, xv.y);
        __half2 h1 = __floats2half2_rn(xv.z, xv.w);
        *(uint2*)&xs[r * XLDH + c4] = make_uint2(h2u(h0), h2u(h1));
    }
    __syncthreads();

    unsigned xs_base = (unsigned)__cvta_generic_to_shared(xs);

    const float* Bs[4] = {b0, b1, b2, b3};

    int n0   = warp * 16;
    int lrow = lane & 15;
    int lcol = (lane >> 4) * 8;

#pragma unroll 1
    for (int w = 0; w < 4; w++) {
        const float* __restrict__ B = Bs[w];
        float*  outf = 0;
        __half* outh = 0;
        int ishalf = (w == 1 || w == 2);
        if (w == 0)      outf = g_q;
        else if (w == 1) outh = g_k;
        else if (w == 2) outh = g_v;
        else             outf = out3;

        // preload B fragments: 8 coalesced LDG.128 (L2/L1-hot, shared by all blocks)
        uint4 bfv[8];
        {
            const uint4* wp = g_wf + ((size_t)(w * 8 + warp)) * 8 * 32;
#pragma unroll
            for (int kt = 0; kt < 8; kt++)
                bfv[kt] = wp[kt * 32 + lane];
        }

        float2 bias[2];
#pragma unroll
        for (int nt = 0; nt < 2; nt++)
            bias[nt] = *(const float2*)(B + n0 + nt * 8 + 2 * (lane & 3));

#pragma unroll
        for (int chunk = 0; chunk < 8; chunk++) {
            float acc[2][4];
#pragma unroll
            for (int nt = 0; nt < 2; nt++)
#pragma unroll
                for (int i = 0; i < 4; i++) acc[nt][i] = 0.f;

            unsigned abase = xs_base +
                ((chunk * 16 + lrow) * XLDH + lcol) * 2;   // bytes
#pragma unroll
            for (int kt = 0; kt < 8; kt++) {
                unsigned a0, a1, a2, a3;
                asm volatile(
                    "ldmatrix.sync.aligned.m8n8.x4.shared.b16 {%0,%1,%2,%3}, [%4];"
                    : "=r"(a0), "=r"(a1), "=r"(a2), "=r"(a3)
                    : "r"(abase + kt * 32));
                unsigned af[4] = {a0, a1, a2, a3};
                unsigned bf0[2] = {bfv[kt].x, bfv[kt].y};
                unsigned bf1[2] = {bfv[kt].z, bfv[kt].w};
                mma_f16(acc[0], af, bf0);
                mma_f16(acc[1], af, bf1);
            }

            int r0 = row0 + chunk * 16 + (lane >> 2);
#pragma unroll
            for (int nt = 0; nt < 2; nt++) {
                int c = n0 + nt * 8 + 2 * (lane & 3);
                float o00 = acc[nt][0] + bias[nt].x;
                float o01 = acc[nt][1] + bias[nt].y;
                float o10 = acc[nt][2] + bias[nt].x;
                float o11 = acc[nt][3] + bias[nt].y;
                if (ishalf) {
                    if (r0 < n)
                        *(__half2*)(outh + (size_t)r0 * DI + c) = __floats2half2_rn(o00, o01);
                    if (r0 + 8 < n)
                        *(__half2*)(outh + (size_t)(r0 + 8) * DI + c) = __floats2half2_rn(o10, o11);
                } else {
                    if (r0 < n)
                        *(float2*)(outf + (size_t)r0 * DI + c) = make_float2(o00, o01);
                    if (r0 + 8 < n)
                        *(float2*)(outf + (size_t)(r0 + 8) * DI + c) = make_float2(o10, o11);
                }
            }
        }
    }
}

// ---------------- edge dtype sniff + CSR build ----------------
__global__ void sniff_dtype(const int* __restrict__ ei32, int e) {
    if (threadIdx.x == 0 && blockIdx.x == 0) {
        int allzero = 1;
        int stride = (2 * e) / 256;
        if (stride < 2) stride = 2;
        for (int s = 0; s < 256; s++) {
            long long idx = (long long)s * stride | 1;
            if (idx < 4LL * e) {
                if (ei32[idx] != 0) { allzero = 0; break; }
            }
        }
        g_is64 = allzero;
    }
}

__global__ void zero_deg(int n) {
    for (int i = blockIdx.x * blockDim.x + threadIdx.x; i < n; i += gridDim.x * blockDim.x)
        g_deg[i] = 0;
}

__device__ __forceinline__ int load_edge(const int* __restrict__ ei32,
                                         int is64, long long pos) {
    return is64 ? ei32[2 * pos] : ei32[pos];
}

__global__ void hist_edges(const int* __restrict__ ei32, int e, int n) {
    int is64 = g_is64;
    for (int i = blockIdx.x * blockDim.x + threadIdx.x; i < e; i += gridDim.x * blockDim.x) {
        int d = load_edge(ei32, is64, (long long)e + i);
        d = min(max(d, 0), n - 1);
        atomicAdd(&g_deg[d], 1);
    }
}

// ---------------- 3-phase parallel exclusive scan ----------------
__global__ __launch_bounds__(1024) void scan_p1(int n) {
    __shared__ int wsum[32];
    int tid = threadIdx.x, lane = tid & 31, wid = tid >> 5;
    int i = blockIdx.x * 1024 + tid;
    int v = (i < n) ? g_deg[i] : 0;
    int inc = v;
#pragma unroll
    for (int o = 1; o < 32; o <<= 1) {
        int t = __shfl_up_sync(0xffffffffu, inc, o);
        if (lane >= o) inc += t;
    }
    if (lane == 31) wsum[wid] = inc;
    __syncthreads();
    if (wid == 0) {
        int wv = wsum[lane];
        int wi = wv;
#pragma unroll
        for (int o = 1; o < 32; o <<= 1) {
            int t = __shfl_up_sync(0xffffffffu, wi, o);
            if (lane >= o) wi += t;
        }
        wsum[lane] = wi - wv;
        if (lane == 31) g_bsum[blockIdx.x] = wi;
    }
    __syncthreads();
    if (i < n) g_off[i] = wsum[wid] + inc - v;
}

__global__ void scan_p2(int nb) {
    int lane = threadIdx.x;
    int acc = 0;
    for (int base = 0; base < nb; base += 32) {
        int v = (base + lane < nb) ? g_bsum[base + lane] : 0;
        int inc = v;
#pragma unroll
        for (int o = 1; o < 32; o <<= 1) {
            int t = __shfl_up_sync(0xffffffffu, inc, o);
            if (lane >= o) inc += t;
        }
        if (base + lane < nb) g_bsum[base + lane] = acc + inc - v;
        acc += __shfl_sync(0xffffffffu, inc, 31);
    }
    if (lane == 0) g_bsum[255] = acc;
}

__global__ __launch_bounds__(1024) void scan_p3(int n) {
    int i = blockIdx.x * 1024 + threadIdx.x;
    if (i < n) {
        int off = g_off[i] + g_bsum[blockIdx.x];
        g_off[i] = off;
        g_cur[i] = off;
    }
    if (i == 0) g_off[n] = g_bsum[255];
}

__global__ void fill_csr(const int* __restrict__ ei32, int e, int n) {
    int is64 = g_is64;
    for (int i = blockIdx.x * blockDim.x + threadIdx.x; i < e; i += gridDim.x * blockDim.x) {
        int s = load_edge(ei32, is64, i);
        int d = load_edge(ei32, is64, (long long)e + i);
        s = min(max(s, 0), n - 1);
        d = min(max(d, 0), n - 1);
        int pos = atomicAdd(&g_cur[d], 1);
        g_csr_src[pos] = s;
    }
}

// ---------------- attention: one warp per node, all 4 heads, fp16 k/v, MLP=8 ----------------
__device__ __forceinline__ float red8(float d) {
    d += __shfl_xor_sync(0xffffffffu, d, 4);
    d += __shfl_xor_sync(0xffffffffu, d, 2);
    d += __shfl_xor_sync(0xffffffffu, d, 1);
    return d;
}

__device__ __forceinline__ float dot_h(const uint2 kp, float4 q4) {
    float2 a = __half22float2(*(const __half2*)&kp.x);
    float2 b = __half22float2(*(const __half2*)&kp.y);
    return q4.x * a.x + q4.y * a.y + q4.z * b.x + q4.w * b.y;
}

__global__ __launch_bounds__(256) void attn_node(float* __restrict__ out, int n) {
    int warp = (blockIdx.x * blockDim.x + threadIdx.x) >> 5;
    int lane = threadIdx.x & 31;
    if (warp >= n) return;
    int node = warp;

    int base = g_off[node];
    int end  = g_off[node + 1];

    const __half* __restrict__ kh = g_k;
    const __half* __restrict__ vh = g_v;

    float4 q4 = *(const float4*)(g_q + (size_t)node * DI + 4 * lane);
    const float scale = 0.17677669529663688f;  // 1/sqrt(32)

    float  z    = 0.f;
    float4 acc4 = make_float4(0.f, 0.f, 0.f, 0.f);

    for (int i0 = base; i0 < end; i0 += 32) {
        int nchunk = min(32, end - i0);
        int sidx = (i0 + lane < end) ? g_csr_src[i0 + lane] : 0;

        int j = 0;
        for (; j + 3 < nchunk; j += 4) {
            int s0 = __shfl_sync(0xffffffffu, sidx, j);
            int s1 = __shfl_sync(0xffffffffu, sidx, j + 1);
            int s2 = __shfl_sync(0xffffffffu, sidx, j + 2);
            int s3 = __shfl_sync(0xffffffffu, sidx, j + 3);
            uint2 kp0 = *(const uint2*)(kh + (size_t)s0 * DI + 4 * lane);
            uint2 kp1 = *(const uint2*)(kh + (size_t)s1 * DI + 4 * lane);
            uint2 kp2 = *(const uint2*)(kh + (size_t)s2 * DI + 4 * lane);
            uint2 kp3 = *(const uint2*)(kh + (size_t)s3 * DI + 4 * lane);
            uint2 vp0 = *(const uint2*)(vh + (size_t)s0 * DI + 4 * lane);
            uint2 vp1 = *(const uint2*)(vh + (size_t)s1 * DI + 4 * lane);
            uint2 vp2 = *(const uint2*)(vh + (size_t)s2 * DI + 4 * lane);
            uint2 vp3 = *(const uint2*)(vh + (size_t)s3 * DI + 4 * lane);

            float d0 = red8(dot_h(kp0, q4));
            float d1 = red8(dot_h(kp1, q4));
            float d2 = red8(dot_h(kp2, q4));
            float d3 = red8(dot_h(kp3, q4));
            float p0 = __expf(d0 * scale);
            float p1 = __expf(d1 * scale);
            float p2 = __expf(d2 * scale);
            float p3 = __expf(d3 * scale);
            z += (p0 + p1) + (p2 + p3);

            float2 v0a = __half22float2(*(const __half2*)&vp0.x);
            float2 v0b = __half22float2(*(const __half2*)&vp0.y);
            float2 v1a = __half22float2(*(const __half2*)&vp1.x);
            float2 v1b = __half22float2(*(const __half2*)&vp1.y);
            float2 v2a = __half22float2(*(const __half2*)&vp2.x);
            float2 v2b = __half22float2(*(const __half2*)&vp2.y);
            float2 v3a = __half22float2(*(const __half2*)&vp3.x);
            float2 v3b = __half22float2(*(const __half2*)&vp3.y);
            acc4.x += p0 * v0a.x + p1 * v1a.x + p2 * v2a.x + p3 * v3a.x;
            acc4.y += p0 * v0a.y + p1 * v1a.y + p2 * v2a.y + p3 * v3a.y;
            acc4.z += p0 * v0b.x + p1 * v1b.x + p2 * v2b.x + p3 * v3b.x;
            acc4.w += p0 * v0b.y + p1 * v1b.y + p2 * v2b.y + p3 * v3b.y;
        }
        for (; j < nchunk; j++) {
            int s0 = __shfl_sync(0xffffffffu, sidx, j);
            uint2 kp0 = *(const uint2*)(kh + (size_t)s0 * DI + 4 * lane);
            uint2 vp0 = *(const uint2*)(vh + (size_t)s0 * DI + 4 * lane);
            float d0 = red8(dot_h(kp0, q4));
            float p0 = __expf(d0 * scale);
            z += p0;
            float2 v0a = __half22float2(*(const __half2*)&vp0.x);
            float2 v0b = __half22float2(*(const __half2*)&vp0.y);
            acc4.x += p0 * v0a.x;
            acc4.y += p0 * v0a.y;
            acc4.z += p0 * v0b.x;
            acc4.w += p0 * v0b.y;
        }
    }

    float inv = 1.f / (z + 1e-16f);
    float4* op = (float4*)(out + (size_t)node * DI + 4 * lane);
    float4 o = *op;
    o.x += acc4.x * inv;
    o.y += acc4.y * inv;
    o.z += acc4.z * inv;
    o.w += acc4.w * inv;
    *op = o;
}

// ---------------- launch: GEMM overlapped with CSR build via side stream ----------------
extern "C" void kernel_launch(void* const* d_in, const int* in_sizes, int n_in,
                              void* d_out, int out_size) {
    const float* x   = (const float*)d_in[0];
    const int*   ei  = (const int*)d_in[1];
    const float* Wq  = (const float*)d_in[2];
    const float* bq  = (const float*)d_in[3];
    const float* Wk  = (const float*)d_in[4];
    const float* bk  = (const float*)d_in[5];
    const float* Wv  = (const float*)d_in[6];
    const float* bv  = (const float*)d_in[7];
    const float* Wsk = (const float*)d_in[8];
    const float* bsk = (const float*)d_in[9];
    float*       out = (float*)d_out;

    int n = in_sizes[0] / DI;
    int e = in_sizes[1] / 2;

    static cudaStream_t sB = 0;
    static cudaEvent_t  evFork = 0, evJoin = 0;
    if (!sB) {
        cudaStreamCreateWithFlags(&sB, cudaStreamNonBlocking);
        cudaEventCreateWithFlags(&evFork, cudaEventDisableTiming);
        cudaEventCreateWithFlags(&evJoin, cudaEventDisableTiming);
    }

    // fork: side stream joins the capture graph
    cudaEventRecord(evFork, 0);
    cudaStreamWaitEvent(sB, evFork, 0);

    // main stream: weight fragment prep + fused GEMM
    prep_w<<<128, 256>>>(Wq, Wk, Wv, Wsk);
    int gblocks = (n + 127) / 128;
    gemm_mma<<<gblocks, 256>>>(x, bq, bk, bv, bsk, out, n);

    // side stream: CSR build chain (independent of GEMM)
    sniff_dtype<<<1, 32, 0, sB>>>(ei, e);
    zero_deg<<<256, 256, 0, sB>>>(n);
    hist_edges<<<2048, 256, 0, sB>>>(ei, e, n);
    int nb = (n + 1023) / 1024;
    scan_p1<<<nb, 1024, 0, sB>>>(n);
    scan_p2<<<1, 32, 0, sB>>>(nb);
    scan_p3<<<nb, 1024, 0, sB>>>(n);
    fill_csr<<<2048, 256, 0, sB>>>(ei, e, n);

    // join: attention needs both GEMM outputs and CSR
    cudaEventRecord(evJoin, sB);
    cudaStreamWaitEvent(0, evJoin, 0);

    int blocks = (n * 32 + 255) / 256;
    attn_node<<<blocks, 256>>>(out, n);
}

// round 17
// speedup vs baseline: 3.9880x; 1.1476x over previous
#include <cuda_runtime.h>
#include <cuda_fp16.h>
#include <math.h>

#define NMAX 100000
#define EMAX 1600000
#define DI   128
#define H4   4
#define C32  32
#define XLDH 136   // fp16 leading dim: 272B = 17x16B -> ldmatrix conflict-free

// ---------------- static device scratch ----------------
__device__ __half g_q[NMAX * DI];          // q, fp16
__device__ __half g_kv[NMAX * 2 * DI];     // per node: 128 k halves | 128 v halves
// B fragments in register order: [w][warp][kt(8)][lane(32)][4 words]
__device__ uint4  g_wf[4 * 8 * 8 * 32];
__device__ int    g_csr_src[EMAX];
__device__ int    g_deg[NMAX];
__device__ int    g_off[NMAX + 1];
__device__ int    g_cur[NMAX];
__device__ int    g_bsum[256];
__device__ int    g_is64;

// ---------------- fp16 mma helpers ----------------
__device__ __forceinline__ void mma_f16(float* c, const unsigned* a, const unsigned* b) {
    asm volatile(
        "mma.sync.aligned.m16n8k16.row.col.f32.f16.f16.f32 "
        "{%0,%1,%2,%3}, {%4,%5,%6,%7}, {%8,%9}, {%0,%1,%2,%3};\n"
        : "+f"(c[0]), "+f"(c[1]), "+f"(c[2]), "+f"(c[3])
        : "r"(a[0]), "r"(a[1]), "r"(a[2]), "r"(a[3]), "r"(b[0]), "r"(b[1]));
}
__device__ __forceinline__ unsigned h2u(__half2 h) {
    return *reinterpret_cast<unsigned*>(&h);
}

// ---------------- weight prep: W fp32 -> fragment-ordered fp16 words ----------------
__global__ void prep_w(const float* __restrict__ W0, const float* __restrict__ W1,
                       const float* __restrict__ W2, const float* __restrict__ W3) {
    const float* Ws[4] = {W0, W1, W2, W3};
    int idx = blockIdx.x * 256 + threadIdx.x;   // 0..32767 words
    int w    = idx >> 13;
    int rem  = idx & 8191;
    int warp = rem >> 10;
    int kt   = (rem >> 7) & 7;
    int lane = (rem >> 2) & 31;
    int q    = rem & 3;
    int nt   = q >> 1;
    int reg  = q & 1;
    int col  = warp * 16 + nt * 8 + (lane >> 2);
    int k    = kt * 16 + (lane & 3) * 2 + reg * 8;
    const float* W = Ws[w];
    __half2 val = __floats2half2_rn(W[(size_t)k * DI + col], W[(size_t)(k + 1) * DI + col]);
    ((unsigned*)g_wf)[idx] = h2u(val);
}

// ---------------- fused fp16 tensor-core GEMM: 128-row tiles, all 4 W ----------------
__global__ __launch_bounds__(256) void gemm_mma(
    const float* __restrict__ X,
    const float* __restrict__ b0, const float* __restrict__ b1,
    const float* __restrict__ b2, const float* __restrict__ b3,
    float* __restrict__ out3, int n)
{
    __shared__ __half xs[128 * XLDH];   // ~34.8 KB

    int tid  = threadIdx.x;
    int warp = tid >> 5;
    int lane = tid & 31;
    int row0 = blockIdx.x * 128;

    // stage X tile (128 rows x 128 k) as fp16 -- once per block
#pragma unroll
    for (int t = 0; t < 16; t++) {
        int idx = tid + t * 256;
        int r   = idx >> 5;
        int c4  = (idx & 31) * 4;
        float4 xv = make_float4(0.f, 0.f, 0.f, 0.f);
        int gr = row0 + r;
        if (gr < n) xv = *(const float4*)(X + (size_t)gr * DI + c4);
        __half2 h0 = __floats2half2_rn(xv.x, xv.y);
        __half2 h1 = __floats2half2_rn(xv.z, xv.w);
        *(uint2*)&xs[r * XLDH + c4] = make_uint2(h2u(h0), h2u(h1));
    }
    __syncthreads();

    unsigned xs_base = (unsigned)__cvta_generic_to_shared(xs);

    const float* Bs[4] = {b0, b1, b2, b3};

    int n0   = warp * 16;
    int lrow = lane & 15;
    int lcol = (lane >> 4) * 8;

#pragma unroll 1
    for (int w = 0; w < 4; w++) {
        const float* __restrict__ B = Bs[w];
        // output target: w0->q(h), w1->kv k-half, w2->kv v-half, w3->out fp32
        __half* outh = 0;
        float*  outf = 0;
        size_t  ostride;
        size_t  obase = 0;
        if (w == 0)      { outh = g_q;  ostride = DI; }
        else if (w == 1) { outh = g_kv; ostride = 2 * DI; }
        else if (w == 2) { outh = g_kv; ostride = 2 * DI; obase = DI; }
        else             { outf = out3; ostride = DI; }

        // preload B fragments: 8 coalesced LDG.128
        uint4 bfv[8];
        {
            const uint4* wp = g_wf + ((size_t)(w * 8 + warp)) * 8 * 32;
#pragma unroll
            for (int kt = 0; kt < 8; kt++)
                bfv[kt] = wp[kt * 32 + lane];
        }

        float2 bias[2];
#pragma unroll
        for (int nt = 0; nt < 2; nt++)
            bias[nt] = *(const float2*)(B + n0 + nt * 8 + 2 * (lane & 3));

#pragma unroll
        for (int chunk = 0; chunk < 8; chunk++) {
            float acc[2][4];
#pragma unroll
            for (int nt = 0; nt < 2; nt++)
#pragma unroll
                for (int i = 0; i < 4; i++) acc[nt][i] = 0.f;

            unsigned abase = xs_base +
                ((chunk * 16 + lrow) * XLDH + lcol) * 2;
#pragma unroll
            for (int kt = 0; kt < 8; kt++) {
                unsigned a0, a1, a2, a3;
                asm volatile(
                    "ldmatrix.sync.aligned.m8n8.x4.shared.b16 {%0,%1,%2,%3}, [%4];"
                    : "=r"(a0), "=r"(a1), "=r"(a2), "=r"(a3)
                    : "r"(abase + kt * 32));
                unsigned af[4] = {a0, a1, a2, a3};
                unsigned bf0[2] = {bfv[kt].x, bfv[kt].y};
                unsigned bf1[2] = {bfv[kt].z, bfv[kt].w};
                mma_f16(acc[0], af, bf0);
                mma_f16(acc[1], af, bf1);
            }

            int r0 = row0 + chunk * 16 + (lane >> 2);
#pragma unroll
            for (int nt = 0; nt < 2; nt++) {
                int c = n0 + nt * 8 + 2 * (lane & 3);
                float o00 = acc[nt][0] + bias[nt].x;
                float o01 = acc[nt][1] + bias[nt].y;
                float o10 = acc[nt][2] + bias[nt].x;
                float o11 = acc[nt][3] + bias[nt].y;
                if (outh) {
                    if (r0 < n)
                        *(__half2*)(outh + (size_t)r0 * ostride + obase + c) =
                            __floats2half2_rn(o00, o01);
                    if (r0 + 8 < n)
                        *(__half2*)(outh + (size_t)(r0 + 8) * ostride + obase + c) =
                            __floats2half2_rn(o10, o11);
                } else {
                    if (r0 < n)
                        *(float2*)(outf + (size_t)r0 * DI + c) = make_float2(o00, o01);
                    if (r0 + 8 < n)
                        *(float2*)(outf + (size_t)(r0 + 8) * DI + c) = make_float2(o10, o11);
                }
            }
        }
    }
}

// ---------------- edge dtype sniff + CSR build ----------------
__global__ void sniff_dtype(const int* __restrict__ ei32, int e) {
    if (threadIdx.x == 0 && blockIdx.x == 0) {
        int allzero = 1;
        int stride = (2 * e) / 256;
        if (stride < 2) stride = 2;
        for (int s = 0; s < 256; s++) {
            long long idx = (long long)s * stride | 1;
            if (idx < 4LL * e) {
                if (ei32[idx] != 0) { allzero = 0; break; }
            }
        }
        g_is64 = allzero;
    }
}

__global__ void zero_deg(int n) {
    for (int i = blockIdx.x * blockDim.x + threadIdx.x; i < n; i += gridDim.x * blockDim.x)
        g_deg[i] = 0;
}

__device__ __forceinline__ int load_edge(const int* __restrict__ ei32,
                                         int is64, long long pos) {
    return is64 ? ei32[2 * pos] : ei32[pos];
}

__global__ void hist_edges(const int* __restrict__ ei32, int e, int n) {
    int is64 = g_is64;
    for (int i = blockIdx.x * blockDim.x + threadIdx.x; i < e; i += gridDim.x * blockDim.x) {
        int d = load_edge(ei32, is64, (long long)e + i);
        d = min(max(d, 0), n - 1);
        atomicAdd(&g_deg[d], 1);
    }
}

// ---------------- 3-phase parallel exclusive scan ----------------
__global__ __launch_bounds__(1024) void scan_p1(int n) {
    __shared__ int wsum[32];
    int tid = threadIdx.x, lane = tid & 31, wid = tid >> 5;
    int i = blockIdx.x * 1024 + tid;
    int v = (i < n) ? g_deg[i] : 0;
    int inc = v;
#pragma unroll
    for (int o = 1; o < 32; o <<= 1) {
        int t = __shfl_up_sync(0xffffffffu, inc, o);
        if (lane >= o) inc += t;
    }
    if (lane == 31) wsum[wid] = inc;
    __syncthreads();
    if (wid == 0) {
        int wv = wsum[lane];
        int wi = wv;
#pragma unroll
        for (int o = 1; o < 32; o <<= 1) {
            int t = __shfl_up_sync(0xffffffffu, wi, o);
            if (lane >= o) wi += t;
        }
        wsum[lane] = wi - wv;
        if (lane == 31) g_bsum[blockIdx.x] = wi;
    }
    __syncthreads();
    if (i < n) g_off[i] = wsum[wid] + inc - v;
}

__global__ void scan_p2(int nb) {
    int lane = threadIdx.x;
    int acc = 0;
    for (int base = 0; base < nb; base += 32) {
        int v = (base + lane < nb) ? g_bsum[base + lane] : 0;
        int inc = v;
#pragma unroll
        for (int o = 1; o < 32; o <<= 1) {
            int t = __shfl_up_sync(0xffffffffu, inc, o);
            if (lane >= o) inc += t;
        }
        if (base + lane < nb) g_bsum[base + lane] = acc + inc - v;
        acc += __shfl_sync(0xffffffffu, inc, 31);
    }
    if (lane == 0) g_bsum[255] = acc;
}

__global__ __launch_bounds__(1024) void scan_p3(int n) {
    int i = blockIdx.x * 1024 + threadIdx.x;
    if (i < n) {
        int off = g_off[i] + g_bsum[blockIdx.x];
        g_off[i] = off;
        g_cur[i] = off;
    }
    if (i == 0) g_off[n] = g_bsum[255];
}

__global__ void fill_csr(const int* __restrict__ ei32, int e, int n) {
    int is64 = g_is64;
    for (int i = blockIdx.x * blockDim.x + threadIdx.x; i < e; i += gridDim.x * blockDim.x) {
        int s = load_edge(ei32, is64, i);
        int d = load_edge(ei32, is64, (long long)e + i);
        s = min(max(s, 0), n - 1);
        d = min(max(d, 0), n - 1);
        int pos = atomicAdd(&g_cur[d], 1);
        g_csr_src[pos] = s;
    }
}

// ---------------- attention: one warp per node, all 4 heads, packed fp16 kv ----------------
__device__ __forceinline__ float red8(float d) {
    d += __shfl_xor_sync(0xffffffffu, d, 4);
    d += __shfl_xor_sync(0xffffffffu, d, 2);
    d += __shfl_xor_sync(0xffffffffu, d, 1);
    return d;
}

__device__ __forceinline__ float dot_h(const uint2 kp, float4 q4) {
    float2 a = __half22float2(*(const __half2*)&kp.x);
    float2 b = __half22float2(*(const __half2*)&kp.y);
    return q4.x * a.x + q4.y * a.y + q4.z * b.x + q4.w * b.y;
}

__global__ __launch_bounds__(256) void attn_node(float* __restrict__ out, int n) {
    int warp = (blockIdx.x * blockDim.x + threadIdx.x) >> 5;
    int lane = threadIdx.x & 31;
    if (warp >= n) return;
    int node = warp;

    int base = g_off[node];
    int end  = g_off[node + 1];

    const __half* __restrict__ kv = g_kv;

    // q fp16 -> float4 once
    float4 q4;
    {
        uint2 qp = *(const uint2*)(g_q + (size_t)node * DI + 4 * lane);
        float2 qa = __half22float2(*(const __half2*)&qp.x);
        float2 qb = __half22float2(*(const __half2*)&qp.y);
        q4 = make_float4(qa.x, qa.y, qb.x, qb.y);
    }
    const float scale = 0.17677669529663688f;  // 1/sqrt(32)

    float  z    = 0.f;
    float4 acc4 = make_float4(0.f, 0.f, 0.f, 0.f);

    for (int i0 = base; i0 < end; i0 += 32) {
        int nchunk = min(32, end - i0);
        int sidx = (i0 + lane < end) ? g_csr_src[i0 + lane] : 0;

        int j = 0;
        for (; j + 3 < nchunk; j += 4) {
            int s0 = __shfl_sync(0xffffffffu, sidx, j);
            int s1 = __shfl_sync(0xffffffffu, sidx, j + 1);
            int s2 = __shfl_sync(0xffffffffu, sidx, j + 2);
            int s3 = __shfl_sync(0xffffffffu, sidx, j + 3);
            const __half* r0p = kv + (size_t)s0 * (2 * DI);
            const __half* r1p = kv + (size_t)s1 * (2 * DI);
            const __half* r2p = kv + (size_t)s2 * (2 * DI);
            const __half* r3p = kv + (size_t)s3 * (2 * DI);
            uint2 kp0 = *(const uint2*)(r0p + 4 * lane);
            uint2 kp1 = *(const uint2*)(r1p + 4 * lane);
            uint2 kp2 = *(const uint2*)(r2p + 4 * lane);
            uint2 kp3 = *(const uint2*)(r3p + 4 * lane);
            uint2 vp0 = *(const uint2*)(r0p + DI + 4 * lane);
            uint2 vp1 = *(const uint2*)(r1p + DI + 4 * lane);
            uint2 vp2 = *(const uint2*)(r2p + DI + 4 * lane);
            uint2 vp3 = *(const uint2*)(r3p + DI + 4 * lane);

            float d0 = red8(dot_h(kp0, q4));
            float d1 = red8(dot_h(kp1, q4));
            float d2 = red8(dot_h(kp2, q4));
            float d3 = red8(dot_h(kp3, q4));
            float p0 = __expf(d0 * scale);
            float p1 = __expf(d1 * scale);
            float p2 = __expf(d2 * scale);
            float p3 = __expf(d3 * scale);
            z += (p0 + p1) + (p2 + p3);

            float2 v0a = __half22float2(*(const __half2*)&vp0.x);
            float2 v0b = __half22float2(*(const __half2*)&vp0.y);
            float2 v1a = __half22float2(*(const __half2*)&vp1.x);
            float2 v1b = __half22float2(*(const __half2*)&vp1.y);
            float2 v2a = __half22float2(*(const __half2*)&vp2.x);
            float2 v2b = __half22float2(*(const __half2*)&vp2.y);
            float2 v3a = __half22float2(*(const __half2*)&vp3.x);
            float2 v3b = __half22float2(*(const __half2*)&vp3.y);
            acc4.x += p0 * v0a.x + p1 * v1a.x + p2 * v2a.x + p3 * v3a.x;
            acc4.y += p0 * v0a.y + p1 * v1a.y + p2 * v2a.y + p3 * v3a.y;
            acc4.z += p0 * v0b.x + p1 * v1b.x + p2 * v2b.x + p3 * v3b.x;
            acc4.w += p0 * v0b.y + p1 * v1b.y + p2 * v2b.y + p3 * v3b.y;
        }
        for (; j < nchunk; j++) {
            int s0 = __shfl_sync(0xffffffffu, sidx, j);
            const __half* r0p = kv + (size_t)s0 * (2 * DI);
            uint2 kp0 = *(const uint2*)(r0p + 4 * lane);
            uint2 vp0 = *(const uint2*)(r0p + DI + 4 * lane);
            float d0 = red8(dot_h(kp0, q4));
            float p0 = __expf(d0 * scale);
            z += p0;
            float2 v0a = __half22float2(*(const __half2*)&vp0.x);
            float2 v0b = __half22float2(*(const __half2*)&vp0.y);
            acc4.x += p0 * v0a.x;
            acc4.y += p0 * v0a.y;
            acc4.z += p0 * v0b.x;
            acc4.w += p0 * v0b.y;
        }
    }

    float inv = 1.f / (z + 1e-16f);
    float4* op = (float4*)(out + (size_t)node * DI + 4 * lane);
    float4 o = *op;
    o.x += acc4.x * inv;
    o.y += acc4.y * inv;
    o.z += acc4.z * inv;
    o.w += acc4.w * inv;
    *op = o;
}

// ---------------- launch: GEMM overlapped with CSR build via side stream ----------------
extern "C" void kernel_launch(void* const* d_in, const int* in_sizes, int n_in,
                              void* d_out, int out_size) {
    const float* x   = (const float*)d_in[0];
    const int*   ei  = (const int*)d_in[1];
    const float* Wq  = (const float*)d_in[2];
    const float* bq  = (const float*)d_in[3];
    const float* Wk  = (const float*)d_in[4];
    const float* bk  = (const float*)d_in[5];
    const float* Wv  = (const float*)d_in[6];
    const float* bv  = (const float*)d_in[7];
    const float* Wsk = (const float*)d_in[8];
    const float* bsk = (const float*)d_in[9];
    float*       out = (float*)d_out;

    int n = in_sizes[0] / DI;
    int e = in_sizes[1] / 2;

    static cudaStream_t sB = 0;
    static cudaEvent_t  evFork = 0, evJoin = 0;
    if (!sB) {
        cudaStreamCreateWithFlags(&sB, cudaStreamNonBlocking);
        cudaEventCreateWithFlags(&evFork, cudaEventDisableTiming);
        cudaEventCreateWithFlags(&evJoin, cudaEventDisableTiming);
    }

    // fork: side stream joins the capture graph
    cudaEventRecord(evFork, 0);
    cudaStreamWaitEvent(sB, evFork, 0);

    // main stream: weight fragment prep + fused GEMM
    prep_w<<<128, 256>>>(Wq, Wk, Wv, Wsk);
    int gblocks = (n + 127) / 128;
    gemm_mma<<<gblocks, 256>>>(x, bq, bk, bv, bsk, out, n);

    // side stream: CSR build chain (independent of GEMM)
    sniff_dtype<<<1, 32, 0, sB>>>(ei, e);
    zero_deg<<<256, 256, 0, sB>>>(n);
    hist_edges<<<2048, 256, 0, sB>>>(ei, e, n);
    int nb = (n + 1023) / 1024;
    scan_p1<<<nb, 1024, 0, sB>>>(n);
    scan_p2<<<1, 32, 0, sB>>>(nb);
    scan_p3<<<nb, 1024, 0, sB>>>(n);
    fill_csr<<<2048, 256, 0, sB>>>(ei, e, n);

    // join: attention needs both GEMM outputs and CSR
    cudaEventRecord(evJoin, sB);
    cudaStreamWaitEvent(0, evJoin, 0);

    int blocks = (n * 32 + 255) / 256;
    attn_node<<<blocks, 256>>>(out, n);
}